// round 1
// baseline (speedup 1.0000x reference)
#include <cuda_runtime.h>
#include <cuda_bf16.h>
#include <math.h>

#define LSEQ 2048
#define BATCH 4
#define DMODEL 512
#define NHEAD 8
#define DKH 64
#define NLAYER 4
#define DFFN 2048
#define MROWS (LSEQ * BATCH)   // 8192
#define NVOCAB 32000

// ---------------- scratch (device globals; no allocation allowed) ----------------
__device__ float g_x[MROWS * DMODEL];
__device__ float g_q[MROWS * DMODEL];
__device__ float g_k[MROWS * DMODEL];
__device__ float g_v[MROWS * DMODEL];
__device__ float g_ctx[MROWS * DMODEL];
__device__ float g_t[MROWS * DMODEL];
__device__ float g_ff[MROWS * DFFN];

// ---------------- embedding + sinusoidal positional encoding ----------------
__global__ void __launch_bounds__(128) embed_kernel(float* __restrict__ x,
                                                    const int* __restrict__ tok,
                                                    const float* __restrict__ emb)
{
    int m = blockIdx.x;           // m = l*B + b
    int l = m >> 2;               // B = 4
    int t = tok[m];
    const float sq = 22.627416997969522f;  // sqrt(512)
    const double nlog = 9.210340371976184; // ln(10000)
#pragma unroll
    for (int j = 0; j < 4; j++) {
        int d = threadIdx.x + j * 128;
        int i = d >> 1;
        // match reference fp32 pipeline: freq rounded to fp32, angle fp32 product,
        // then accurate (double) sin/cos of the fp32 angle (fast-math proof).
        float freqf = (float)exp(-(double)(2 * i) * (nlog / 512.0));
        float angf = (float)l * freqf;
        double ang = (double)angf;
        float pe = (d & 1) ? (float)cos(ang) : (float)sin(ang);
        x[(size_t)m * DMODEL + d] = emb[(size_t)t * DMODEL + d] * sq + pe;
    }
}

// ---------------- SGEMM: C[M,N] = A[M,K] * W[N,K]^T (+bias, +relu) ----------------
// BM=BN=128, BK=16, 256 threads, 8x8 microtile. All dims are multiples of tile sizes.
#define GBM 128
#define GBN 128
#define GBK 16

template <bool BIAS, bool RELU>
__global__ void __launch_bounds__(256) sgemm_kernel(float* __restrict__ C,
                                                    const float* __restrict__ A,
                                                    const float* __restrict__ W,
                                                    const float* __restrict__ bias,
                                                    int M, int N, int K)
{
    __shared__ __align__(16) float As[GBK][GBM + 4];
    __shared__ __align__(16) float Ws[GBK][GBN + 4];

    const int tid = threadIdx.x;
    const int bm = blockIdx.y * GBM;
    const int bn = blockIdx.x * GBN;
    const int tx = tid & 15;
    const int ty = tid >> 4;

    const int lr = tid >> 2;        // 0..63
    const int lc = (tid & 3) * 4;   // 0,4,8,12

    const float* Aptr = A + (size_t)(bm + lr) * K + lc;
    const float* Wptr = W + (size_t)(bn + lr) * K + lc;
    const size_t a64 = (size_t)64 * K;

    float acc[8][8];
#pragma unroll
    for (int i = 0; i < 8; i++)
#pragma unroll
        for (int j = 0; j < 8; j++) acc[i][j] = 0.f;

    for (int k0 = 0; k0 < K; k0 += GBK) {
        float4 a0 = *(const float4*)(Aptr + k0);
        float4 a1 = *(const float4*)(Aptr + a64 + k0);
        float4 w0 = *(const float4*)(Wptr + k0);
        float4 w1 = *(const float4*)(Wptr + a64 + k0);
        As[lc + 0][lr] = a0.x; As[lc + 1][lr] = a0.y; As[lc + 2][lr] = a0.z; As[lc + 3][lr] = a0.w;
        As[lc + 0][lr + 64] = a1.x; As[lc + 1][lr + 64] = a1.y; As[lc + 2][lr + 64] = a1.z; As[lc + 3][lr + 64] = a1.w;
        Ws[lc + 0][lr] = w0.x; Ws[lc + 1][lr] = w0.y; Ws[lc + 2][lr] = w0.z; Ws[lc + 3][lr] = w0.w;
        Ws[lc + 0][lr + 64] = w1.x; Ws[lc + 1][lr + 64] = w1.y; Ws[lc + 2][lr + 64] = w1.z; Ws[lc + 3][lr + 64] = w1.w;
        __syncthreads();
#pragma unroll
        for (int kk = 0; kk < GBK; kk++) {
            float4 av0 = *(const float4*)&As[kk][ty * 8];
            float4 av1 = *(const float4*)&As[kk][ty * 8 + 4];
            float4 bv0 = *(const float4*)&Ws[kk][tx * 8];
            float4 bv1 = *(const float4*)&Ws[kk][tx * 8 + 4];
            float a[8] = {av0.x, av0.y, av0.z, av0.w, av1.x, av1.y, av1.z, av1.w};
            float b[8] = {bv0.x, bv0.y, bv0.z, bv0.w, bv1.x, bv1.y, bv1.z, bv1.w};
#pragma unroll
            for (int i = 0; i < 8; i++)
#pragma unroll
                for (int j = 0; j < 8; j++) acc[i][j] += a[i] * b[j];
        }
        __syncthreads();
    }

    float bv[8];
#pragma unroll
    for (int j = 0; j < 8; j++) bv[j] = BIAS ? bias[bn + tx * 8 + j] : 0.f;

#pragma unroll
    for (int i = 0; i < 8; i++) {
        size_t row = (size_t)(bm + ty * 8 + i);
        float* cp = C + row * N + bn + tx * 8;
        float r[8];
#pragma unroll
        for (int j = 0; j < 8; j++) {
            float v = acc[i][j] + bv[j];
            if (RELU) v = fmaxf(v, 0.f);
            r[j] = v;
        }
        *(float4*)(cp) = make_float4(r[0], r[1], r[2], r[3]);
        *(float4*)(cp + 4) = make_float4(r[4], r[5], r[6], r[7]);
    }
}

// ---------------- flash attention (fp32, causal) ----------------
// grid: (L/64, B, H), 256 threads. BM=BN=64, DK=64. Dynamic smem = 49664 B.
#define ATTN_SMEM ((64 * 64 + 64 * 65 + 64 * 65) * 4)

__global__ void __launch_bounds__(256) attn_kernel(float* __restrict__ out,
                                                   const float* __restrict__ Q,
                                                   const float* __restrict__ Kt,
                                                   const float* __restrict__ V)
{
    extern __shared__ float sm[];
    float* Qs = sm;                 // [64][64]
    float* KVs = sm + 64 * 64;      // [64][65]
    float* Ss = KVs + 64 * 65;      // [64][65]

    const int tid = threadIdx.x;
    const int b = blockIdx.y, h = blockIdx.z;
    const int l0 = blockIdx.x * 64;
    const int hoff = h * DKH;
    const float scale = 0.125f;     // 1/sqrt(64)

    // load Q tile
    for (int idx = tid; idx < 64 * 64; idx += 256) {
        int r = idx >> 6, c = idx & 63;
        Qs[r * 64 + c] = Q[((size_t)(l0 + r) * BATCH + b) * DMODEL + hoff + c];
    }

    const int r = tid >> 2;        // row owner (4 threads per row)
    const int sub = tid & 3;
    const int tr = tid >> 4, tc = tid & 15;

    float mrow = -INFINITY, lsum = 0.f;
    float acc[16];
#pragma unroll
    for (int i = 0; i < 16; i++) acc[i] = 0.f;

    const int ntiles = blockIdx.x + 1;
    for (int jt = 0; jt < ntiles; jt++) {
        __syncthreads();  // KVs/Ss free from previous iteration; Qs ready (iter 0)
        // load K tile
        for (int idx = tid; idx < 64 * 64; idx += 256) {
            int rr = idx >> 6, c = idx & 63;
            KVs[rr * 65 + c] = Kt[((size_t)(jt * 64 + rr) * BATCH + b) * DMODEL + hoff + c];
        }
        __syncthreads();

        // S = Q * K^T : 16x16 thread grid, 4x4 microtile
        float s[4][4];
#pragma unroll
        for (int i = 0; i < 4; i++)
#pragma unroll
            for (int j = 0; j < 4; j++) s[i][j] = 0.f;
        const float* q0 = Qs + (4 * tr + 0) * 64;
        const float* q1 = Qs + (4 * tr + 1) * 64;
        const float* q2 = Qs + (4 * tr + 2) * 64;
        const float* q3 = Qs + (4 * tr + 3) * 64;
        const float* k0 = KVs + (4 * tc + 0) * 65;
        const float* k1 = KVs + (4 * tc + 1) * 65;
        const float* k2 = KVs + (4 * tc + 2) * 65;
        const float* k3 = KVs + (4 * tc + 3) * 65;
#pragma unroll 8
        for (int d = 0; d < 64; d++) {
            float a0 = q0[d], a1 = q1[d], a2 = q2[d], a3 = q3[d];
            float c0 = k0[d], c1 = k1[d], c2 = k2[d], c3 = k3[d];
            s[0][0] += a0 * c0; s[0][1] += a0 * c1; s[0][2] += a0 * c2; s[0][3] += a0 * c3;
            s[1][0] += a1 * c0; s[1][1] += a1 * c1; s[1][2] += a1 * c2; s[1][3] += a1 * c3;
            s[2][0] += a2 * c0; s[2][1] += a2 * c1; s[2][2] += a2 * c2; s[2][3] += a2 * c3;
            s[3][0] += a3 * c0; s[3][1] += a3 * c1; s[3][2] += a3 * c2; s[3][3] += a3 * c3;
        }
#pragma unroll
        for (int i = 0; i < 4; i++) {
            int lq = l0 + 4 * tr + i;
#pragma unroll
            for (int j = 0; j < 4; j++) {
                int gk = jt * 64 + 4 * tc + j;
                Ss[(4 * tr + i) * 65 + 4 * tc + j] = (gk > lq) ? -INFINITY : s[i][j] * scale;
            }
        }
        __syncthreads();

        // load V tile (overwrites K) + online softmax update (disjoint smem)
        for (int idx = tid; idx < 64 * 64; idx += 256) {
            int rr = idx >> 6, c = idx & 63;
            KVs[rr * 65 + c] = V[((size_t)(jt * 64 + rr) * BATCH + b) * DMODEL + hoff + c];
        }
        float ps[16];
        float tmax = -INFINITY;
#pragma unroll
        for (int n = 0; n < 16; n++) {
            ps[n] = Ss[r * 65 + sub * 16 + n];
            tmax = fmaxf(tmax, ps[n]);
        }
        tmax = fmaxf(tmax, __shfl_xor_sync(0xffffffffu, tmax, 1));
        tmax = fmaxf(tmax, __shfl_xor_sync(0xffffffffu, tmax, 2));
        float newm = fmaxf(mrow, tmax);
        float corr = expf(mrow - newm);
        mrow = newm;
        float psum = 0.f;
#pragma unroll
        for (int n = 0; n < 16; n++) {
            float p = expf(ps[n] - newm);
            Ss[r * 65 + sub * 16 + n] = p;
            psum += p;
        }
        psum += __shfl_xor_sync(0xffffffffu, psum, 1);
        psum += __shfl_xor_sync(0xffffffffu, psum, 2);
        lsum = lsum * corr + psum;
#pragma unroll
        for (int i = 0; i < 16; i++) acc[i] *= corr;
        __syncthreads();

        // ctx += P * V : thread (r, sub) owns cols sub*16..sub*16+15 of row r
        const int d0 = sub * 16;
#pragma unroll 4
        for (int n = 0; n < 64; n++) {
            float p = Ss[r * 65 + n];
            const float* vp = KVs + n * 65 + d0;
#pragma unroll
            for (int dd = 0; dd < 16; dd++) acc[dd] += p * vp[dd];
        }
    }

    float inv = 1.f / lsum;
    float* op = out + ((size_t)(l0 + r) * BATCH + b) * DMODEL + hoff + sub * 16;
#pragma unroll
    for (int dd = 0; dd < 16; dd++) op[dd] = acc[dd] * inv;
}

// ---------------- fused residual-add + LayerNorm (torch-style, ddof=1) ----------------
__global__ void __launch_bounds__(128) add_ln_kernel(float* __restrict__ x,
                                                     const float* __restrict__ y,
                                                     const float* __restrict__ a,
                                                     const float* __restrict__ b)
{
    const int m = blockIdx.x;
    const int tid = threadIdx.x;
    const size_t base = (size_t)m * DMODEL;
    __shared__ float red[8];

    float v[4];
#pragma unroll
    for (int j = 0; j < 4; j++) {
        int d = tid + j * 128;
        float xv = x[base + d];
        if (y) xv += y[base + d];
        v[j] = xv;
    }
    float s = v[0] + v[1] + v[2] + v[3];
#pragma unroll
    for (int o = 16; o > 0; o >>= 1) s += __shfl_xor_sync(0xffffffffu, s, o);
    if ((tid & 31) == 0) red[tid >> 5] = s;
    __syncthreads();
    float mean = (red[0] + red[1] + red[2] + red[3]) * (1.f / 512.f);

    float ss = 0.f;
#pragma unroll
    for (int j = 0; j < 4; j++) {
        float dm = v[j] - mean;
        ss += dm * dm;
    }
#pragma unroll
    for (int o = 16; o > 0; o >>= 1) ss += __shfl_xor_sync(0xffffffffu, ss, o);
    if ((tid & 31) == 0) red[4 + (tid >> 5)] = ss;
    __syncthreads();
    float var = (red[4] + red[5] + red[6] + red[7]) * (1.f / 511.f);
    float inv = 1.f / (sqrtf(var) + 1e-6f);

#pragma unroll
    for (int j = 0; j < 4; j++) {
        int d = tid + j * 128;
        x[base + d] = a[d] * (v[j] - mean) * inv + b[d];
    }
}

// ---------------- orchestration ----------------
extern "C" void kernel_launch(void* const* d_in, const int* in_sizes, int n_in,
                              void* d_out, int out_size)
{
    (void)in_sizes; (void)n_in; (void)out_size;
    const int*   input = (const int*)  d_in[0];
    const float* emb   = (const float*)d_in[1];
    const float* Wq    = (const float*)d_in[2];
    const float* Wk    = (const float*)d_in[3];
    const float* Wv    = (const float*)d_in[4];
    const float* Wo    = (const float*)d_in[5];
    const float* w1    = (const float*)d_in[6];
    const float* b1    = (const float*)d_in[7];
    const float* w2    = (const float*)d_in[8];
    const float* b2    = (const float*)d_in[9];
    const float* ln1a  = (const float*)d_in[10];
    const float* ln1b  = (const float*)d_in[11];
    const float* ln2a  = (const float*)d_in[12];
    const float* ln2b  = (const float*)d_in[13];
    const float* fna   = (const float*)d_in[14];
    const float* fnb   = (const float*)d_in[15];
    const float* decW  = (const float*)d_in[16];
    const float* decb  = (const float*)d_in[17];
    float* out = (float*)d_out;

    float *x, *q, *k, *v, *ctx, *t, *ff;
    cudaGetSymbolAddress((void**)&x,   g_x);
    cudaGetSymbolAddress((void**)&q,   g_q);
    cudaGetSymbolAddress((void**)&k,   g_k);
    cudaGetSymbolAddress((void**)&v,   g_v);
    cudaGetSymbolAddress((void**)&ctx, g_ctx);
    cudaGetSymbolAddress((void**)&t,   g_t);
    cudaGetSymbolAddress((void**)&ff,  g_ff);

    cudaFuncSetAttribute(attn_kernel, cudaFuncAttributeMaxDynamicSharedMemorySize, ATTN_SMEM);

    embed_kernel<<<MROWS, 128>>>(x, input, emb);

    const dim3 gpD(DMODEL / GBN, MROWS / GBM);    // (4, 64)
    const dim3 gpF(DFFN / GBN, MROWS / GBM);      // (16, 64)
    const dim3 gpV(NVOCAB / GBN, MROWS / GBM);    // (250, 64)
    const dim3 gAttn(LSEQ / 64, BATCH, NHEAD);

    for (int l = 0; l < NLAYER; l++) {
        const float* wq = Wq + (size_t)l * DMODEL * DMODEL;
        const float* wk = Wk + (size_t)l * DMODEL * DMODEL;
        const float* wv = Wv + (size_t)l * DMODEL * DMODEL;
        const float* wo = Wo + (size_t)l * DMODEL * DMODEL;

        sgemm_kernel<false, false><<<gpD, 256>>>(q, x, wq, nullptr, MROWS, DMODEL, DMODEL);
        sgemm_kernel<false, false><<<gpD, 256>>>(k, x, wk, nullptr, MROWS, DMODEL, DMODEL);
        sgemm_kernel<false, false><<<gpD, 256>>>(v, x, wv, nullptr, MROWS, DMODEL, DMODEL);

        attn_kernel<<<gAttn, 256, ATTN_SMEM>>>(ctx, q, k, v);

        sgemm_kernel<false, false><<<gpD, 256>>>(t, ctx, wo, nullptr, MROWS, DMODEL, DMODEL);
        add_ln_kernel<<<MROWS, 128>>>(x, t, ln1a + l * DMODEL, ln1b + l * DMODEL);

        sgemm_kernel<true, true><<<gpF, 256>>>(ff, x, w1 + (size_t)l * DFFN * DMODEL,
                                               b1 + l * DFFN, MROWS, DFFN, DMODEL);
        sgemm_kernel<true, false><<<gpD, 256>>>(t, ff, w2 + (size_t)l * DMODEL * DFFN,
                                                b2 + l * DMODEL, MROWS, DMODEL, DFFN);
        add_ln_kernel<<<MROWS, 128>>>(x, t, ln2a + l * DMODEL, ln2b + l * DMODEL);
    }

    add_ln_kernel<<<MROWS, 128>>>(x, nullptr, fna, fnb);
    sgemm_kernel<true, false><<<gpV, 256>>>(out, x, decW, decb, MROWS, NVOCAB, DMODEL);
}

// round 3
// speedup vs baseline: 1.4615x; 1.4615x over previous
#include <cuda_runtime.h>
#include <cuda_bf16.h>
#include <math.h>
#include <stdint.h>

#define LSEQ 2048
#define BATCH 4
#define DMODEL 512
#define NHEAD 8
#define DKH 64
#define NLAYER 4
#define DFFN 2048
#define MROWS (LSEQ * BATCH)   // 8192
#define NVOCAB 32000

// ---------------- scratch (device globals; no allocation allowed) ----------------
__device__ float g_x[MROWS * DMODEL];
__device__ float g_q[MROWS * DMODEL];
__device__ float g_k[MROWS * DMODEL];
__device__ float g_v[MROWS * DMODEL];
__device__ float g_ctx[MROWS * DMODEL];
__device__ float g_t[MROWS * DMODEL];
__device__ float g_ff[MROWS * DFFN];

// weight split storage (bf16 hi/lo), element offsets:
#define WQ0 0
#define WK0 1048576
#define WV0 2097152
#define WO0 3145728
#define W10 4194304
#define W20 8388608
#define WD0 12582912
#define WTOT 28966912
__device__ __nv_bfloat16 g_whi[WTOT];
__device__ __nv_bfloat16 g_wlo[WTOT];
// activation split storage (max 8192*2048)
__device__ __nv_bfloat16 g_ahi[MROWS * DFFN];
__device__ __nv_bfloat16 g_alo[MROWS * DFFN];

// ---------------- fp32 -> bf16 hi/lo split ----------------
__global__ void __launch_bounds__(256) split_kernel(__nv_bfloat16* __restrict__ hi,
                                                    __nv_bfloat16* __restrict__ lo,
                                                    const float* __restrict__ src,
                                                    int n4)
{
    int i = blockIdx.x * 256 + threadIdx.x;
    if (i >= n4) return;
    float4 v = ((const float4*)src)[i];
    __nv_bfloat16 h0 = __float2bfloat16(v.x);
    __nv_bfloat16 h1 = __float2bfloat16(v.y);
    __nv_bfloat16 h2 = __float2bfloat16(v.z);
    __nv_bfloat16 h3 = __float2bfloat16(v.w);
    __nv_bfloat16 l0 = __float2bfloat16(v.x - __bfloat162float(h0));
    __nv_bfloat16 l1 = __float2bfloat16(v.y - __bfloat162float(h1));
    __nv_bfloat16 l2 = __float2bfloat16(v.z - __bfloat162float(h2));
    __nv_bfloat16 l3 = __float2bfloat16(v.w - __bfloat162float(h3));
    __nv_bfloat162 ph0; ph0.x = h0; ph0.y = h1;
    __nv_bfloat162 ph1; ph1.x = h2; ph1.y = h3;
    __nv_bfloat162 pl0; pl0.x = l0; pl0.y = l1;
    __nv_bfloat162 pl1; pl1.x = l2; pl1.y = l3;
    ((__nv_bfloat162*)hi)[2 * i + 0] = ph0;
    ((__nv_bfloat162*)hi)[2 * i + 1] = ph1;
    ((__nv_bfloat162*)lo)[2 * i + 0] = pl0;
    ((__nv_bfloat162*)lo)[2 * i + 1] = pl1;
}

// ---------------- bf16 mma.sync GEMM: C[M,N] = A[M,K]*W[N,K]^T, 3x split ----------------
// BM=128, BN=128, BK=32, 256 threads, warp grid 2(m) x 4(n), warp tile 64x32.
#define TSTRIDE 80                   // bytes per smem row (64B data + 16B pad)
#define TILE_B (128 * TSTRIDE)       // 10240 per operand tile
#define STAGE_B (4 * TILE_B)         // Ah, Al, Bh, Bl
#define GEMM_SMEM (2 * STAGE_B)      // 81920 (double buffered)
#define OFF_AH 0
#define OFF_AL TILE_B
#define OFF_BH (2 * TILE_B)
#define OFF_BL (3 * TILE_B)

__device__ __forceinline__ uint32_t s2u(const void* p) {
    uint32_t a;
    asm("{ .reg .u64 t; cvta.to.shared.u64 t, %1; cvt.u32.u64 %0, t; }" : "=r"(a) : "l"(p));
    return a;
}
__device__ __forceinline__ void cpa16(uint32_t d, const void* s) {
    asm volatile("cp.async.cg.shared.global [%0], [%1], 16;" :: "r"(d), "l"(s));
}

#define LDSM4(r, a) \
    asm volatile("ldmatrix.sync.aligned.m8n8.x4.shared.b16 {%0,%1,%2,%3}, [%4];" \
        : "=r"((r)[0]), "=r"((r)[1]), "=r"((r)[2]), "=r"((r)[3]) : "r"(a))

#define MMA16816(c, a, b0, b1) \
    asm volatile("mma.sync.aligned.m16n8k16.row.col.f32.bf16.bf16.f32 " \
        "{%0,%1,%2,%3}, {%4,%5,%6,%7}, {%8,%9}, {%0,%1,%2,%3};" \
        : "+f"((c)[0]), "+f"((c)[1]), "+f"((c)[2]), "+f"((c)[3]) \
        : "r"((a)[0]), "r"((a)[1]), "r"((a)[2]), "r"((a)[3]), "r"(b0), "r"(b1))

template <bool BIAS, bool RELU>
__global__ void __launch_bounds__(256) gemm_mma(float* __restrict__ C,
                                                const __nv_bfloat16* __restrict__ Ahi,
                                                const __nv_bfloat16* __restrict__ Alo,
                                                const __nv_bfloat16* __restrict__ Bhi,
                                                const __nv_bfloat16* __restrict__ Blo,
                                                const float* __restrict__ bias,
                                                int M, int N, int K)
{
    extern __shared__ char smem[];
    const uint32_t sb = s2u(smem);
    const int tid = threadIdx.x;
    const int warp = tid >> 5, lane = tid & 31;
    const int bm = blockIdx.y * 128;
    const int bn = blockIdx.x * 128;
    const int warp_m = warp >> 2;          // 0..1
    const int warp_n = warp & 3;           // 0..3
    const int nch = K >> 5;                // K/32

    const __nv_bfloat16* pAh = Ahi + (size_t)bm * K;
    const __nv_bfloat16* pAl = Alo + (size_t)bm * K;
    const __nv_bfloat16* pBh = Bhi + (size_t)bn * K;
    const __nv_bfloat16* pBl = Blo + (size_t)bn * K;

    // loader: 512 (row,seg) pairs per operand tile; seg = 16B = 8 bf16
    const int lrow = tid >> 1;                  // 0..127
    const int lseg2 = (tid & 1) * 2;            // 0 or 2

    auto load_stage = [&](uint32_t st, int k0) {
#pragma unroll
        for (int ss = 0; ss < 2; ss++) {
            int seg = lseg2 + ss;
            uint32_t d = st + lrow * TSTRIDE + seg * 16;
            const size_t go = (size_t)lrow * K + k0 + seg * 8;
            cpa16(d + OFF_AH, pAh + go);
            cpa16(d + OFF_AL, pAl + go);
            cpa16(d + OFF_BH, pBh + go);
            cpa16(d + OFF_BL, pBl + go);
        }
    };

    float acc[16][4];
#pragma unroll
    for (int i = 0; i < 16; i++)
#pragma unroll
        for (int j = 0; j < 4; j++) acc[i][j] = 0.f;

    // lane->ldmatrix address components
    const int g = lane >> 3, lr = lane & 7;
    // A: matrices (rows0-7,k0) (rows8-15,k0) (rows0-7,k8) (rows8-15,k8)
    const int a_row = lr + (g & 1) * 8;
    const int a_k8 = g >> 1;
    // B: matrices (n0-7,k0) (n0-7,k8) (n8-15,k0) (n8-15,k8)
    const int b_row = lr + (g >> 1) * 8;
    const int b_k8 = g & 1;

    load_stage(sb, 0);
    asm volatile("cp.async.commit_group;" ::: "memory");

    for (int i = 0; i < nch; i++) {
        const uint32_t st = sb + (i & 1) * STAGE_B;
        __syncthreads();   // all warps done reading the stage we are about to overwrite
        if (i + 1 < nch) load_stage(sb + ((i + 1) & 1) * STAGE_B, (i + 1) * 32);
        asm volatile("cp.async.commit_group;" ::: "memory");
        asm volatile("cp.async.wait_group 1;" ::: "memory");
        __syncthreads();

#pragma unroll
        for (int ks = 0; ks < 2; ks++) {
            uint32_t bh[8], bl[8];
#pragma unroll
            for (int npair = 0; npair < 2; npair++) {
                uint32_t baddr = st + (warp_n * 32 + npair * 16 + b_row) * TSTRIDE +
                                 (ks * 2 + b_k8) * 16;
                LDSM4(&bh[npair * 4], baddr + OFF_BH);
                LDSM4(&bl[npair * 4], baddr + OFF_BL);
            }
#pragma unroll
            for (int mi = 0; mi < 4; mi++) {
                uint32_t ah[4], al[4];
                uint32_t aaddr = st + (warp_m * 64 + mi * 16 + a_row) * TSTRIDE +
                                 (ks * 2 + a_k8) * 16;
                LDSM4(ah, aaddr + OFF_AH);
                LDSM4(al, aaddr + OFF_AL);
#pragma unroll
                for (int nj = 0; nj < 4; nj++)
                    MMA16816(acc[mi * 4 + nj], ah, bh[nj * 2], bh[nj * 2 + 1]);
#pragma unroll
                for (int nj = 0; nj < 4; nj++)
                    MMA16816(acc[mi * 4 + nj], ah, bl[nj * 2], bl[nj * 2 + 1]);
#pragma unroll
                for (int nj = 0; nj < 4; nj++)
                    MMA16816(acc[mi * 4 + nj], al, bh[nj * 2], bh[nj * 2 + 1]);
            }
        }
    }

    // epilogue
    const int tm = lane >> 2, tn = (lane & 3) * 2;
#pragma unroll
    for (int mi = 0; mi < 4; mi++) {
#pragma unroll
        for (int nj = 0; nj < 4; nj++) {
            const float* a4 = acc[mi * 4 + nj];
            int row0 = bm + warp_m * 64 + mi * 16 + tm;
            int col = bn + warp_n * 32 + nj * 8 + tn;
            float b0 = 0.f, b1 = 0.f;
            if (BIAS) { b0 = bias[col]; b1 = bias[col + 1]; }
            float v0 = a4[0] + b0, v1 = a4[1] + b1;
            float v2 = a4[2] + b0, v3 = a4[3] + b1;
            if (RELU) {
                v0 = fmaxf(v0, 0.f); v1 = fmaxf(v1, 0.f);
                v2 = fmaxf(v2, 0.f); v3 = fmaxf(v3, 0.f);
            }
            *(float2*)(C + (size_t)row0 * N + col) = make_float2(v0, v1);
            *(float2*)(C + (size_t)(row0 + 8) * N + col) = make_float2(v2, v3);
        }
    }
}

// ---------------- embedding + sinusoidal positional encoding ----------------
__global__ void __launch_bounds__(128) embed_kernel(float* __restrict__ x,
                                                    const int* __restrict__ tok,
                                                    const float* __restrict__ emb)
{
    int m = blockIdx.x;
    int l = m >> 2;
    int t = tok[m];
    const float sq = 22.627416997969522f;
    const double nlog = 9.210340371976184;
#pragma unroll
    for (int j = 0; j < 4; j++) {
        int d = threadIdx.x + j * 128;
        int i = d >> 1;
        float freqf = (float)exp(-(double)(2 * i) * (nlog / 512.0));
        float angf = (float)l * freqf;
        double ang = (double)angf;
        float pe = (d & 1) ? (float)cos(ang) : (float)sin(ang);
        x[(size_t)m * DMODEL + d] = emb[(size_t)t * DMODEL + d] * sq + pe;
    }
}

// ---------------- flash attention (fp32, causal) ----------------
#define ATTN_SMEM ((64 * 64 + 64 * 65 + 64 * 65) * 4)

__global__ void __launch_bounds__(256) attn_kernel(float* __restrict__ out,
                                                   const float* __restrict__ Q,
                                                   const float* __restrict__ Kt,
                                                   const float* __restrict__ V)
{
    extern __shared__ float sm[];
    float* Qs = sm;
    float* KVs = sm + 64 * 64;
    float* Ss = KVs + 64 * 65;

    const int tid = threadIdx.x;
    const int b = blockIdx.y, h = blockIdx.z;
    const int l0 = blockIdx.x * 64;
    const int hoff = h * DKH;
    const float scale = 0.125f;

    for (int idx = tid; idx < 64 * 64; idx += 256) {
        int r = idx >> 6, c = idx & 63;
        Qs[r * 64 + c] = Q[((size_t)(l0 + r) * BATCH + b) * DMODEL + hoff + c];
    }

    const int r = tid >> 2;
    const int sub = tid & 3;
    const int tr = tid >> 4, tc = tid & 15;

    float mrow = -INFINITY, lsum = 0.f;
    float acc[16];
#pragma unroll
    for (int i = 0; i < 16; i++) acc[i] = 0.f;

    const int ntiles = blockIdx.x + 1;
    for (int jt = 0; jt < ntiles; jt++) {
        __syncthreads();
        for (int idx = tid; idx < 64 * 64; idx += 256) {
            int rr = idx >> 6, c = idx & 63;
            KVs[rr * 65 + c] = Kt[((size_t)(jt * 64 + rr) * BATCH + b) * DMODEL + hoff + c];
        }
        __syncthreads();

        float s[4][4];
#pragma unroll
        for (int i = 0; i < 4; i++)
#pragma unroll
            for (int j = 0; j < 4; j++) s[i][j] = 0.f;
        const float* q0 = Qs + (4 * tr + 0) * 64;
        const float* q1 = Qs + (4 * tr + 1) * 64;
        const float* q2 = Qs + (4 * tr + 2) * 64;
        const float* q3 = Qs + (4 * tr + 3) * 64;
        const float* k0 = KVs + (4 * tc + 0) * 65;
        const float* k1 = KVs + (4 * tc + 1) * 65;
        const float* k2 = KVs + (4 * tc + 2) * 65;
        const float* k3 = KVs + (4 * tc + 3) * 65;
#pragma unroll 8
        for (int d = 0; d < 64; d++) {
            float a0 = q0[d], a1 = q1[d], a2 = q2[d], a3 = q3[d];
            float c0 = k0[d], c1 = k1[d], c2 = k2[d], c3 = k3[d];
            s[0][0] += a0 * c0; s[0][1] += a0 * c1; s[0][2] += a0 * c2; s[0][3] += a0 * c3;
            s[1][0] += a1 * c0; s[1][1] += a1 * c1; s[1][2] += a1 * c2; s[1][3] += a1 * c3;
            s[2][0] += a2 * c0; s[2][1] += a2 * c1; s[2][2] += a2 * c2; s[2][3] += a2 * c3;
            s[3][0] += a3 * c0; s[3][1] += a3 * c1; s[3][2] += a3 * c2; s[3][3] += a3 * c3;
        }
#pragma unroll
        for (int i = 0; i < 4; i++) {
            int lq = l0 + 4 * tr + i;
#pragma unroll
            for (int j = 0; j < 4; j++) {
                int gk = jt * 64 + 4 * tc + j;
                Ss[(4 * tr + i) * 65 + 4 * tc + j] = (gk > lq) ? -INFINITY : s[i][j] * scale;
            }
        }
        __syncthreads();

        for (int idx = tid; idx < 64 * 64; idx += 256) {
            int rr = idx >> 6, c = idx & 63;
            KVs[rr * 65 + c] = V[((size_t)(jt * 64 + rr) * BATCH + b) * DMODEL + hoff + c];
        }
        float ps[16];
        float tmax = -INFINITY;
#pragma unroll
        for (int n = 0; n < 16; n++) {
            ps[n] = Ss[r * 65 + sub * 16 + n];
            tmax = fmaxf(tmax, ps[n]);
        }
        tmax = fmaxf(tmax, __shfl_xor_sync(0xffffffffu, tmax, 1));
        tmax = fmaxf(tmax, __shfl_xor_sync(0xffffffffu, tmax, 2));
        float newm = fmaxf(mrow, tmax);
        float corr = expf(mrow - newm);
        mrow = newm;
        float psum = 0.f;
#pragma unroll
        for (int n = 0; n < 16; n++) {
            float p = expf(ps[n] - newm);
            Ss[r * 65 + sub * 16 + n] = p;
            psum += p;
        }
        psum += __shfl_xor_sync(0xffffffffu, psum, 1);
        psum += __shfl_xor_sync(0xffffffffu, psum, 2);
        lsum = lsum * corr + psum;
#pragma unroll
        for (int i = 0; i < 16; i++) acc[i] *= corr;
        __syncthreads();

        const int d0 = sub * 16;
#pragma unroll 4
        for (int n = 0; n < 64; n++) {
            float p = Ss[r * 65 + n];
            const float* vp = KVs + n * 65 + d0;
#pragma unroll
            for (int dd = 0; dd < 16; dd++) acc[dd] += p * vp[dd];
        }
    }

    float inv = 1.f / lsum;
    float* op = out + ((size_t)(l0 + r) * BATCH + b) * DMODEL + hoff + sub * 16;
#pragma unroll
    for (int dd = 0; dd < 16; dd++) op[dd] = acc[dd] * inv;
}

// ---------------- fused residual-add + LayerNorm (torch-style, ddof=1) ----------------
__global__ void __launch_bounds__(128) add_ln_kernel(float* __restrict__ x,
                                                     const float* __restrict__ y,
                                                     const float* __restrict__ a,
                                                     const float* __restrict__ b)
{
    const int m = blockIdx.x;
    const int tid = threadIdx.x;
    const size_t base = (size_t)m * DMODEL;
    __shared__ float red[8];

    float v[4];
#pragma unroll
    for (int j = 0; j < 4; j++) {
        int d = tid + j * 128;
        float xv = x[base + d];
        if (y) xv += y[base + d];
        v[j] = xv;
    }
    float s = v[0] + v[1] + v[2] + v[3];
#pragma unroll
    for (int o = 16; o > 0; o >>= 1) s += __shfl_xor_sync(0xffffffffu, s, o);
    if ((tid & 31) == 0) red[tid >> 5] = s;
    __syncthreads();
    float mean = (red[0] + red[1] + red[2] + red[3]) * (1.f / 512.f);

    float ss = 0.f;
#pragma unroll
    for (int j = 0; j < 4; j++) {
        float dm = v[j] - mean;
        ss += dm * dm;
    }
#pragma unroll
    for (int o = 16; o > 0; o >>= 1) ss += __shfl_xor_sync(0xffffffffu, ss, o);
    if ((tid & 31) == 0) red[4 + (tid >> 5)] = ss;
    __syncthreads();
    float var = (red[4] + red[5] + red[6] + red[7]) * (1.f / 511.f);
    float inv = 1.f / (sqrtf(var) + 1e-6f);

#pragma unroll
    for (int j = 0; j < 4; j++) {
        int d = tid + j * 128;
        x[base + d] = a[d] * (v[j] - mean) * inv + b[d];
    }
}

// ---------------- orchestration ----------------
extern "C" void kernel_launch(void* const* d_in, const int* in_sizes, int n_in,
                              void* d_out, int out_size)
{
    (void)in_sizes; (void)n_in; (void)out_size;
    const int*   input = (const int*)  d_in[0];
    const float* emb   = (const float*)d_in[1];
    const float* Wq    = (const float*)d_in[2];
    const float* Wk    = (const float*)d_in[3];
    const float* Wv    = (const float*)d_in[4];
    const float* Wo    = (const float*)d_in[5];
    const float* w1    = (const float*)d_in[6];
    const float* b1    = (const float*)d_in[7];
    const float* w2    = (const float*)d_in[8];
    const float* b2    = (const float*)d_in[9];
    const float* ln1a  = (const float*)d_in[10];
    const float* ln1b  = (const float*)d_in[11];
    const float* ln2a  = (const float*)d_in[12];
    const float* ln2b  = (const float*)d_in[13];
    const float* fna   = (const float*)d_in[14];
    const float* fnb   = (const float*)d_in[15];
    const float* decW  = (const float*)d_in[16];
    const float* decb  = (const float*)d_in[17];
    float* out = (float*)d_out;

    float *x, *q, *k, *v, *ctx, *t, *ff;
    __nv_bfloat16 *whi, *wlo, *ahi, *alo;
    cudaGetSymbolAddress((void**)&x,   g_x);
    cudaGetSymbolAddress((void**)&q,   g_q);
    cudaGetSymbolAddress((void**)&k,   g_k);
    cudaGetSymbolAddress((void**)&v,   g_v);
    cudaGetSymbolAddress((void**)&ctx, g_ctx);
    cudaGetSymbolAddress((void**)&t,   g_t);
    cudaGetSymbolAddress((void**)&ff,  g_ff);
    cudaGetSymbolAddress((void**)&whi, g_whi);
    cudaGetSymbolAddress((void**)&wlo, g_wlo);
    cudaGetSymbolAddress((void**)&ahi, g_ahi);
    cudaGetSymbolAddress((void**)&alo, g_alo);

    cudaFuncSetAttribute(attn_kernel, cudaFuncAttributeMaxDynamicSharedMemorySize, ATTN_SMEM);
    cudaFuncSetAttribute(gemm_mma<false, false>, cudaFuncAttributeMaxDynamicSharedMemorySize, GEMM_SMEM);
    cudaFuncSetAttribute(gemm_mma<true, true>,   cudaFuncAttributeMaxDynamicSharedMemorySize, GEMM_SMEM);
    cudaFuncSetAttribute(gemm_mma<true, false>,  cudaFuncAttributeMaxDynamicSharedMemorySize, GEMM_SMEM);

    // weight splits (recomputed each call; deterministic)
    split_kernel<<<(4 * 262144) / 1024, 256>>>(whi + WQ0, wlo + WQ0, Wq, (4 * 262144) / 4);
    split_kernel<<<(4 * 262144) / 1024, 256>>>(whi + WK0, wlo + WK0, Wk, (4 * 262144) / 4);
    split_kernel<<<(4 * 262144) / 1024, 256>>>(whi + WV0, wlo + WV0, Wv, (4 * 262144) / 4);
    split_kernel<<<(4 * 262144) / 1024, 256>>>(whi + WO0, wlo + WO0, Wo, (4 * 262144) / 4);
    split_kernel<<<4194304 / 1024, 256>>>(whi + W10, wlo + W10, w1, 4194304 / 4);
    split_kernel<<<4194304 / 1024, 256>>>(whi + W20, wlo + W20, w2, 4194304 / 4);
    split_kernel<<<16384000 / 1024, 256>>>(whi + WD0, wlo + WD0, decW, 16384000 / 4);

    embed_kernel<<<MROWS, 128>>>(x, input, emb);

    const dim3 gD(DMODEL / 128, MROWS / 128);     // (4, 64)
    const dim3 gF(DFFN / 128, MROWS / 128);       // (16, 64)
    const dim3 gV(NVOCAB / 128, MROWS / 128);     // (250, 64)
    const dim3 gAttn(LSEQ / 64, BATCH, NHEAD);
    const int XN4 = (MROWS * DMODEL) / 4;
    const int FN4 = (MROWS * DFFN) / 4;

    for (int l = 0; l < NLAYER; l++) {
        const size_t wofs = (size_t)l * DMODEL * DMODEL;
        const size_t f1 = (size_t)l * DFFN * DMODEL;

        split_kernel<<<XN4 / 256, 256>>>(ahi, alo, x, XN4);
        gemm_mma<false, false><<<gD, 256, GEMM_SMEM>>>(q, ahi, alo, whi + WQ0 + wofs, wlo + WQ0 + wofs,
                                                       nullptr, MROWS, DMODEL, DMODEL);
        gemm_mma<false, false><<<gD, 256, GEMM_SMEM>>>(k, ahi, alo, whi + WK0 + wofs, wlo + WK0 + wofs,
                                                       nullptr, MROWS, DMODEL, DMODEL);
        gemm_mma<false, false><<<gD, 256, GEMM_SMEM>>>(v, ahi, alo, whi + WV0 + wofs, wlo + WV0 + wofs,
                                                       nullptr, MROWS, DMODEL, DMODEL);

        attn_kernel<<<gAttn, 256, ATTN_SMEM>>>(ctx, q, k, v);

        split_kernel<<<XN4 / 256, 256>>>(ahi, alo, ctx, XN4);
        gemm_mma<false, false><<<gD, 256, GEMM_SMEM>>>(t, ahi, alo, whi + WO0 + wofs, wlo + WO0 + wofs,
                                                       nullptr, MROWS, DMODEL, DMODEL);
        add_ln_kernel<<<MROWS, 128>>>(x, t, ln1a + l * DMODEL, ln1b + l * DMODEL);

        split_kernel<<<XN4 / 256, 256>>>(ahi, alo, x, XN4);
        gemm_mma<true, true><<<gF, 256, GEMM_SMEM>>>(ff, ahi, alo, whi + W10 + f1, wlo + W10 + f1,
                                                     b1 + l * DFFN, MROWS, DFFN, DMODEL);
        split_kernel<<<FN4 / 256, 256>>>(ahi, alo, ff, FN4);
        gemm_mma<true, false><<<gD, 256, GEMM_SMEM>>>(t, ahi, alo, whi + W20 + f1, wlo + W20 + f1,
                                                      b2 + l * DMODEL, MROWS, DMODEL, DFFN);
        add_ln_kernel<<<MROWS, 128>>>(x, t, ln2a + l * DMODEL, ln2b + l * DMODEL);
    }

    add_ln_kernel<<<MROWS, 128>>>(x, nullptr, fna, fnb);
    split_kernel<<<XN4 / 256, 256>>>(ahi, alo, x, XN4);
    gemm_mma<true, false><<<gV, 256, GEMM_SMEM>>>(out, ahi, alo, whi + WD0, wlo + WD0,
                                                  decb, MROWS, NVOCAB, DMODEL);
}

// round 4
// speedup vs baseline: 2.8919x; 1.9787x over previous
#include <cuda_runtime.h>
#include <cuda_bf16.h>
#include <math.h>
#include <stdint.h>

#define LSEQ 2048
#define BATCH 4
#define DMODEL 512
#define NHEAD 8
#define DKH 64
#define NLAYER 4
#define DFFN 2048
#define MROWS (LSEQ * BATCH)   // 8192
#define NVOCAB 32000

// ---------------- scratch (device globals; no allocation allowed) ----------------
__device__ float g_x[MROWS * DMODEL];
__device__ float g_t[MROWS * DMODEL];
// split activations (hi at 0, lo at +MROWS*DMODEL)
__device__ __nv_bfloat16 g_xs[2 * MROWS * DMODEL];
__device__ __nv_bfloat16 g_qs[2 * MROWS * DMODEL];
__device__ __nv_bfloat16 g_ks[2 * MROWS * DMODEL];
__device__ __nv_bfloat16 g_vs[2 * MROWS * DMODEL];
__device__ __nv_bfloat16 g_cs[2 * MROWS * DMODEL];
__device__ __nv_bfloat16 g_ahi[MROWS * DFFN];
__device__ __nv_bfloat16 g_alo[MROWS * DFFN];

// weight split storage (bf16 hi/lo), element offsets:
#define WQ0 0
#define WK0 1048576
#define WV0 2097152
#define WO0 3145728
#define W10 4194304
#define W20 8388608
#define WD0 12582912
#define WTOT 28966912
__device__ __nv_bfloat16 g_whi[WTOT];
__device__ __nv_bfloat16 g_wlo[WTOT];

// ---------------- helpers ----------------
__device__ __forceinline__ uint32_t s2u(const void* p) {
    uint32_t a;
    asm("{ .reg .u64 t; cvta.to.shared.u64 t, %1; cvt.u32.u64 %0, t; }" : "=r"(a) : "l"(p));
    return a;
}
__device__ __forceinline__ void cpa16(uint32_t d, const void* s) {
    asm volatile("cp.async.cg.shared.global [%0], [%1], 16;" :: "r"(d), "l"(s));
}
__device__ __forceinline__ uint32_t bf2pack(float x, float y) {
    __nv_bfloat162 t; t.x = __float2bfloat16(x); t.y = __float2bfloat16(y);
    return *(uint32_t*)&t;
}

#define LDSM4(r, a) \
    asm volatile("ldmatrix.sync.aligned.m8n8.x4.shared.b16 {%0,%1,%2,%3}, [%4];" \
        : "=r"((r)[0]), "=r"((r)[1]), "=r"((r)[2]), "=r"((r)[3]) : "r"(a))
#define LDSM4T(r, a) \
    asm volatile("ldmatrix.sync.aligned.m8n8.x4.trans.shared.b16 {%0,%1,%2,%3}, [%4];" \
        : "=r"((r)[0]), "=r"((r)[1]), "=r"((r)[2]), "=r"((r)[3]) : "r"(a))

#define MMA16816(c, a, b0, b1) \
    asm volatile("mma.sync.aligned.m16n8k16.row.col.f32.bf16.bf16.f32 " \
        "{%0,%1,%2,%3}, {%4,%5,%6,%7}, {%8,%9}, {%0,%1,%2,%3};" \
        : "+f"((c)[0]), "+f"((c)[1]), "+f"((c)[2]), "+f"((c)[3]) \
        : "r"((a)[0]), "r"((a)[1]), "r"((a)[2]), "r"((a)[3]), "r"(b0), "r"(b1))

// ---------------- fp32 -> bf16 hi/lo split (weights only) ----------------
__global__ void __launch_bounds__(256) split_kernel(__nv_bfloat16* __restrict__ hi,
                                                    __nv_bfloat16* __restrict__ lo,
                                                    const float* __restrict__ src,
                                                    int n4)
{
    int i = blockIdx.x * 256 + threadIdx.x;
    if (i >= n4) return;
    float4 v = ((const float4*)src)[i];
    float h0f, h1f, h2f, h3f;
    __nv_bfloat16 h0 = __float2bfloat16(v.x); h0f = __bfloat162float(h0);
    __nv_bfloat16 h1 = __float2bfloat16(v.y); h1f = __bfloat162float(h1);
    __nv_bfloat16 h2 = __float2bfloat16(v.z); h2f = __bfloat162float(h2);
    __nv_bfloat16 h3 = __float2bfloat16(v.w); h3f = __bfloat162float(h3);
    ((uint32_t*)hi)[2 * i + 0] = bf2pack(v.x, v.y);
    ((uint32_t*)hi)[2 * i + 1] = bf2pack(v.z, v.w);
    ((uint32_t*)lo)[2 * i + 0] = bf2pack(v.x - h0f, v.y - h1f);
    ((uint32_t*)lo)[2 * i + 1] = bf2pack(v.z - h2f, v.w - h3f);
}

// ---------------- bf16 mma.sync GEMM: C[M,N] = A[M,K]*W[N,K]^T, 3x split ----------------
#define TSTRIDE 80
#define TILE_B (128 * TSTRIDE)
#define STAGE_B (4 * TILE_B)
#define GEMM_SMEM (2 * STAGE_B)
#define OFF_AH 0
#define OFF_AL TILE_B
#define OFF_BH (2 * TILE_B)
#define OFF_BL (3 * TILE_B)

template <bool BIAS, bool RELU, bool SPLIT>
__global__ void __launch_bounds__(256) gemm_mma(float* __restrict__ C,
                                                __nv_bfloat16* __restrict__ Oh,
                                                __nv_bfloat16* __restrict__ Ol,
                                                float oscale,
                                                const __nv_bfloat16* __restrict__ Ahi,
                                                const __nv_bfloat16* __restrict__ Alo,
                                                const __nv_bfloat16* __restrict__ Bhi,
                                                const __nv_bfloat16* __restrict__ Blo,
                                                const float* __restrict__ bias,
                                                int M, int N, int K)
{
    extern __shared__ char smem[];
    const uint32_t sb = s2u(smem);
    const int tid = threadIdx.x;
    const int warp = tid >> 5, lane = tid & 31;
    const int bm = blockIdx.y * 128;
    const int bn = blockIdx.x * 128;
    const int warp_m = warp >> 2;
    const int warp_n = warp & 3;
    const int nch = K >> 5;

    const __nv_bfloat16* pAh = Ahi + (size_t)bm * K;
    const __nv_bfloat16* pAl = Alo + (size_t)bm * K;
    const __nv_bfloat16* pBh = Bhi + (size_t)bn * K;
    const __nv_bfloat16* pBl = Blo + (size_t)bn * K;

    const int lrow = tid >> 1;
    const int lseg2 = (tid & 1) * 2;

    auto load_stage = [&](uint32_t st, int k0) {
#pragma unroll
        for (int ss = 0; ss < 2; ss++) {
            int seg = lseg2 + ss;
            uint32_t d = st + lrow * TSTRIDE + seg * 16;
            const size_t go = (size_t)lrow * K + k0 + seg * 8;
            cpa16(d + OFF_AH, pAh + go);
            cpa16(d + OFF_AL, pAl + go);
            cpa16(d + OFF_BH, pBh + go);
            cpa16(d + OFF_BL, pBl + go);
        }
    };

    float acc[16][4];
#pragma unroll
    for (int i = 0; i < 16; i++)
#pragma unroll
        for (int j = 0; j < 4; j++) acc[i][j] = 0.f;

    const int g = lane >> 3, lr = lane & 7;
    const int a_row = lr + (g & 1) * 8;
    const int a_k8 = g >> 1;
    const int b_row = lr + (g >> 1) * 8;
    const int b_k8 = g & 1;

    load_stage(sb, 0);
    asm volatile("cp.async.commit_group;" ::: "memory");

    for (int i = 0; i < nch; i++) {
        const uint32_t st = sb + (i & 1) * STAGE_B;
        __syncthreads();
        if (i + 1 < nch) load_stage(sb + ((i + 1) & 1) * STAGE_B, (i + 1) * 32);
        asm volatile("cp.async.commit_group;" ::: "memory");
        asm volatile("cp.async.wait_group 1;" ::: "memory");
        __syncthreads();

#pragma unroll
        for (int ks = 0; ks < 2; ks++) {
            uint32_t bh[8], bl[8];
#pragma unroll
            for (int npair = 0; npair < 2; npair++) {
                uint32_t baddr = st + (warp_n * 32 + npair * 16 + b_row) * TSTRIDE +
                                 (ks * 2 + b_k8) * 16;
                LDSM4(&bh[npair * 4], baddr + OFF_BH);
                LDSM4(&bl[npair * 4], baddr + OFF_BL);
            }
#pragma unroll
            for (int mi = 0; mi < 4; mi++) {
                uint32_t ah[4], al[4];
                uint32_t aaddr = st + (warp_m * 64 + mi * 16 + a_row) * TSTRIDE +
                                 (ks * 2 + a_k8) * 16;
                LDSM4(ah, aaddr + OFF_AH);
                LDSM4(al, aaddr + OFF_AL);
#pragma unroll
                for (int nj = 0; nj < 4; nj++)
                    MMA16816(acc[mi * 4 + nj], ah, bh[nj * 2], bh[nj * 2 + 1]);
#pragma unroll
                for (int nj = 0; nj < 4; nj++)
                    MMA16816(acc[mi * 4 + nj], ah, bl[nj * 2], bl[nj * 2 + 1]);
#pragma unroll
                for (int nj = 0; nj < 4; nj++)
                    MMA16816(acc[mi * 4 + nj], al, bh[nj * 2], bh[nj * 2 + 1]);
            }
        }
    }

    const int tm = lane >> 2, tn = (lane & 3) * 2;
#pragma unroll
    for (int mi = 0; mi < 4; mi++) {
#pragma unroll
        for (int nj = 0; nj < 4; nj++) {
            const float* a4 = acc[mi * 4 + nj];
            int row0 = bm + warp_m * 64 + mi * 16 + tm;
            int col = bn + warp_n * 32 + nj * 8 + tn;
            float b0 = 0.f, b1 = 0.f;
            if (BIAS) { b0 = bias[col]; b1 = bias[col + 1]; }
            float v0 = a4[0] * oscale + b0, v1 = a4[1] * oscale + b1;
            float v2 = a4[2] * oscale + b0, v3 = a4[3] * oscale + b1;
            if (RELU) {
                v0 = fmaxf(v0, 0.f); v1 = fmaxf(v1, 0.f);
                v2 = fmaxf(v2, 0.f); v3 = fmaxf(v3, 0.f);
            }
            if (SPLIT) {
                uint32_t h0 = bf2pack(v0, v1), h1 = bf2pack(v2, v3);
                __nv_bfloat162 hh0 = *(__nv_bfloat162*)&h0;
                __nv_bfloat162 hh1 = *(__nv_bfloat162*)&h1;
                uint32_t l0p = bf2pack(v0 - __bfloat162float(hh0.x),
                                       v1 - __bfloat162float(hh0.y));
                uint32_t l1p = bf2pack(v2 - __bfloat162float(hh1.x),
                                       v3 - __bfloat162float(hh1.y));
                *(uint32_t*)(Oh + (size_t)row0 * N + col) = h0;
                *(uint32_t*)(Oh + (size_t)(row0 + 8) * N + col) = h1;
                *(uint32_t*)(Ol + (size_t)row0 * N + col) = l0p;
                *(uint32_t*)(Ol + (size_t)(row0 + 8) * N + col) = l1p;
            } else {
                *(float2*)(C + (size_t)row0 * N + col) = make_float2(v0, v1);
                *(float2*)(C + (size_t)(row0 + 8) * N + col) = make_float2(v2, v3);
            }
        }
    }
}

// ---------------- embedding + positional encoding (fp32 + split out) ----------------
__global__ void __launch_bounds__(128) embed_kernel(float* __restrict__ x,
                                                    __nv_bfloat16* __restrict__ xh,
                                                    __nv_bfloat16* __restrict__ xl,
                                                    const int* __restrict__ tok,
                                                    const float* __restrict__ emb)
{
    int m = blockIdx.x;
    int l = m >> 2;
    int t = tok[m];
    const float sq = 22.627416997969522f;
    const double nlog = 9.210340371976184;
#pragma unroll
    for (int j = 0; j < 4; j++) {
        int d = threadIdx.x + j * 128;
        int i = d >> 1;
        float freqf = (float)exp(-(double)(2 * i) * (nlog / 512.0));
        float angf = (float)l * freqf;
        double ang = (double)angf;
        float pe = (d & 1) ? (float)cos(ang) : (float)sin(ang);
        float v = emb[(size_t)t * DMODEL + d] * sq + pe;
        x[(size_t)m * DMODEL + d] = v;
        __nv_bfloat16 h = __float2bfloat16(v);
        xh[(size_t)m * DMODEL + d] = h;
        xl[(size_t)m * DMODEL + d] = __float2bfloat16(v - __bfloat162float(h));
    }
}

// ---------------- mma flash attention (causal, 3x bf16 split) ----------------
#define AT_S 144
#define AQ_B (128 * AT_S)        // 18432
#define AKV_TILE (64 * AT_S)     // 9216
#define AKV_STAGE (4 * AKV_TILE) // 36864
#define ATTN_SMEM (2 * AQ_B + 2 * AKV_STAGE)  // 110592

__global__ void __launch_bounds__(256) attn_mma(
    __nv_bfloat16* __restrict__ ctxh, __nv_bfloat16* __restrict__ ctxl,
    const __nv_bfloat16* __restrict__ qh, const __nv_bfloat16* __restrict__ ql,
    const __nv_bfloat16* __restrict__ kh, const __nv_bfloat16* __restrict__ kl,
    const __nv_bfloat16* __restrict__ vh, const __nv_bfloat16* __restrict__ vl)
{
    extern __shared__ char smem[];
    const uint32_t sb = s2u(smem);
    const int tid = threadIdx.x, warp = tid >> 5, lane = tid & 31;
    const int bx = blockIdx.x, b = blockIdx.y, h = blockIdx.z;
    const int l0 = bx * 128;
    const int ntiles = 2 * bx + 2;

    const uint32_t sQh = sb, sQl = sb + AQ_B;
    const uint32_t sKV = sb + 2 * AQ_B;

    // load Q (hi + lo): 128 rows x 8 segs x 2 arrays
#pragma unroll
    for (int t = 0; t < 8; t++) {
        int idx = tid + t * 256;
        int row = idx >> 4;
        int sub = idx & 15;
        int seg = sub & 7;
        const __nv_bfloat16* src = (sub < 8) ? qh : ql;
        uint32_t dst = ((sub < 8) ? sQh : sQl) + row * AT_S + seg * 16;
        cpa16(dst, src + ((size_t)(l0 + row) * 4 + b) * 512 + h * 64 + seg * 8);
    }
    asm volatile("cp.async.commit_group;" ::: "memory");

    auto load_kv = [&](int s, int jt) {
        uint32_t st = sKV + s * AKV_STAGE;
#pragma unroll
        for (int t = 0; t < 8; t++) {
            int idx = tid + t * 256;
            int arr = idx >> 9;
            int row = (idx >> 3) & 63;
            int seg = idx & 7;
            const __nv_bfloat16* src = (arr == 0) ? kh : (arr == 1) ? kl : (arr == 2) ? vh : vl;
            cpa16(st + arr * AKV_TILE + row * AT_S + seg * 16,
                  src + ((size_t)(jt * 64 + row) * 4 + b) * 512 + h * 64 + seg * 8);
        }
    };
    load_kv(0, 0);
    asm volatile("cp.async.commit_group;" ::: "memory");

    const int a_row = (lane & 7) + ((lane >> 3) & 1) * 8;
    const int a_k8 = lane >> 4;
    const int b_row = (lane & 7) + (lane >> 4) * 8;
    const int b_k8 = (lane >> 3) & 1;

    uint32_t qfh[4][4], qfl[4][4];
    float ctx[8][4];
#pragma unroll
    for (int i = 0; i < 8; i++)
#pragma unroll
        for (int j = 0; j < 4; j++) ctx[i][j] = 0.f;
    float m0 = -INFINITY, m1 = -INFINITY, l0s = 0.f, l1s = 0.f;

    for (int jt = 0; jt < ntiles; jt++) {
        const uint32_t st = sKV + (jt & 1) * AKV_STAGE;
        __syncthreads();
        if (jt + 1 < ntiles) {
            load_kv((jt + 1) & 1, jt + 1);
            asm volatile("cp.async.commit_group;" ::: "memory");
            asm volatile("cp.async.wait_group 1;" ::: "memory");
        } else {
            asm volatile("cp.async.wait_group 0;" ::: "memory");
        }
        __syncthreads();

        if (jt == 0) {
#pragma unroll
            for (int kb = 0; kb < 4; kb++) {
                uint32_t qa = sQh + (warp * 16 + a_row) * AT_S + (kb * 2 + a_k8) * 16;
                LDSM4(qfh[kb], qa);
                LDSM4(qfl[kb], qa + AQ_B);
            }
        }

        // S = Q K^T (3 terms)
        float S[8][4];
#pragma unroll
        for (int i = 0; i < 8; i++)
#pragma unroll
            for (int j = 0; j < 4; j++) S[i][j] = 0.f;
#pragma unroll
        for (int kb = 0; kb < 4; kb++) {
#pragma unroll
            for (int ng = 0; ng < 4; ng++) {
                uint32_t kbh[4], kbl[4];
                uint32_t ka = st + (ng * 16 + b_row) * AT_S + (kb * 2 + b_k8) * 16;
                LDSM4(kbh, ka);
                LDSM4(kbl, ka + AKV_TILE);
                int nb = ng * 2;
                MMA16816(S[nb], qfh[kb], kbh[0], kbh[1]);
                MMA16816(S[nb + 1], qfh[kb], kbh[2], kbh[3]);
                MMA16816(S[nb], qfh[kb], kbl[0], kbl[1]);
                MMA16816(S[nb + 1], qfh[kb], kbl[2], kbl[3]);
                MMA16816(S[nb], qfl[kb], kbh[0], kbh[1]);
                MMA16816(S[nb + 1], qfl[kb], kbh[2], kbh[3]);
            }
        }

        const int qr0 = l0 + warp * 16 + (lane >> 2);
        const int qr1 = qr0 + 8;
        if (jt >= ntiles - 2) {
#pragma unroll
            for (int nb = 0; nb < 8; nb++) {
                int c = jt * 64 + nb * 8 + 2 * (lane & 3);
                if (c > qr0) S[nb][0] = -INFINITY;
                if (c + 1 > qr0) S[nb][1] = -INFINITY;
                if (c > qr1) S[nb][2] = -INFINITY;
                if (c + 1 > qr1) S[nb][3] = -INFINITY;
            }
        }

        // online softmax
        float mx0 = -INFINITY, mx1 = -INFINITY;
#pragma unroll
        for (int nb = 0; nb < 8; nb++) {
            mx0 = fmaxf(mx0, fmaxf(S[nb][0], S[nb][1]));
            mx1 = fmaxf(mx1, fmaxf(S[nb][2], S[nb][3]));
        }
        mx0 = fmaxf(mx0, __shfl_xor_sync(0xffffffffu, mx0, 1));
        mx0 = fmaxf(mx0, __shfl_xor_sync(0xffffffffu, mx0, 2));
        mx1 = fmaxf(mx1, __shfl_xor_sync(0xffffffffu, mx1, 1));
        mx1 = fmaxf(mx1, __shfl_xor_sync(0xffffffffu, mx1, 2));
        float nm0 = fmaxf(m0, mx0), nm1 = fmaxf(m1, mx1);
        float c0 = __expf(m0 - nm0), c1 = __expf(m1 - nm1);
        m0 = nm0; m1 = nm1;
        float s0 = 0.f, s1 = 0.f;
#pragma unroll
        for (int nb = 0; nb < 8; nb++) {
            S[nb][0] = __expf(S[nb][0] - nm0);
            S[nb][1] = __expf(S[nb][1] - nm0);
            S[nb][2] = __expf(S[nb][2] - nm1);
            S[nb][3] = __expf(S[nb][3] - nm1);
            s0 += S[nb][0] + S[nb][1];
            s1 += S[nb][2] + S[nb][3];
        }
        s0 += __shfl_xor_sync(0xffffffffu, s0, 1);
        s0 += __shfl_xor_sync(0xffffffffu, s0, 2);
        s1 += __shfl_xor_sync(0xffffffffu, s1, 1);
        s1 += __shfl_xor_sync(0xffffffffu, s1, 2);
        l0s = l0s * c0 + s0;
        l1s = l1s * c1 + s1;
#pragma unroll
        for (int nb = 0; nb < 8; nb++) {
            ctx[nb][0] *= c0; ctx[nb][1] *= c0;
            ctx[nb][2] *= c1; ctx[nb][3] *= c1;
        }

        // P fragments (hi/lo split)
        uint32_t ph[4][4], pl[4][4];
#pragma unroll
        for (int kb = 0; kb < 4; kb++) {
            const float* sA = S[2 * kb];
            const float* sB = S[2 * kb + 1];
            ph[kb][0] = bf2pack(sA[0], sA[1]);
            ph[kb][1] = bf2pack(sA[2], sA[3]);
            ph[kb][2] = bf2pack(sB[0], sB[1]);
            ph[kb][3] = bf2pack(sB[2], sB[3]);
            __nv_bfloat162 t0 = *(__nv_bfloat162*)&ph[kb][0];
            __nv_bfloat162 t1 = *(__nv_bfloat162*)&ph[kb][1];
            __nv_bfloat162 t2 = *(__nv_bfloat162*)&ph[kb][2];
            __nv_bfloat162 t3 = *(__nv_bfloat162*)&ph[kb][3];
            pl[kb][0] = bf2pack(sA[0] - __bfloat162float(t0.x), sA[1] - __bfloat162float(t0.y));
            pl[kb][1] = bf2pack(sA[2] - __bfloat162float(t1.x), sA[3] - __bfloat162float(t1.y));
            pl[kb][2] = bf2pack(sB[0] - __bfloat162float(t2.x), sB[1] - __bfloat162float(t2.y));
            pl[kb][3] = bf2pack(sB[2] - __bfloat162float(t3.x), sB[3] - __bfloat162float(t3.y));
        }

        // ctx += P V (3 terms); V via ldmatrix.trans
        const uint32_t vrow = (lane & 7) + ((lane >> 3) & 1) * 8;
        const uint32_t vcol16 = (lane >> 4) * 16;
#pragma unroll
        for (int kb = 0; kb < 4; kb++) {
#pragma unroll
            for (int ngd = 0; ngd < 4; ngd++) {
                uint32_t vbh[4], vbl[4];
                uint32_t va = st + 2 * AKV_TILE + (kb * 16 + vrow) * AT_S + ngd * 32 + vcol16;
                LDSM4T(vbh, va);
                LDSM4T(vbl, va + AKV_TILE);
                int nd = ngd * 2;
                MMA16816(ctx[nd], ph[kb], vbh[0], vbh[1]);
                MMA16816(ctx[nd + 1], ph[kb], vbh[2], vbh[3]);
                MMA16816(ctx[nd], ph[kb], vbl[0], vbl[1]);
                MMA16816(ctx[nd + 1], ph[kb], vbl[2], vbl[3]);
                MMA16816(ctx[nd], pl[kb], vbh[0], vbh[1]);
                MMA16816(ctx[nd + 1], pl[kb], vbh[2], vbh[3]);
            }
        }
    }

    // write split ctx
    float inv0 = 1.f / l0s, inv1 = 1.f / l1s;
    const size_t mg0 = (size_t)(l0 + warp * 16 + (lane >> 2)) * 4 + b;
    const size_t mg1 = mg0 + 32;   // q row +8 -> m +32
#pragma unroll
    for (int nd = 0; nd < 8; nd++) {
        int col = h * 64 + nd * 8 + 2 * (lane & 3);
        float v0 = ctx[nd][0] * inv0, v1 = ctx[nd][1] * inv0;
        float v2 = ctx[nd][2] * inv1, v3 = ctx[nd][3] * inv1;
        uint32_t h0 = bf2pack(v0, v1), h1 = bf2pack(v2, v3);
        __nv_bfloat162 hh0 = *(__nv_bfloat162*)&h0;
        __nv_bfloat162 hh1 = *(__nv_bfloat162*)&h1;
        uint32_t l0p = bf2pack(v0 - __bfloat162float(hh0.x), v1 - __bfloat162float(hh0.y));
        uint32_t l1p = bf2pack(v2 - __bfloat162float(hh1.x), v3 - __bfloat162float(hh1.y));
        *(uint32_t*)(ctxh + mg0 * 512 + col) = h0;
        *(uint32_t*)(ctxh + mg1 * 512 + col) = h1;
        *(uint32_t*)(ctxl + mg0 * 512 + col) = l0p;
        *(uint32_t*)(ctxl + mg1 * 512 + col) = l1p;
    }
}

// ---------------- fused residual-add + LayerNorm (+ split out) ----------------
__global__ void __launch_bounds__(128) add_ln_kernel(float* __restrict__ x,
                                                     __nv_bfloat16* __restrict__ xh,
                                                     __nv_bfloat16* __restrict__ xl,
                                                     const float* __restrict__ y,
                                                     const float* __restrict__ a,
                                                     const float* __restrict__ b)
{
    const int m = blockIdx.x;
    const int tid = threadIdx.x;
    const size_t base = (size_t)m * DMODEL;
    __shared__ float red[8];

    float v[4];
#pragma unroll
    for (int j = 0; j < 4; j++) {
        int d = tid + j * 128;
        float xv = x[base + d];
        if (y) xv += y[base + d];
        v[j] = xv;
    }
    float s = v[0] + v[1] + v[2] + v[3];
#pragma unroll
    for (int o = 16; o > 0; o >>= 1) s += __shfl_xor_sync(0xffffffffu, s, o);
    if ((tid & 31) == 0) red[tid >> 5] = s;
    __syncthreads();
    float mean = (red[0] + red[1] + red[2] + red[3]) * (1.f / 512.f);

    float ss = 0.f;
#pragma unroll
    for (int j = 0; j < 4; j++) {
        float dm = v[j] - mean;
        ss += dm * dm;
    }
#pragma unroll
    for (int o = 16; o > 0; o >>= 1) ss += __shfl_xor_sync(0xffffffffu, ss, o);
    if ((tid & 31) == 0) red[4 + (tid >> 5)] = ss;
    __syncthreads();
    float var = (red[4] + red[5] + red[6] + red[7]) * (1.f / 511.f);
    float inv = 1.f / (sqrtf(var) + 1e-6f);

#pragma unroll
    for (int j = 0; j < 4; j++) {
        int d = tid + j * 128;
        float o = a[d] * (v[j] - mean) * inv + b[d];
        x[base + d] = o;
        __nv_bfloat16 h = __float2bfloat16(o);
        xh[base + d] = h;
        xl[base + d] = __float2bfloat16(o - __bfloat162float(h));
    }
}

// ---------------- orchestration ----------------
extern "C" void kernel_launch(void* const* d_in, const int* in_sizes, int n_in,
                              void* d_out, int out_size)
{
    (void)in_sizes; (void)n_in; (void)out_size;
    const int*   input = (const int*)  d_in[0];
    const float* emb   = (const float*)d_in[1];
    const float* Wq    = (const float*)d_in[2];
    const float* Wk    = (const float*)d_in[3];
    const float* Wv    = (const float*)d_in[4];
    const float* Wo    = (const float*)d_in[5];
    const float* w1    = (const float*)d_in[6];
    const float* b1    = (const float*)d_in[7];
    const float* w2    = (const float*)d_in[8];
    const float* b2    = (const float*)d_in[9];
    const float* ln1a  = (const float*)d_in[10];
    const float* ln1b  = (const float*)d_in[11];
    const float* ln2a  = (const float*)d_in[12];
    const float* ln2b  = (const float*)d_in[13];
    const float* fna   = (const float*)d_in[14];
    const float* fnb   = (const float*)d_in[15];
    const float* decW  = (const float*)d_in[16];
    const float* decb  = (const float*)d_in[17];
    float* out = (float*)d_out;

    float *x, *t;
    __nv_bfloat16 *xs, *qs, *ks, *vs, *cs, *ahi, *alo, *whi, *wlo;
    cudaGetSymbolAddress((void**)&x,   g_x);
    cudaGetSymbolAddress((void**)&t,   g_t);
    cudaGetSymbolAddress((void**)&xs,  g_xs);
    cudaGetSymbolAddress((void**)&qs,  g_qs);
    cudaGetSymbolAddress((void**)&ks,  g_ks);
    cudaGetSymbolAddress((void**)&vs,  g_vs);
    cudaGetSymbolAddress((void**)&cs,  g_cs);
    cudaGetSymbolAddress((void**)&ahi, g_ahi);
    cudaGetSymbolAddress((void**)&alo, g_alo);
    cudaGetSymbolAddress((void**)&whi, g_whi);
    cudaGetSymbolAddress((void**)&wlo, g_wlo);

    const int AS = MROWS * DMODEL;   // 4194304
    __nv_bfloat16 *xh = xs, *xl = xs + AS;
    __nv_bfloat16 *qh = qs, *ql = qs + AS;
    __nv_bfloat16 *kh = ks, *kl = ks + AS;
    __nv_bfloat16 *vh = vs, *vl = vs + AS;
    __nv_bfloat16 *ch = cs, *cl = cs + AS;

    cudaFuncSetAttribute(attn_mma, cudaFuncAttributeMaxDynamicSharedMemorySize, ATTN_SMEM);
    cudaFuncSetAttribute(gemm_mma<false, false, true>,  cudaFuncAttributeMaxDynamicSharedMemorySize, GEMM_SMEM);
    cudaFuncSetAttribute(gemm_mma<false, false, false>, cudaFuncAttributeMaxDynamicSharedMemorySize, GEMM_SMEM);
    cudaFuncSetAttribute(gemm_mma<true, true, true>,    cudaFuncAttributeMaxDynamicSharedMemorySize, GEMM_SMEM);
    cudaFuncSetAttribute(gemm_mma<true, false, false>,  cudaFuncAttributeMaxDynamicSharedMemorySize, GEMM_SMEM);

    // weight splits
    split_kernel<<<(4 * 262144) / 1024, 256>>>(whi + WQ0, wlo + WQ0, Wq, (4 * 262144) / 4);
    split_kernel<<<(4 * 262144) / 1024, 256>>>(whi + WK0, wlo + WK0, Wk, (4 * 262144) / 4);
    split_kernel<<<(4 * 262144) / 1024, 256>>>(whi + WV0, wlo + WV0, Wv, (4 * 262144) / 4);
    split_kernel<<<(4 * 262144) / 1024, 256>>>(whi + WO0, wlo + WO0, Wo, (4 * 262144) / 4);
    split_kernel<<<4194304 / 1024, 256>>>(whi + W10, wlo + W10, w1, 4194304 / 4);
    split_kernel<<<4194304 / 1024, 256>>>(whi + W20, wlo + W20, w2, 4194304 / 4);
    split_kernel<<<16384000 / 1024, 256>>>(whi + WD0, wlo + WD0, decW, 16384000 / 4);

    embed_kernel<<<MROWS, 128>>>(x, xh, xl, input, emb);

    const dim3 gD(DMODEL / 128, MROWS / 128);
    const dim3 gF(DFFN / 128, MROWS / 128);
    const dim3 gV(NVOCAB / 128, MROWS / 128);
    const dim3 gAttn(LSEQ / 128, BATCH, NHEAD);

    for (int l = 0; l < NLAYER; l++) {
        const size_t wofs = (size_t)l * DMODEL * DMODEL;
        const size_t f1 = (size_t)l * DFFN * DMODEL;

        gemm_mma<false, false, true><<<gD, 256, GEMM_SMEM>>>(
            nullptr, qh, ql, 0.125f, xh, xl, whi + WQ0 + wofs, wlo + WQ0 + wofs,
            nullptr, MROWS, DMODEL, DMODEL);
        gemm_mma<false, false, true><<<gD, 256, GEMM_SMEM>>>(
            nullptr, kh, kl, 1.0f, xh, xl, whi + WK0 + wofs, wlo + WK0 + wofs,
            nullptr, MROWS, DMODEL, DMODEL);
        gemm_mma<false, false, true><<<gD, 256, GEMM_SMEM>>>(
            nullptr, vh, vl, 1.0f, xh, xl, whi + WV0 + wofs, wlo + WV0 + wofs,
            nullptr, MROWS, DMODEL, DMODEL);

        attn_mma<<<gAttn, 256, ATTN_SMEM>>>(ch, cl, qh, ql, kh, kl, vh, vl);

        gemm_mma<false, false, false><<<gD, 256, GEMM_SMEM>>>(
            t, nullptr, nullptr, 1.0f, ch, cl, whi + WO0 + wofs, wlo + WO0 + wofs,
            nullptr, MROWS, DMODEL, DMODEL);
        add_ln_kernel<<<MROWS, 128>>>(x, xh, xl, t, ln1a + l * DMODEL, ln1b + l * DMODEL);

        gemm_mma<true, true, true><<<gF, 256, GEMM_SMEM>>>(
            nullptr, ahi, alo, 1.0f, xh, xl, whi + W10 + f1, wlo + W10 + f1,
            b1 + l * DFFN, MROWS, DFFN, DMODEL);
        gemm_mma<true, false, false><<<gD, 256, GEMM_SMEM>>>(
            t, nullptr, nullptr, 1.0f, ahi, alo, whi + W20 + f1, wlo + W20 + f1,
            b2 + l * DMODEL, MROWS, DMODEL, DFFN);
        add_ln_kernel<<<MROWS, 128>>>(x, xh, xl, t, ln2a + l * DMODEL, ln2b + l * DMODEL);
    }

    add_ln_kernel<<<MROWS, 128>>>(x, xh, xl, nullptr, fna, fnb);
    gemm_mma<true, false, false><<<gV, 256, GEMM_SMEM>>>(
        out, nullptr, nullptr, 1.0f, xh, xl, whi + WD0, wlo + WD0,
        decb, MROWS, NVOCAB, DMODEL);
}

// round 5
// speedup vs baseline: 2.9977x; 1.0366x over previous
#include <cuda_runtime.h>
#include <cuda_bf16.h>
#include <math.h>
#include <stdint.h>

#define LSEQ 2048
#define BATCH 4
#define DMODEL 512
#define NHEAD 8
#define DKH 64
#define NLAYER 4
#define DFFN 2048
#define MROWS (LSEQ * BATCH)   // 8192
#define NVOCAB 32000

// ---------------- scratch (device globals; no allocation allowed) ----------------
__device__ float g_x[MROWS * DMODEL];
__device__ float g_t[MROWS * DMODEL];
__device__ __nv_bfloat16 g_xs[2 * MROWS * DMODEL];
__device__ __nv_bfloat16 g_qkvs[2 * MROWS * 3 * DMODEL];   // fused qkv, stride 1536
__device__ __nv_bfloat16 g_cs[2 * MROWS * DMODEL];
__device__ __nv_bfloat16 g_ahi[MROWS * DFFN];
__device__ __nv_bfloat16 g_alo[MROWS * DFFN];

// weight split storage (bf16 hi/lo), element offsets:
#define WQKV0 0                 // fused [NLAYER][1536][512]
#define WO0 3145728
#define W10 4194304
#define W20 8388608
#define WD0 12582912
#define WTOT 28966912
__device__ __nv_bfloat16 g_whi[WTOT];
__device__ __nv_bfloat16 g_wlo[WTOT];

// ---------------- helpers ----------------
__device__ __forceinline__ uint32_t s2u(const void* p) {
    uint32_t a;
    asm("{ .reg .u64 t; cvta.to.shared.u64 t, %1; cvt.u32.u64 %0, t; }" : "=r"(a) : "l"(p));
    return a;
}
__device__ __forceinline__ void cpa16(uint32_t d, const void* s) {
    asm volatile("cp.async.cg.shared.global [%0], [%1], 16;" :: "r"(d), "l"(s));
}
__device__ __forceinline__ uint32_t bf2pack(float x, float y) {
    __nv_bfloat162 t; t.x = __float2bfloat16(x); t.y = __float2bfloat16(y);
    return *(uint32_t*)&t;
}

#define LDSM4(r, a) \
    asm volatile("ldmatrix.sync.aligned.m8n8.x4.shared.b16 {%0,%1,%2,%3}, [%4];" \
        : "=r"((r)[0]), "=r"((r)[1]), "=r"((r)[2]), "=r"((r)[3]) : "r"(a))
#define LDSM4T(r, a) \
    asm volatile("ldmatrix.sync.aligned.m8n8.x4.trans.shared.b16 {%0,%1,%2,%3}, [%4];" \
        : "=r"((r)[0]), "=r"((r)[1]), "=r"((r)[2]), "=r"((r)[3]) : "r"(a))

#define MMA16816(c, a, b0, b1) \
    asm volatile("mma.sync.aligned.m16n8k16.row.col.f32.bf16.bf16.f32 " \
        "{%0,%1,%2,%3}, {%4,%5,%6,%7}, {%8,%9}, {%0,%1,%2,%3};" \
        : "+f"((c)[0]), "+f"((c)[1]), "+f"((c)[2]), "+f"((c)[3]) \
        : "r"((a)[0]), "r"((a)[1]), "r"((a)[2]), "r"((a)[3]), "r"(b0), "r"(b1))

// ---------------- fp32 -> bf16 hi/lo split (weights; optional scale) ----------------
__global__ void __launch_bounds__(256) split_kernel(__nv_bfloat16* __restrict__ hi,
                                                    __nv_bfloat16* __restrict__ lo,
                                                    const float* __restrict__ src,
                                                    float scale, int n4)
{
    int i = blockIdx.x * 256 + threadIdx.x;
    if (i >= n4) return;
    float4 v = ((const float4*)src)[i];
    v.x *= scale; v.y *= scale; v.z *= scale; v.w *= scale;
    float h0f, h1f, h2f, h3f;
    __nv_bfloat16 h0 = __float2bfloat16(v.x); h0f = __bfloat162float(h0);
    __nv_bfloat16 h1 = __float2bfloat16(v.y); h1f = __bfloat162float(h1);
    __nv_bfloat16 h2 = __float2bfloat16(v.z); h2f = __bfloat162float(h2);
    __nv_bfloat16 h3 = __float2bfloat16(v.w); h3f = __bfloat162float(h3);
    ((uint32_t*)hi)[2 * i + 0] = bf2pack(v.x, v.y);
    ((uint32_t*)hi)[2 * i + 1] = bf2pack(v.z, v.w);
    ((uint32_t*)lo)[2 * i + 0] = bf2pack(v.x - h0f, v.y - h1f);
    ((uint32_t*)lo)[2 * i + 1] = bf2pack(v.z - h2f, v.w - h3f);
}

// ---------------- bf16 mma.sync GEMM: C[M,N] = A[M,K]*W[N,K]^T, 3x split ----------------
// BM=128, BN=256, BK=32; 256 threads; warp grid 2(m)x4(n); warp tile 64x64; 3 stages.
#define TSTRIDE 80
#define A_TILE_B (128 * TSTRIDE)            // 10240
#define B_TILE_B (256 * TSTRIDE)            // 20480
#define STAGE_B (2 * A_TILE_B + 2 * B_TILE_B)  // 61440
#define GEMM_SMEM (3 * STAGE_B)             // 184320
#define OFF_AH 0
#define OFF_AL A_TILE_B
#define OFF_BH (2 * A_TILE_B)
#define OFF_BL (2 * A_TILE_B + B_TILE_B)

template <bool BIAS, bool RELU, bool SPLIT>
__global__ void __launch_bounds__(256) gemm_mma(float* __restrict__ C,
                                                __nv_bfloat16* __restrict__ Oh,
                                                __nv_bfloat16* __restrict__ Ol,
                                                const __nv_bfloat16* __restrict__ Ahi,
                                                const __nv_bfloat16* __restrict__ Alo,
                                                const __nv_bfloat16* __restrict__ Bhi,
                                                const __nv_bfloat16* __restrict__ Blo,
                                                const float* __restrict__ bias,
                                                int M, int N, int K)
{
    extern __shared__ char smem[];
    const uint32_t sb = s2u(smem);
    const int tid = threadIdx.x;
    const int warp = tid >> 5, lane = tid & 31;
    const int bm = blockIdx.y * 128;
    const int bn = blockIdx.x * 256;
    const int warp_m = warp >> 2;          // 0..1
    const int warp_n = warp & 3;           // 0..3
    const int nch = K >> 5;

    const __nv_bfloat16* pAh = Ahi + (size_t)bm * K;
    const __nv_bfloat16* pAl = Alo + (size_t)bm * K;
    const __nv_bfloat16* pBh = Bhi + (size_t)bn * K;
    const __nv_bfloat16* pBl = Blo + (size_t)bn * K;

    auto load_stage = [&](uint32_t st, int k0) {
        // A: 2 arrays x 128 rows x 4 segs = 1024 chunks of 16B
#pragma unroll
        for (int j = 0; j < 4; j++) {
            int idx = tid + j * 256;
            int arr = idx >> 9;
            int r = (idx >> 2) & 127;
            int seg = idx & 3;
            const __nv_bfloat16* src = arr ? pAl : pAh;
            cpa16(st + arr * A_TILE_B + r * TSTRIDE + seg * 16,
                  src + (size_t)r * K + k0 + seg * 8);
        }
        // B: 2 arrays x 256 rows x 4 segs = 2048 chunks
#pragma unroll
        for (int j = 0; j < 8; j++) {
            int idx = tid + j * 256;
            int arr = idx >> 10;
            int r = (idx >> 2) & 255;
            int seg = idx & 3;
            const __nv_bfloat16* src = arr ? pBl : pBh;
            cpa16(st + OFF_BH + arr * B_TILE_B + r * TSTRIDE + seg * 16,
                  src + (size_t)r * K + k0 + seg * 8);
        }
    };

    float acc[4][8][4];
#pragma unroll
    for (int i = 0; i < 4; i++)
#pragma unroll
        for (int j = 0; j < 8; j++)
#pragma unroll
            for (int q = 0; q < 4; q++) acc[i][j][q] = 0.f;

    const int g = lane >> 3, lr = lane & 7;
    const int a_row = lr + (g & 1) * 8;
    const int a_k8 = g >> 1;
    const int b_row = lr + (g >> 1) * 8;
    const int b_k8 = g & 1;

    load_stage(sb, 0);
    asm volatile("cp.async.commit_group;" ::: "memory");
    if (nch > 1) load_stage(sb + STAGE_B, 32);
    asm volatile("cp.async.commit_group;" ::: "memory");

    for (int i = 0; i < nch; i++) {
        const uint32_t st = sb + (i % 3) * STAGE_B;
        asm volatile("cp.async.wait_group 1;" ::: "memory");
        __syncthreads();   // publishes stage i; also: all warps done with stage i-1
        if (i + 2 < nch) load_stage(sb + ((i + 2) % 3) * STAGE_B, (i + 2) * 32);
        asm volatile("cp.async.commit_group;" ::: "memory");

#pragma unroll
        for (int ks = 0; ks < 2; ks++) {
            uint32_t ah[4][4], al[4][4];
#pragma unroll
            for (int mi = 0; mi < 4; mi++) {
                uint32_t aaddr = st + (warp_m * 64 + mi * 16 + a_row) * TSTRIDE +
                                 (ks * 2 + a_k8) * 16;
                LDSM4(ah[mi], aaddr + OFF_AH);
                LDSM4(al[mi], aaddr + OFF_AL);
            }
#pragma unroll
            for (int ng = 0; ng < 4; ng++) {
                uint32_t bh[4], bl[4];
                uint32_t baddr = st + (warp_n * 64 + ng * 16 + b_row) * TSTRIDE +
                                 (ks * 2 + b_k8) * 16;
                LDSM4(bh, baddr + OFF_BH);
                LDSM4(bl, baddr + OFF_BL);
#pragma unroll
                for (int mi = 0; mi < 4; mi++) {
                    MMA16816(acc[mi][2 * ng], ah[mi], bh[0], bh[1]);
                    MMA16816(acc[mi][2 * ng + 1], ah[mi], bh[2], bh[3]);
                    MMA16816(acc[mi][2 * ng], ah[mi], bl[0], bl[1]);
                    MMA16816(acc[mi][2 * ng + 1], ah[mi], bl[2], bl[3]);
                    MMA16816(acc[mi][2 * ng], al[mi], bh[0], bh[1]);
                    MMA16816(acc[mi][2 * ng + 1], al[mi], bh[2], bh[3]);
                }
            }
        }
    }

    const int tm = lane >> 2, tn = (lane & 3) * 2;
#pragma unroll
    for (int mi = 0; mi < 4; mi++) {
#pragma unroll
        for (int nj = 0; nj < 8; nj++) {
            const float* a4 = acc[mi][nj];
            int row0 = bm + warp_m * 64 + mi * 16 + tm;
            int col = bn + warp_n * 64 + nj * 8 + tn;
            float b0 = 0.f, b1 = 0.f;
            if (BIAS) { b0 = bias[col]; b1 = bias[col + 1]; }
            float v0 = a4[0] + b0, v1 = a4[1] + b1;
            float v2 = a4[2] + b0, v3 = a4[3] + b1;
            if (RELU) {
                v0 = fmaxf(v0, 0.f); v1 = fmaxf(v1, 0.f);
                v2 = fmaxf(v2, 0.f); v3 = fmaxf(v3, 0.f);
            }
            if (SPLIT) {
                uint32_t h0 = bf2pack(v0, v1), h1 = bf2pack(v2, v3);
                __nv_bfloat162 hh0 = *(__nv_bfloat162*)&h0;
                __nv_bfloat162 hh1 = *(__nv_bfloat162*)&h1;
                uint32_t l0p = bf2pack(v0 - __bfloat162float(hh0.x),
                                       v1 - __bfloat162float(hh0.y));
                uint32_t l1p = bf2pack(v2 - __bfloat162float(hh1.x),
                                       v3 - __bfloat162float(hh1.y));
                *(uint32_t*)(Oh + (size_t)row0 * N + col) = h0;
                *(uint32_t*)(Oh + (size_t)(row0 + 8) * N + col) = h1;
                *(uint32_t*)(Ol + (size_t)row0 * N + col) = l0p;
                *(uint32_t*)(Ol + (size_t)(row0 + 8) * N + col) = l1p;
            } else {
                *(float2*)(C + (size_t)row0 * N + col) = make_float2(v0, v1);
                *(float2*)(C + (size_t)(row0 + 8) * N + col) = make_float2(v2, v3);
            }
        }
    }
}

// ---------------- embedding + positional encoding (fp32 + split out) ----------------
__global__ void __launch_bounds__(128) embed_kernel(float* __restrict__ x,
                                                    __nv_bfloat16* __restrict__ xh,
                                                    __nv_bfloat16* __restrict__ xl,
                                                    const int* __restrict__ tok,
                                                    const float* __restrict__ emb)
{
    int m = blockIdx.x;
    int l = m >> 2;
    int t = tok[m];
    const float sq = 22.627416997969522f;
    const double nlog = 9.210340371976184;
#pragma unroll
    for (int j = 0; j < 4; j++) {
        int d = threadIdx.x + j * 128;
        int i = d >> 1;
        float freqf = (float)exp(-(double)(2 * i) * (nlog / 512.0));
        float angf = (float)l * freqf;
        double ang = (double)angf;
        float pe = (d & 1) ? (float)cos(ang) : (float)sin(ang);
        float v = emb[(size_t)t * DMODEL + d] * sq + pe;
        x[(size_t)m * DMODEL + d] = v;
        __nv_bfloat16 h = __float2bfloat16(v);
        xh[(size_t)m * DMODEL + d] = h;
        xl[(size_t)m * DMODEL + d] = __float2bfloat16(v - __bfloat162float(h));
    }
}

// ---------------- mma flash attention (causal, 3x bf16 split), fused-QKV input --------
#define QKVSTR 1536
#define AT_S 144
#define AQ_B (128 * AT_S)
#define AKV_TILE (64 * AT_S)
#define AKV_STAGE (4 * AKV_TILE)
#define ATTN_SMEM (2 * AQ_B + 2 * AKV_STAGE)  // 110592

__global__ void __launch_bounds__(256) attn_mma(
    __nv_bfloat16* __restrict__ ctxh, __nv_bfloat16* __restrict__ ctxl,
    const __nv_bfloat16* __restrict__ qkvh, const __nv_bfloat16* __restrict__ qkvl)
{
    extern __shared__ char smem[];
    const uint32_t sb = s2u(smem);
    const int tid = threadIdx.x, warp = tid >> 5, lane = tid & 31;
    const int bx = blockIdx.x, b = blockIdx.y, h = blockIdx.z;
    const int l0 = bx * 128;
    const int ntiles = 2 * bx + 2;

    const uint32_t sQh = sb, sQl = sb + AQ_B;
    const uint32_t sKV = sb + 2 * AQ_B;

#pragma unroll
    for (int t = 0; t < 8; t++) {
        int idx = tid + t * 256;
        int row = idx >> 4;
        int sub = idx & 15;
        int seg = sub & 7;
        const __nv_bfloat16* src = (sub < 8) ? qkvh : qkvl;
        uint32_t dst = ((sub < 8) ? sQh : sQl) + row * AT_S + seg * 16;
        cpa16(dst, src + ((size_t)(l0 + row) * 4 + b) * QKVSTR + h * 64 + seg * 8);
    }
    asm volatile("cp.async.commit_group;" ::: "memory");

    auto load_kv = [&](int s, int jt) {
        uint32_t st = sKV + s * AKV_STAGE;
#pragma unroll
        for (int t = 0; t < 8; t++) {
            int idx = tid + t * 256;
            int arr = idx >> 9;
            int row = (idx >> 3) & 63;
            int seg = idx & 7;
            const __nv_bfloat16* src = (arr & 1) ? qkvl : qkvh;
            int coff = (arr < 2) ? 512 : 1024;
            cpa16(st + arr * AKV_TILE + row * AT_S + seg * 16,
                  src + ((size_t)(jt * 64 + row) * 4 + b) * QKVSTR + coff + h * 64 + seg * 8);
        }
    };
    load_kv(0, 0);
    asm volatile("cp.async.commit_group;" ::: "memory");

    const int a_row = (lane & 7) + ((lane >> 3) & 1) * 8;
    const int a_k8 = lane >> 4;
    const int b_row = (lane & 7) + (lane >> 4) * 8;
    const int b_k8 = (lane >> 3) & 1;

    uint32_t qfh[4][4], qfl[4][4];
    float ctx[8][4];
#pragma unroll
    for (int i = 0; i < 8; i++)
#pragma unroll
        for (int j = 0; j < 4; j++) ctx[i][j] = 0.f;
    float m0 = -INFINITY, m1 = -INFINITY, l0s = 0.f, l1s = 0.f;

    for (int jt = 0; jt < ntiles; jt++) {
        const uint32_t st = sKV + (jt & 1) * AKV_STAGE;
        __syncthreads();
        if (jt + 1 < ntiles) {
            load_kv((jt + 1) & 1, jt + 1);
            asm volatile("cp.async.commit_group;" ::: "memory");
            asm volatile("cp.async.wait_group 1;" ::: "memory");
        } else {
            asm volatile("cp.async.wait_group 0;" ::: "memory");
        }
        __syncthreads();

        if (jt == 0) {
#pragma unroll
            for (int kb = 0; kb < 4; kb++) {
                uint32_t qa = sQh + (warp * 16 + a_row) * AT_S + (kb * 2 + a_k8) * 16;
                LDSM4(qfh[kb], qa);
                LDSM4(qfl[kb], qa + AQ_B);
            }
        }

        float S[8][4];
#pragma unroll
        for (int i = 0; i < 8; i++)
#pragma unroll
            for (int j = 0; j < 4; j++) S[i][j] = 0.f;
#pragma unroll
        for (int kb = 0; kb < 4; kb++) {
#pragma unroll
            for (int ng = 0; ng < 4; ng++) {
                uint32_t kbh[4], kbl[4];
                uint32_t ka = st + (ng * 16 + b_row) * AT_S + (kb * 2 + b_k8) * 16;
                LDSM4(kbh, ka);
                LDSM4(kbl, ka + AKV_TILE);
                int nb = ng * 2;
                MMA16816(S[nb], qfh[kb], kbh[0], kbh[1]);
                MMA16816(S[nb + 1], qfh[kb], kbh[2], kbh[3]);
                MMA16816(S[nb], qfh[kb], kbl[0], kbl[1]);
                MMA16816(S[nb + 1], qfh[kb], kbl[2], kbl[3]);
                MMA16816(S[nb], qfl[kb], kbh[0], kbh[1]);
                MMA16816(S[nb + 1], qfl[kb], kbh[2], kbh[3]);
            }
        }

        const int qr0 = l0 + warp * 16 + (lane >> 2);
        const int qr1 = qr0 + 8;
        if (jt >= ntiles - 2) {
#pragma unroll
            for (int nb = 0; nb < 8; nb++) {
                int c = jt * 64 + nb * 8 + 2 * (lane & 3);
                if (c > qr0) S[nb][0] = -INFINITY;
                if (c + 1 > qr0) S[nb][1] = -INFINITY;
                if (c > qr1) S[nb][2] = -INFINITY;
                if (c + 1 > qr1) S[nb][3] = -INFINITY;
            }
        }

        float mx0 = -INFINITY, mx1 = -INFINITY;
#pragma unroll
        for (int nb = 0; nb < 8; nb++) {
            mx0 = fmaxf(mx0, fmaxf(S[nb][0], S[nb][1]));
            mx1 = fmaxf(mx1, fmaxf(S[nb][2], S[nb][3]));
        }
        mx0 = fmaxf(mx0, __shfl_xor_sync(0xffffffffu, mx0, 1));
        mx0 = fmaxf(mx0, __shfl_xor_sync(0xffffffffu, mx0, 2));
        mx1 = fmaxf(mx1, __shfl_xor_sync(0xffffffffu, mx1, 1));
        mx1 = fmaxf(mx1, __shfl_xor_sync(0xffffffffu, mx1, 2));
        float nm0 = fmaxf(m0, mx0), nm1 = fmaxf(m1, mx1);
        float c0 = __expf(m0 - nm0), c1 = __expf(m1 - nm1);
        m0 = nm0; m1 = nm1;
        float s0 = 0.f, s1 = 0.f;
#pragma unroll
        for (int nb = 0; nb < 8; nb++) {
            S[nb][0] = __expf(S[nb][0] - nm0);
            S[nb][1] = __expf(S[nb][1] - nm0);
            S[nb][2] = __expf(S[nb][2] - nm1);
            S[nb][3] = __expf(S[nb][3] - nm1);
            s0 += S[nb][0] + S[nb][1];
            s1 += S[nb][2] + S[nb][3];
        }
        s0 += __shfl_xor_sync(0xffffffffu, s0, 1);
        s0 += __shfl_xor_sync(0xffffffffu, s0, 2);
        s1 += __shfl_xor_sync(0xffffffffu, s1, 1);
        s1 += __shfl_xor_sync(0xffffffffu, s1, 2);
        l0s = l0s * c0 + s0;
        l1s = l1s * c1 + s1;
#pragma unroll
        for (int nb = 0; nb < 8; nb++) {
            ctx[nb][0] *= c0; ctx[nb][1] *= c0;
            ctx[nb][2] *= c1; ctx[nb][3] *= c1;
        }

        uint32_t ph[4][4], pl[4][4];
#pragma unroll
        for (int kb = 0; kb < 4; kb++) {
            const float* sA = S[2 * kb];
            const float* sB = S[2 * kb + 1];
            ph[kb][0] = bf2pack(sA[0], sA[1]);
            ph[kb][1] = bf2pack(sA[2], sA[3]);
            ph[kb][2] = bf2pack(sB[0], sB[1]);
            ph[kb][3] = bf2pack(sB[2], sB[3]);
            __nv_bfloat162 t0 = *(__nv_bfloat162*)&ph[kb][0];
            __nv_bfloat162 t1 = *(__nv_bfloat162*)&ph[kb][1];
            __nv_bfloat162 t2 = *(__nv_bfloat162*)&ph[kb][2];
            __nv_bfloat162 t3 = *(__nv_bfloat162*)&ph[kb][3];
            pl[kb][0] = bf2pack(sA[0] - __bfloat162float(t0.x), sA[1] - __bfloat162float(t0.y));
            pl[kb][1] = bf2pack(sA[2] - __bfloat162float(t1.x), sA[3] - __bfloat162float(t1.y));
            pl[kb][2] = bf2pack(sB[0] - __bfloat162float(t2.x), sB[1] - __bfloat162float(t2.y));
            pl[kb][3] = bf2pack(sB[2] - __bfloat162float(t3.x), sB[3] - __bfloat162float(t3.y));
        }

        const uint32_t vrow = (lane & 7) + ((lane >> 3) & 1) * 8;
        const uint32_t vcol16 = (lane >> 4) * 16;
#pragma unroll
        for (int kb = 0; kb < 4; kb++) {
#pragma unroll
            for (int ngd = 0; ngd < 4; ngd++) {
                uint32_t vbh[4], vbl[4];
                uint32_t va = st + 2 * AKV_TILE + (kb * 16 + vrow) * AT_S + ngd * 32 + vcol16;
                LDSM4T(vbh, va);
                LDSM4T(vbl, va + AKV_TILE);
                int nd = ngd * 2;
                MMA16816(ctx[nd], ph[kb], vbh[0], vbh[1]);
                MMA16816(ctx[nd + 1], ph[kb], vbh[2], vbh[3]);
                MMA16816(ctx[nd], ph[kb], vbl[0], vbl[1]);
                MMA16816(ctx[nd + 1], ph[kb], vbl[2], vbl[3]);
                MMA16816(ctx[nd], pl[kb], vbh[0], vbh[1]);
                MMA16816(ctx[nd + 1], pl[kb], vbh[2], vbh[3]);
            }
        }
    }

    float inv0 = 1.f / l0s, inv1 = 1.f / l1s;
    const size_t mg0 = (size_t)(l0 + warp * 16 + (lane >> 2)) * 4 + b;
    const size_t mg1 = mg0 + 32;
#pragma unroll
    for (int nd = 0; nd < 8; nd++) {
        int col = h * 64 + nd * 8 + 2 * (lane & 3);
        float v0 = ctx[nd][0] * inv0, v1 = ctx[nd][1] * inv0;
        float v2 = ctx[nd][2] * inv1, v3 = ctx[nd][3] * inv1;
        uint32_t h0 = bf2pack(v0, v1), h1 = bf2pack(v2, v3);
        __nv_bfloat162 hh0 = *(__nv_bfloat162*)&h0;
        __nv_bfloat162 hh1 = *(__nv_bfloat162*)&h1;
        uint32_t l0p = bf2pack(v0 - __bfloat162float(hh0.x), v1 - __bfloat162float(hh0.y));
        uint32_t l1p = bf2pack(v2 - __bfloat162float(hh1.x), v3 - __bfloat162float(hh1.y));
        *(uint32_t*)(ctxh + mg0 * 512 + col) = h0;
        *(uint32_t*)(ctxh + mg1 * 512 + col) = h1;
        *(uint32_t*)(ctxl + mg0 * 512 + col) = l0p;
        *(uint32_t*)(ctxl + mg1 * 512 + col) = l1p;
    }
}

// ---------------- fused residual-add + LayerNorm (+ split out) ----------------
__global__ void __launch_bounds__(128) add_ln_kernel(float* __restrict__ x,
                                                     __nv_bfloat16* __restrict__ xh,
                                                     __nv_bfloat16* __restrict__ xl,
                                                     const float* __restrict__ y,
                                                     const float* __restrict__ a,
                                                     const float* __restrict__ b)
{
    const int m = blockIdx.x;
    const int tid = threadIdx.x;
    const size_t base = (size_t)m * DMODEL;
    __shared__ float red[8];

    float v[4];
#pragma unroll
    for (int j = 0; j < 4; j++) {
        int d = tid + j * 128;
        float xv = x[base + d];
        if (y) xv += y[base + d];
        v[j] = xv;
    }
    float s = v[0] + v[1] + v[2] + v[3];
#pragma unroll
    for (int o = 16; o > 0; o >>= 1) s += __shfl_xor_sync(0xffffffffu, s, o);
    if ((tid & 31) == 0) red[tid >> 5] = s;
    __syncthreads();
    float mean = (red[0] + red[1] + red[2] + red[3]) * (1.f / 512.f);

    float ss = 0.f;
#pragma unroll
    for (int j = 0; j < 4; j++) {
        float dm = v[j] - mean;
        ss += dm * dm;
    }
#pragma unroll
    for (int o = 16; o > 0; o >>= 1) ss += __shfl_xor_sync(0xffffffffu, ss, o);
    if ((tid & 31) == 0) red[4 + (tid >> 5)] = ss;
    __syncthreads();
    float var = (red[4] + red[5] + red[6] + red[7]) * (1.f / 511.f);
    float inv = 1.f / (sqrtf(var) + 1e-6f);

#pragma unroll
    for (int j = 0; j < 4; j++) {
        int d = tid + j * 128;
        float o = a[d] * (v[j] - mean) * inv + b[d];
        x[base + d] = o;
        __nv_bfloat16 h = __float2bfloat16(o);
        xh[base + d] = h;
        xl[base + d] = __float2bfloat16(o - __bfloat162float(h));
    }
}

// ---------------- orchestration ----------------
extern "C" void kernel_launch(void* const* d_in, const int* in_sizes, int n_in,
                              void* d_out, int out_size)
{
    (void)in_sizes; (void)n_in; (void)out_size;
    const int*   input = (const int*)  d_in[0];
    const float* emb   = (const float*)d_in[1];
    const float* Wq    = (const float*)d_in[2];
    const float* Wk    = (const float*)d_in[3];
    const float* Wv    = (const float*)d_in[4];
    const float* Wo    = (const float*)d_in[5];
    const float* w1    = (const float*)d_in[6];
    const float* b1    = (const float*)d_in[7];
    const float* w2    = (const float*)d_in[8];
    const float* b2    = (const float*)d_in[9];
    const float* ln1a  = (const float*)d_in[10];
    const float* ln1b  = (const float*)d_in[11];
    const float* ln2a  = (const float*)d_in[12];
    const float* ln2b  = (const float*)d_in[13];
    const float* fna   = (const float*)d_in[14];
    const float* fnb   = (const float*)d_in[15];
    const float* decW  = (const float*)d_in[16];
    const float* decb  = (const float*)d_in[17];
    float* out = (float*)d_out;

    float *x, *t;
    __nv_bfloat16 *xs, *qkvs, *cs, *ahi, *alo, *whi, *wlo;
    cudaGetSymbolAddress((void**)&x,    g_x);
    cudaGetSymbolAddress((void**)&t,    g_t);
    cudaGetSymbolAddress((void**)&xs,   g_xs);
    cudaGetSymbolAddress((void**)&qkvs, g_qkvs);
    cudaGetSymbolAddress((void**)&cs,   g_cs);
    cudaGetSymbolAddress((void**)&ahi,  g_ahi);
    cudaGetSymbolAddress((void**)&alo,  g_alo);
    cudaGetSymbolAddress((void**)&whi,  g_whi);
    cudaGetSymbolAddress((void**)&wlo,  g_wlo);

    const int AS = MROWS * DMODEL;
    const int QAS = MROWS * 3 * DMODEL;
    __nv_bfloat16 *xh = xs, *xl = xs + AS;
    __nv_bfloat16 *qkvh = qkvs, *qkvl = qkvs + QAS;
    __nv_bfloat16 *ch = cs, *cl = cs + AS;

    cudaFuncSetAttribute(attn_mma, cudaFuncAttributeMaxDynamicSharedMemorySize, ATTN_SMEM);
    cudaFuncSetAttribute(gemm_mma<false, false, true>,  cudaFuncAttributeMaxDynamicSharedMemorySize, GEMM_SMEM);
    cudaFuncSetAttribute(gemm_mma<false, false, false>, cudaFuncAttributeMaxDynamicSharedMemorySize, GEMM_SMEM);
    cudaFuncSetAttribute(gemm_mma<true, true, true>,    cudaFuncAttributeMaxDynamicSharedMemorySize, GEMM_SMEM);
    cudaFuncSetAttribute(gemm_mma<true, false, false>,  cudaFuncAttributeMaxDynamicSharedMemorySize, GEMM_SMEM);

    // weight splits: fused QKV per layer [1536][512] (q scaled by 1/8), then Wo/w1/w2/decW
    for (int l = 0; l < NLAYER; l++) {
        size_t so = (size_t)l * 262144;
        size_t dq = (size_t)l * 1536 * 512;
        split_kernel<<<256, 256>>>(whi + WQKV0 + dq,              wlo + WQKV0 + dq,              Wq + so, 0.125f, 65536);
        split_kernel<<<256, 256>>>(whi + WQKV0 + dq + 512 * 512,  wlo + WQKV0 + dq + 512 * 512,  Wk + so, 1.0f,   65536);
        split_kernel<<<256, 256>>>(whi + WQKV0 + dq + 1024 * 512, wlo + WQKV0 + dq + 1024 * 512, Wv + so, 1.0f,   65536);
    }
    split_kernel<<<1024, 256>>>(whi + WO0, wlo + WO0, Wo, 1.0f, 1048576 / 4);
    split_kernel<<<4096, 256>>>(whi + W10, wlo + W10, w1, 1.0f, 4194304 / 4);
    split_kernel<<<4096, 256>>>(whi + W20, wlo + W20, w2, 1.0f, 4194304 / 4);
    split_kernel<<<16000, 256>>>(whi + WD0, wlo + WD0, decW, 1.0f, 16384000 / 4);

    embed_kernel<<<MROWS, 128>>>(x, xh, xl, input, emb);

    const dim3 gQKV(3 * DMODEL / 256, MROWS / 128);  // (6, 64)
    const dim3 gD(DMODEL / 256, MROWS / 128);        // (2, 64)
    const dim3 gF(DFFN / 256, MROWS / 128);          // (8, 64)
    const dim3 gV(NVOCAB / 256, MROWS / 128);        // (125, 64)
    const dim3 gAttn(LSEQ / 128, BATCH, NHEAD);

    for (int l = 0; l < NLAYER; l++) {
        const size_t qofs = (size_t)l * 1536 * 512;
        const size_t wofs = (size_t)l * DMODEL * DMODEL;
        const size_t f1 = (size_t)l * DFFN * DMODEL;

        gemm_mma<false, false, true><<<gQKV, 256, GEMM_SMEM>>>(
            nullptr, qkvh, qkvl, xh, xl, whi + WQKV0 + qofs, wlo + WQKV0 + qofs,
            nullptr, MROWS, 3 * DMODEL, DMODEL);

        attn_mma<<<gAttn, 256, ATTN_SMEM>>>(ch, cl, qkvh, qkvl);

        gemm_mma<false, false, false><<<gD, 256, GEMM_SMEM>>>(
            t, nullptr, nullptr, ch, cl, whi + WO0 + wofs, wlo + WO0 + wofs,
            nullptr, MROWS, DMODEL, DMODEL);
        add_ln_kernel<<<MROWS, 128>>>(x, xh, xl, t, ln1a + l * DMODEL, ln1b + l * DMODEL);

        gemm_mma<true, true, true><<<gF, 256, GEMM_SMEM>>>(
            nullptr, ahi, alo, xh, xl, whi + W10 + f1, wlo + W10 + f1,
            b1 + l * DFFN, MROWS, DFFN, DMODEL);
        gemm_mma<true, false, false><<<gD, 256, GEMM_SMEM>>>(
            t, nullptr, nullptr, ahi, alo, whi + W20 + f1, wlo + W20 + f1,
            b2 + l * DMODEL, MROWS, DMODEL, DFFN);
        add_ln_kernel<<<MROWS, 128>>>(x, xh, xl, t, ln2a + l * DMODEL, ln2b + l * DMODEL);
    }

    add_ln_kernel<<<MROWS, 128>>>(x, xh, xl, nullptr, fna, fnb);
    gemm_mma<true, false, false><<<gV, 256, GEMM_SMEM>>>(
        out, nullptr, nullptr, xh, xl, whi + WD0, wlo + WD0,
        decb, MROWS, NVOCAB, DMODEL);
}

// round 6
// speedup vs baseline: 3.2321x; 1.0782x over previous
#include <cuda_runtime.h>
#include <cuda_bf16.h>
#include <math.h>
#include <stdint.h>

#define LSEQ 2048
#define BATCH 4
#define DMODEL 512
#define NHEAD 8
#define DKH 64
#define NLAYER 4
#define DFFN 2048
#define MROWS (LSEQ * BATCH)   // 8192
#define NVOCAB 32000

// ---------------- scratch (device globals; no allocation allowed) ----------------
__device__ float g_x[MROWS * DMODEL];
__device__ float g_t[MROWS * DMODEL];
__device__ __nv_bfloat16 g_xs[2 * MROWS * DMODEL];
__device__ __nv_bfloat16 g_qkvs[2 * MROWS * 3 * DMODEL];   // fused qkv, stride 1536
__device__ __nv_bfloat16 g_cs[2 * MROWS * DMODEL];
__device__ __nv_bfloat16 g_ahi[MROWS * DFFN];
__device__ __nv_bfloat16 g_alo[MROWS * DFFN];

// weight split storage (bf16 hi/lo), element offsets:
#define WQKV0 0                 // fused [NLAYER][1536][512]
#define WO0 3145728
#define W10 4194304
#define W20 8388608
#define WD0 12582912
#define WTOT 28966912
__device__ __nv_bfloat16 g_whi[WTOT];
__device__ __nv_bfloat16 g_wlo[WTOT];

// ---------------- helpers ----------------
__device__ __forceinline__ uint32_t s2u(const void* p) {
    uint32_t a;
    asm("{ .reg .u64 t; cvta.to.shared.u64 t, %1; cvt.u32.u64 %0, t; }" : "=r"(a) : "l"(p));
    return a;
}
__device__ __forceinline__ void cpa16(uint32_t d, const void* s) {
    asm volatile("cp.async.cg.shared.global [%0], [%1], 16;" :: "r"(d), "l"(s));
}
__device__ __forceinline__ uint32_t bf2pack(float x, float y) {
    __nv_bfloat162 t; t.x = __float2bfloat16(x); t.y = __float2bfloat16(y);
    return *(uint32_t*)&t;
}

#define LDSM4(r, a) \
    asm volatile("ldmatrix.sync.aligned.m8n8.x4.shared.b16 {%0,%1,%2,%3}, [%4];" \
        : "=r"((r)[0]), "=r"((r)[1]), "=r"((r)[2]), "=r"((r)[3]) : "r"(a))
#define LDSM4T(r, a) \
    asm volatile("ldmatrix.sync.aligned.m8n8.x4.trans.shared.b16 {%0,%1,%2,%3}, [%4];" \
        : "=r"((r)[0]), "=r"((r)[1]), "=r"((r)[2]), "=r"((r)[3]) : "r"(a))

#define MMA16816(c, a, b0, b1) \
    asm volatile("mma.sync.aligned.m16n8k16.row.col.f32.bf16.bf16.f32 " \
        "{%0,%1,%2,%3}, {%4,%5,%6,%7}, {%8,%9}, {%0,%1,%2,%3};" \
        : "+f"((c)[0]), "+f"((c)[1]), "+f"((c)[2]), "+f"((c)[3]) \
        : "r"((a)[0]), "r"((a)[1]), "r"((a)[2]), "r"((a)[3]), "r"(b0), "r"(b1))

// ---------------- fp32 -> bf16 hi/lo split (weights; optional scale) ----------------
__global__ void __launch_bounds__(256) split_kernel(__nv_bfloat16* __restrict__ hi,
                                                    __nv_bfloat16* __restrict__ lo,
                                                    const float* __restrict__ src,
                                                    float scale, int n4)
{
    int i = blockIdx.x * 256 + threadIdx.x;
    if (i >= n4) return;
    float4 v = ((const float4*)src)[i];
    v.x *= scale; v.y *= scale; v.z *= scale; v.w *= scale;
    float h0f, h1f, h2f, h3f;
    __nv_bfloat16 h0 = __float2bfloat16(v.x); h0f = __bfloat162float(h0);
    __nv_bfloat16 h1 = __float2bfloat16(v.y); h1f = __bfloat162float(h1);
    __nv_bfloat16 h2 = __float2bfloat16(v.z); h2f = __bfloat162float(h2);
    __nv_bfloat16 h3 = __float2bfloat16(v.w); h3f = __bfloat162float(h3);
    ((uint32_t*)hi)[2 * i + 0] = bf2pack(v.x, v.y);
    ((uint32_t*)hi)[2 * i + 1] = bf2pack(v.z, v.w);
    ((uint32_t*)lo)[2 * i + 0] = bf2pack(v.x - h0f, v.y - h1f);
    ((uint32_t*)lo)[2 * i + 1] = bf2pack(v.z - h2f, v.w - h3f);
}

// ---------------- bf16 mma.sync GEMM: C[M,N] = A[M,K]*W[N,K]^T, 3x split ----------------
// BM=128, BN=256, BK=64; 256 threads; warp grid 2(m)x4(n); warp tile 64x64; 2 stages.
#define TSTRIDE 144                          // 128B data + 16B pad
#define A_TILE_B (128 * TSTRIDE)             // 18432
#define B_TILE_B (256 * TSTRIDE)             // 36864
#define STAGE_B (2 * A_TILE_B + 2 * B_TILE_B)   // 110592
#define GEMM_SMEM (2 * STAGE_B)              // 221184
#define OFF_AH 0
#define OFF_AL A_TILE_B
#define OFF_BH (2 * A_TILE_B)
#define OFF_BL (2 * A_TILE_B + B_TILE_B)

template <bool BIAS, bool RELU, bool SPLIT>
__global__ void __launch_bounds__(256) gemm_mma(float* __restrict__ C,
                                                __nv_bfloat16* __restrict__ Oh,
                                                __nv_bfloat16* __restrict__ Ol,
                                                const __nv_bfloat16* __restrict__ Ahi,
                                                const __nv_bfloat16* __restrict__ Alo,
                                                const __nv_bfloat16* __restrict__ Bhi,
                                                const __nv_bfloat16* __restrict__ Blo,
                                                const float* __restrict__ bias,
                                                int M, int N, int K)
{
    extern __shared__ char smem[];
    const uint32_t sb = s2u(smem);
    const int tid = threadIdx.x;
    const int warp = tid >> 5, lane = tid & 31;
    const int bm = blockIdx.y * 128;
    const int bn = blockIdx.x * 256;
    const int warp_m = warp >> 2;          // 0..1
    const int warp_n = warp & 3;           // 0..3
    const int nch = K >> 6;                // K/64

    const __nv_bfloat16* pAh = Ahi + (size_t)bm * K;
    const __nv_bfloat16* pAl = Alo + (size_t)bm * K;
    const __nv_bfloat16* pBh = Bhi + (size_t)bn * K;
    const __nv_bfloat16* pBl = Blo + (size_t)bn * K;

    auto load_stage = [&](uint32_t st, int k0) {
        // A: 2 arrays x 128 rows x 8 segs = 2048 chunks of 16B
#pragma unroll
        for (int j = 0; j < 8; j++) {
            int idx = tid + j * 256;
            int arr = idx >> 10;
            int r = (idx >> 3) & 127;
            int seg = idx & 7;
            const __nv_bfloat16* src = arr ? pAl : pAh;
            cpa16(st + arr * A_TILE_B + r * TSTRIDE + seg * 16,
                  src + (size_t)r * K + k0 + seg * 8);
        }
        // B: 2 arrays x 256 rows x 8 segs = 4096 chunks
#pragma unroll
        for (int j = 0; j < 16; j++) {
            int idx = tid + j * 256;
            int arr = idx >> 11;
            int r = (idx >> 3) & 255;
            int seg = idx & 7;
            const __nv_bfloat16* src = arr ? pBl : pBh;
            cpa16(st + OFF_BH + arr * B_TILE_B + r * TSTRIDE + seg * 16,
                  src + (size_t)r * K + k0 + seg * 8);
        }
    };

    float acc[4][8][4];
#pragma unroll
    for (int i = 0; i < 4; i++)
#pragma unroll
        for (int j = 0; j < 8; j++)
#pragma unroll
            for (int q = 0; q < 4; q++) acc[i][j][q] = 0.f;

    const int g = lane >> 3, lr = lane & 7;
    const int a_row = lr + (g & 1) * 8;
    const int a_k8 = g >> 1;
    const int b_row = lr + (g >> 1) * 8;
    const int b_k8 = g & 1;

    load_stage(sb, 0);
    asm volatile("cp.async.commit_group;" ::: "memory");

    for (int i = 0; i < nch; i++) {
        const uint32_t st = sb + (i & 1) * STAGE_B;
        __syncthreads();   // everyone done reading the other stage
        if (i + 1 < nch) load_stage(sb + ((i + 1) & 1) * STAGE_B, (i + 1) * 64);
        asm volatile("cp.async.commit_group;" ::: "memory");
        asm volatile("cp.async.wait_group 1;" ::: "memory");   // chunk i arrived
        __syncthreads();

#pragma unroll
        for (int ks = 0; ks < 4; ks++) {
            uint32_t ah[4][4], al[4][4];
#pragma unroll
            for (int mi = 0; mi < 4; mi++) {
                uint32_t aaddr = st + (warp_m * 64 + mi * 16 + a_row) * TSTRIDE +
                                 ks * 32 + a_k8 * 16;
                LDSM4(ah[mi], aaddr + OFF_AH);
                LDSM4(al[mi], aaddr + OFF_AL);
            }
#pragma unroll
            for (int ng = 0; ng < 4; ng++) {
                uint32_t bh[4], bl[4];
                uint32_t baddr = st + (warp_n * 64 + ng * 16 + b_row) * TSTRIDE +
                                 ks * 32 + b_k8 * 16;
                LDSM4(bh, baddr + OFF_BH);
                LDSM4(bl, baddr + OFF_BL);
#pragma unroll
                for (int mi = 0; mi < 4; mi++) {
                    MMA16816(acc[mi][2 * ng], ah[mi], bh[0], bh[1]);
                    MMA16816(acc[mi][2 * ng + 1], ah[mi], bh[2], bh[3]);
                    MMA16816(acc[mi][2 * ng], ah[mi], bl[0], bl[1]);
                    MMA16816(acc[mi][2 * ng + 1], ah[mi], bl[2], bl[3]);
                    MMA16816(acc[mi][2 * ng], al[mi], bh[0], bh[1]);
                    MMA16816(acc[mi][2 * ng + 1], al[mi], bh[2], bh[3]);
                }
            }
        }
    }

    const int tm = lane >> 2, tn = (lane & 3) * 2;
#pragma unroll
    for (int mi = 0; mi < 4; mi++) {
#pragma unroll
        for (int nj = 0; nj < 8; nj++) {
            const float* a4 = acc[mi][nj];
            int row0 = bm + warp_m * 64 + mi * 16 + tm;
            int col = bn + warp_n * 64 + nj * 8 + tn;
            float b0 = 0.f, b1 = 0.f;
            if (BIAS) { b0 = bias[col]; b1 = bias[col + 1]; }
            float v0 = a4[0] + b0, v1 = a4[1] + b1;
            float v2 = a4[2] + b0, v3 = a4[3] + b1;
            if (RELU) {
                v0 = fmaxf(v0, 0.f); v1 = fmaxf(v1, 0.f);
                v2 = fmaxf(v2, 0.f); v3 = fmaxf(v3, 0.f);
            }
            if (SPLIT) {
                uint32_t h0 = bf2pack(v0, v1), h1 = bf2pack(v2, v3);
                __nv_bfloat162 hh0 = *(__nv_bfloat162*)&h0;
                __nv_bfloat162 hh1 = *(__nv_bfloat162*)&h1;
                uint32_t l0p = bf2pack(v0 - __bfloat162float(hh0.x),
                                       v1 - __bfloat162float(hh0.y));
                uint32_t l1p = bf2pack(v2 - __bfloat162float(hh1.x),
                                       v3 - __bfloat162float(hh1.y));
                *(uint32_t*)(Oh + (size_t)row0 * N + col) = h0;
                *(uint32_t*)(Oh + (size_t)(row0 + 8) * N + col) = h1;
                *(uint32_t*)(Ol + (size_t)row0 * N + col) = l0p;
                *(uint32_t*)(Ol + (size_t)(row0 + 8) * N + col) = l1p;
            } else {
                *(float2*)(C + (size_t)row0 * N + col) = make_float2(v0, v1);
                *(float2*)(C + (size_t)(row0 + 8) * N + col) = make_float2(v2, v3);
            }
        }
    }
}

// ---------------- embedding + positional encoding (fp32 + split out) ----------------
__global__ void __launch_bounds__(128) embed_kernel(float* __restrict__ x,
                                                    __nv_bfloat16* __restrict__ xh,
                                                    __nv_bfloat16* __restrict__ xl,
                                                    const int* __restrict__ tok,
                                                    const float* __restrict__ emb)
{
    int m = blockIdx.x;
    int l = m >> 2;
    int t = tok[m];
    const float sq = 22.627416997969522f;
    const double nlog = 9.210340371976184;
#pragma unroll
    for (int j = 0; j < 4; j++) {
        int d = threadIdx.x + j * 128;
        int i = d >> 1;
        float freqf = (float)exp(-(double)(2 * i) * (nlog / 512.0));
        float angf = (float)l * freqf;
        double ang = (double)angf;
        float pe = (d & 1) ? (float)cos(ang) : (float)sin(ang);
        float v = emb[(size_t)t * DMODEL + d] * sq + pe;
        x[(size_t)m * DMODEL + d] = v;
        __nv_bfloat16 h = __float2bfloat16(v);
        xh[(size_t)m * DMODEL + d] = h;
        xl[(size_t)m * DMODEL + d] = __float2bfloat16(v - __bfloat162float(h));
    }
}

// ---------------- mma flash attention (causal, 3x bf16 split), fused-QKV input --------
#define QKVSTR 1536
#define AT_S 144
#define AQ_B (128 * AT_S)
#define AKV_TILE (64 * AT_S)
#define AKV_STAGE (4 * AKV_TILE)
#define ATTN_SMEM (2 * AQ_B + 2 * AKV_STAGE)  // 110592

__global__ void __launch_bounds__(256) attn_mma(
    __nv_bfloat16* __restrict__ ctxh, __nv_bfloat16* __restrict__ ctxl,
    const __nv_bfloat16* __restrict__ qkvh, const __nv_bfloat16* __restrict__ qkvl)
{
    extern __shared__ char smem[];
    const uint32_t sb = s2u(smem);
    const int tid = threadIdx.x, warp = tid >> 5, lane = tid & 31;
    const int bx = blockIdx.x, b = blockIdx.y, h = blockIdx.z;
    const int l0 = bx * 128;
    const int ntiles = 2 * bx + 2;

    const uint32_t sQh = sb, sQl = sb + AQ_B;
    const uint32_t sKV = sb + 2 * AQ_B;

#pragma unroll
    for (int t = 0; t < 8; t++) {
        int idx = tid + t * 256;
        int row = idx >> 4;
        int sub = idx & 15;
        int seg = sub & 7;
        const __nv_bfloat16* src = (sub < 8) ? qkvh : qkvl;
        uint32_t dst = ((sub < 8) ? sQh : sQl) + row * AT_S + seg * 16;
        cpa16(dst, src + ((size_t)(l0 + row) * 4 + b) * QKVSTR + h * 64 + seg * 8);
    }
    asm volatile("cp.async.commit_group;" ::: "memory");

    auto load_kv = [&](int s, int jt) {
        uint32_t st = sKV + s * AKV_STAGE;
#pragma unroll
        for (int t = 0; t < 8; t++) {
            int idx = tid + t * 256;
            int arr = idx >> 9;
            int row = (idx >> 3) & 63;
            int seg = idx & 7;
            const __nv_bfloat16* src = (arr & 1) ? qkvl : qkvh;
            int coff = (arr < 2) ? 512 : 1024;
            cpa16(st + arr * AKV_TILE + row * AT_S + seg * 16,
                  src + ((size_t)(jt * 64 + row) * 4 + b) * QKVSTR + coff + h * 64 + seg * 8);
        }
    };
    load_kv(0, 0);
    asm volatile("cp.async.commit_group;" ::: "memory");

    const int a_row = (lane & 7) + ((lane >> 3) & 1) * 8;
    const int a_k8 = lane >> 4;
    const int b_row = (lane & 7) + (lane >> 4) * 8;
    const int b_k8 = (lane >> 3) & 1;

    uint32_t qfh[4][4], qfl[4][4];
    float ctx[8][4];
#pragma unroll
    for (int i = 0; i < 8; i++)
#pragma unroll
        for (int j = 0; j < 4; j++) ctx[i][j] = 0.f;
    float m0 = -INFINITY, m1 = -INFINITY, l0s = 0.f, l1s = 0.f;

    for (int jt = 0; jt < ntiles; jt++) {
        const uint32_t st = sKV + (jt & 1) * AKV_STAGE;
        __syncthreads();
        if (jt + 1 < ntiles) {
            load_kv((jt + 1) & 1, jt + 1);
            asm volatile("cp.async.commit_group;" ::: "memory");
            asm volatile("cp.async.wait_group 1;" ::: "memory");
        } else {
            asm volatile("cp.async.wait_group 0;" ::: "memory");
        }
        __syncthreads();

        if (jt == 0) {
#pragma unroll
            for (int kb = 0; kb < 4; kb++) {
                uint32_t qa = sQh + (warp * 16 + a_row) * AT_S + (kb * 2 + a_k8) * 16;
                LDSM4(qfh[kb], qa);
                LDSM4(qfl[kb], qa + AQ_B);
            }
        }

        float S[8][4];
#pragma unroll
        for (int i = 0; i < 8; i++)
#pragma unroll
            for (int j = 0; j < 4; j++) S[i][j] = 0.f;
#pragma unroll
        for (int kb = 0; kb < 4; kb++) {
#pragma unroll
            for (int ng = 0; ng < 4; ng++) {
                uint32_t kbh[4], kbl[4];
                uint32_t ka = st + (ng * 16 + b_row) * AT_S + (kb * 2 + b_k8) * 16;
                LDSM4(kbh, ka);
                LDSM4(kbl, ka + AKV_TILE);
                int nb = ng * 2;
                MMA16816(S[nb], qfh[kb], kbh[0], kbh[1]);
                MMA16816(S[nb + 1], qfh[kb], kbh[2], kbh[3]);
                MMA16816(S[nb], qfh[kb], kbl[0], kbl[1]);
                MMA16816(S[nb + 1], qfh[kb], kbl[2], kbl[3]);
                MMA16816(S[nb], qfl[kb], kbh[0], kbh[1]);
                MMA16816(S[nb + 1], qfl[kb], kbh[2], kbh[3]);
            }
        }

        const int qr0 = l0 + warp * 16 + (lane >> 2);
        const int qr1 = qr0 + 8;
        if (jt >= ntiles - 2) {
#pragma unroll
            for (int nb = 0; nb < 8; nb++) {
                int c = jt * 64 + nb * 8 + 2 * (lane & 3);
                if (c > qr0) S[nb][0] = -INFINITY;
                if (c + 1 > qr0) S[nb][1] = -INFINITY;
                if (c > qr1) S[nb][2] = -INFINITY;
                if (c + 1 > qr1) S[nb][3] = -INFINITY;
            }
        }

        float mx0 = -INFINITY, mx1 = -INFINITY;
#pragma unroll
        for (int nb = 0; nb < 8; nb++) {
            mx0 = fmaxf(mx0, fmaxf(S[nb][0], S[nb][1]));
            mx1 = fmaxf(mx1, fmaxf(S[nb][2], S[nb][3]));
        }
        mx0 = fmaxf(mx0, __shfl_xor_sync(0xffffffffu, mx0, 1));
        mx0 = fmaxf(mx0, __shfl_xor_sync(0xffffffffu, mx0, 2));
        mx1 = fmaxf(mx1, __shfl_xor_sync(0xffffffffu, mx1, 1));
        mx1 = fmaxf(mx1, __shfl_xor_sync(0xffffffffu, mx1, 2));
        float nm0 = fmaxf(m0, mx0), nm1 = fmaxf(m1, mx1);
        float c0 = __expf(m0 - nm0), c1 = __expf(m1 - nm1);
        m0 = nm0; m1 = nm1;
        float s0 = 0.f, s1 = 0.f;
#pragma unroll
        for (int nb = 0; nb < 8; nb++) {
            S[nb][0] = __expf(S[nb][0] - nm0);
            S[nb][1] = __expf(S[nb][1] - nm0);
            S[nb][2] = __expf(S[nb][2] - nm1);
            S[nb][3] = __expf(S[nb][3] - nm1);
            s0 += S[nb][0] + S[nb][1];
            s1 += S[nb][2] + S[nb][3];
        }
        s0 += __shfl_xor_sync(0xffffffffu, s0, 1);
        s0 += __shfl_xor_sync(0xffffffffu, s0, 2);
        s1 += __shfl_xor_sync(0xffffffffu, s1, 1);
        s1 += __shfl_xor_sync(0xffffffffu, s1, 2);
        l0s = l0s * c0 + s0;
        l1s = l1s * c1 + s1;
#pragma unroll
        for (int nb = 0; nb < 8; nb++) {
            ctx[nb][0] *= c0; ctx[nb][1] *= c0;
            ctx[nb][2] *= c1; ctx[nb][3] *= c1;
        }

        uint32_t ph[4][4], pl[4][4];
#pragma unroll
        for (int kb = 0; kb < 4; kb++) {
            const float* sA = S[2 * kb];
            const float* sB = S[2 * kb + 1];
            ph[kb][0] = bf2pack(sA[0], sA[1]);
            ph[kb][1] = bf2pack(sA[2], sA[3]);
            ph[kb][2] = bf2pack(sB[0], sB[1]);
            ph[kb][3] = bf2pack(sB[2], sB[3]);
            __nv_bfloat162 t0 = *(__nv_bfloat162*)&ph[kb][0];
            __nv_bfloat162 t1 = *(__nv_bfloat162*)&ph[kb][1];
            __nv_bfloat162 t2 = *(__nv_bfloat162*)&ph[kb][2];
            __nv_bfloat162 t3 = *(__nv_bfloat162*)&ph[kb][3];
            pl[kb][0] = bf2pack(sA[0] - __bfloat162float(t0.x), sA[1] - __bfloat162float(t0.y));
            pl[kb][1] = bf2pack(sA[2] - __bfloat162float(t1.x), sA[3] - __bfloat162float(t1.y));
            pl[kb][2] = bf2pack(sB[0] - __bfloat162float(t2.x), sB[1] - __bfloat162float(t2.y));
            pl[kb][3] = bf2pack(sB[2] - __bfloat162float(t3.x), sB[3] - __bfloat162float(t3.y));
        }

        const uint32_t vrow = (lane & 7) + ((lane >> 3) & 1) * 8;
        const uint32_t vcol16 = (lane >> 4) * 16;
#pragma unroll
        for (int kb = 0; kb < 4; kb++) {
#pragma unroll
            for (int ngd = 0; ngd < 4; ngd++) {
                uint32_t vbh[4], vbl[4];
                uint32_t va = st + 2 * AKV_TILE + (kb * 16 + vrow) * AT_S + ngd * 32 + vcol16;
                LDSM4T(vbh, va);
                LDSM4T(vbl, va + AKV_TILE);
                int nd = ngd * 2;
                MMA16816(ctx[nd], ph[kb], vbh[0], vbh[1]);
                MMA16816(ctx[nd + 1], ph[kb], vbh[2], vbh[3]);
                MMA16816(ctx[nd], ph[kb], vbl[0], vbl[1]);
                MMA16816(ctx[nd + 1], ph[kb], vbl[2], vbl[3]);
                MMA16816(ctx[nd], pl[kb], vbh[0], vbh[1]);
                MMA16816(ctx[nd + 1], pl[kb], vbh[2], vbh[3]);
            }
        }
    }

    float inv0 = 1.f / l0s, inv1 = 1.f / l1s;
    const size_t mg0 = (size_t)(l0 + warp * 16 + (lane >> 2)) * 4 + b;
    const size_t mg1 = mg0 + 32;
#pragma unroll
    for (int nd = 0; nd < 8; nd++) {
        int col = h * 64 + nd * 8 + 2 * (lane & 3);
        float v0 = ctx[nd][0] * inv0, v1 = ctx[nd][1] * inv0;
        float v2 = ctx[nd][2] * inv1, v3 = ctx[nd][3] * inv1;
        uint32_t h0 = bf2pack(v0, v1), h1 = bf2pack(v2, v3);
        __nv_bfloat162 hh0 = *(__nv_bfloat162*)&h0;
        __nv_bfloat162 hh1 = *(__nv_bfloat162*)&h1;
        uint32_t l0p = bf2pack(v0 - __bfloat162float(hh0.x), v1 - __bfloat162float(hh0.y));
        uint32_t l1p = bf2pack(v2 - __bfloat162float(hh1.x), v3 - __bfloat162float(hh1.y));
        *(uint32_t*)(ctxh + mg0 * 512 + col) = h0;
        *(uint32_t*)(ctxh + mg1 * 512 + col) = h1;
        *(uint32_t*)(ctxl + mg0 * 512 + col) = l0p;
        *(uint32_t*)(ctxl + mg1 * 512 + col) = l1p;
    }
}

// ---------------- fused residual-add + LayerNorm (+ optional second LN, + split out) ----
__global__ void __launch_bounds__(128) add_ln_kernel(float* __restrict__ x,
                                                     __nv_bfloat16* __restrict__ xh,
                                                     __nv_bfloat16* __restrict__ xl,
                                                     const float* __restrict__ y,
                                                     const float* __restrict__ a,
                                                     const float* __restrict__ b,
                                                     const float* __restrict__ fa,
                                                     const float* __restrict__ fb)
{
    const int m = blockIdx.x;
    const int tid = threadIdx.x;
    const size_t base = (size_t)m * DMODEL;
    __shared__ float red[8];

    float v[4];
#pragma unroll
    for (int j = 0; j < 4; j++) {
        int d = tid + j * 128;
        float xv = x[base + d];
        if (y) xv += y[base + d];
        v[j] = xv;
    }
    float s = v[0] + v[1] + v[2] + v[3];
#pragma unroll
    for (int o = 16; o > 0; o >>= 1) s += __shfl_xor_sync(0xffffffffu, s, o);
    if ((tid & 31) == 0) red[tid >> 5] = s;
    __syncthreads();
    float mean = (red[0] + red[1] + red[2] + red[3]) * (1.f / 512.f);

    float ss = 0.f;
#pragma unroll
    for (int j = 0; j < 4; j++) {
        float dm = v[j] - mean;
        ss += dm * dm;
    }
#pragma unroll
    for (int o = 16; o > 0; o >>= 1) ss += __shfl_xor_sync(0xffffffffu, ss, o);
    if ((tid & 31) == 0) red[4 + (tid >> 5)] = ss;
    __syncthreads();
    float var = (red[4] + red[5] + red[6] + red[7]) * (1.f / 511.f);
    float inv = 1.f / (sqrtf(var) + 1e-6f);

    float o4[4];
#pragma unroll
    for (int j = 0; j < 4; j++) {
        int d = tid + j * 128;
        o4[j] = a[d] * (v[j] - mean) * inv + b[d];
    }

    if (fa) {
        // second (final) LayerNorm over o4
        __syncthreads();
        float s2 = o4[0] + o4[1] + o4[2] + o4[3];
#pragma unroll
        for (int o = 16; o > 0; o >>= 1) s2 += __shfl_xor_sync(0xffffffffu, s2, o);
        if ((tid & 31) == 0) red[tid >> 5] = s2;
        __syncthreads();
        float mean2 = (red[0] + red[1] + red[2] + red[3]) * (1.f / 512.f);
        float ss2 = 0.f;
#pragma unroll
        for (int j = 0; j < 4; j++) {
            float dm = o4[j] - mean2;
            ss2 += dm * dm;
        }
#pragma unroll
        for (int o = 16; o > 0; o >>= 1) ss2 += __shfl_xor_sync(0xffffffffu, ss2, o);
        if ((tid & 31) == 0) red[4 + (tid >> 5)] = ss2;
        __syncthreads();
        float var2 = (red[4] + red[5] + red[6] + red[7]) * (1.f / 511.f);
        float inv2 = 1.f / (sqrtf(var2) + 1e-6f);
#pragma unroll
        for (int j = 0; j < 4; j++) {
            int d = tid + j * 128;
            o4[j] = fa[d] * (o4[j] - mean2) * inv2 + fb[d];
        }
    }

#pragma unroll
    for (int j = 0; j < 4; j++) {
        int d = tid + j * 128;
        float o = o4[j];
        x[base + d] = o;
        __nv_bfloat16 h = __float2bfloat16(o);
        xh[base + d] = h;
        xl[base + d] = __float2bfloat16(o - __bfloat162float(h));
    }
}

// ---------------- orchestration ----------------
extern "C" void kernel_launch(void* const* d_in, const int* in_sizes, int n_in,
                              void* d_out, int out_size)
{
    (void)in_sizes; (void)n_in; (void)out_size;
    const int*   input = (const int*)  d_in[0];
    const float* emb   = (const float*)d_in[1];
    const float* Wq    = (const float*)d_in[2];
    const float* Wk    = (const float*)d_in[3];
    const float* Wv    = (const float*)d_in[4];
    const float* Wo    = (const float*)d_in[5];
    const float* w1    = (const float*)d_in[6];
    const float* b1    = (const float*)d_in[7];
    const float* w2    = (const float*)d_in[8];
    const float* b2    = (const float*)d_in[9];
    const float* ln1a  = (const float*)d_in[10];
    const float* ln1b  = (const float*)d_in[11];
    const float* ln2a  = (const float*)d_in[12];
    const float* ln2b  = (const float*)d_in[13];
    const float* fna   = (const float*)d_in[14];
    const float* fnb   = (const float*)d_in[15];
    const float* decW  = (const float*)d_in[16];
    const float* decb  = (const float*)d_in[17];
    float* out = (float*)d_out;

    float *x, *t;
    __nv_bfloat16 *xs, *qkvs, *cs, *ahi, *alo, *whi, *wlo;
    cudaGetSymbolAddress((void**)&x,    g_x);
    cudaGetSymbolAddress((void**)&t,    g_t);
    cudaGetSymbolAddress((void**)&xs,   g_xs);
    cudaGetSymbolAddress((void**)&qkvs, g_qkvs);
    cudaGetSymbolAddress((void**)&cs,   g_cs);
    cudaGetSymbolAddress((void**)&ahi,  g_ahi);
    cudaGetSymbolAddress((void**)&alo,  g_alo);
    cudaGetSymbolAddress((void**)&whi,  g_whi);
    cudaGetSymbolAddress((void**)&wlo,  g_wlo);

    const int AS = MROWS * DMODEL;
    const int QAS = MROWS * 3 * DMODEL;
    __nv_bfloat16 *xh = xs, *xl = xs + AS;
    __nv_bfloat16 *qkvh = qkvs, *qkvl = qkvs + QAS;
    __nv_bfloat16 *ch = cs, *cl = cs + AS;

    cudaFuncSetAttribute(attn_mma, cudaFuncAttributeMaxDynamicSharedMemorySize, ATTN_SMEM);
    cudaFuncSetAttribute(gemm_mma<false, false, true>,  cudaFuncAttributeMaxDynamicSharedMemorySize, GEMM_SMEM);
    cudaFuncSetAttribute(gemm_mma<false, false, false>, cudaFuncAttributeMaxDynamicSharedMemorySize, GEMM_SMEM);
    cudaFuncSetAttribute(gemm_mma<true, true, true>,    cudaFuncAttributeMaxDynamicSharedMemorySize, GEMM_SMEM);
    cudaFuncSetAttribute(gemm_mma<true, false, false>,  cudaFuncAttributeMaxDynamicSharedMemorySize, GEMM_SMEM);

    // weight splits: fused QKV per layer [1536][512] (q scaled by 1/8), then Wo/w1/w2/decW
    for (int l = 0; l < NLAYER; l++) {
        size_t so = (size_t)l * 262144;
        size_t dq = (size_t)l * 1536 * 512;
        split_kernel<<<256, 256>>>(whi + WQKV0 + dq,              wlo + WQKV0 + dq,              Wq + so, 0.125f, 65536);
        split_kernel<<<256, 256>>>(whi + WQKV0 + dq + 512 * 512,  wlo + WQKV0 + dq + 512 * 512,  Wk + so, 1.0f,   65536);
        split_kernel<<<256, 256>>>(whi + WQKV0 + dq + 1024 * 512, wlo + WQKV0 + dq + 1024 * 512, Wv + so, 1.0f,   65536);
    }
    split_kernel<<<1024, 256>>>(whi + WO0, wlo + WO0, Wo, 1.0f, 1048576 / 4);
    split_kernel<<<4096, 256>>>(whi + W10, wlo + W10, w1, 1.0f, 4194304 / 4);
    split_kernel<<<4096, 256>>>(whi + W20, wlo + W20, w2, 1.0f, 4194304 / 4);
    split_kernel<<<16000, 256>>>(whi + WD0, wlo + WD0, decW, 1.0f, 16384000 / 4);

    embed_kernel<<<MROWS, 128>>>(x, xh, xl, input, emb);

    const dim3 gQKV(3 * DMODEL / 256, MROWS / 128);  // (6, 64)
    const dim3 gD(DMODEL / 256, MROWS / 128);        // (2, 64)
    const dim3 gF(DFFN / 256, MROWS / 128);          // (8, 64)
    const dim3 gV(NVOCAB / 256, MROWS / 128);        // (125, 64)
    const dim3 gAttn(LSEQ / 128, BATCH, NHEAD);

    for (int l = 0; l < NLAYER; l++) {
        const size_t qofs = (size_t)l * 1536 * 512;
        const size_t wofs = (size_t)l * DMODEL * DMODEL;
        const size_t f1 = (size_t)l * DFFN * DMODEL;

        gemm_mma<false, false, true><<<gQKV, 256, GEMM_SMEM>>>(
            nullptr, qkvh, qkvl, xh, xl, whi + WQKV0 + qofs, wlo + WQKV0 + qofs,
            nullptr, MROWS, 3 * DMODEL, DMODEL);

        attn_mma<<<gAttn, 256, ATTN_SMEM>>>(ch, cl, qkvh, qkvl);

        gemm_mma<false, false, false><<<gD, 256, GEMM_SMEM>>>(
            t, nullptr, nullptr, ch, cl, whi + WO0 + wofs, wlo + WO0 + wofs,
            nullptr, MROWS, DMODEL, DMODEL);
        add_ln_kernel<<<MROWS, 128>>>(x, xh, xl, t, ln1a + l * DMODEL, ln1b + l * DMODEL,
                                      nullptr, nullptr);

        gemm_mma<true, true, true><<<gF, 256, GEMM_SMEM>>>(
            nullptr, ahi, alo, xh, xl, whi + W10 + f1, wlo + W10 + f1,
            b1 + l * DFFN, MROWS, DFFN, DMODEL);
        gemm_mma<true, false, false><<<gD, 256, GEMM_SMEM>>>(
            t, nullptr, nullptr, ahi, alo, whi + W20 + f1, wlo + W20 + f1,
            b2 + l * DMODEL, MROWS, DMODEL, DFFN);
        add_ln_kernel<<<MROWS, 128>>>(x, xh, xl, t, ln2a + l * DMODEL, ln2b + l * DMODEL,
                                      (l == NLAYER - 1) ? fna : nullptr,
                                      (l == NLAYER - 1) ? fnb : nullptr);
    }

    gemm_mma<true, false, false><<<gV, 256, GEMM_SMEM>>>(
        out, nullptr, nullptr, xh, xl, whi + WD0, wlo + WD0,
        decb, MROWS, NVOCAB, DMODEL);
}

// round 7
// speedup vs baseline: 3.6478x; 1.1286x over previous
#include <cuda_runtime.h>
#include <cuda_bf16.h>
#include <cuda_fp16.h>
#include <math.h>
#include <stdint.h>

#define LSEQ 2048
#define BATCH 4
#define DMODEL 512
#define NHEAD 8
#define DKH 64
#define NLAYER 4
#define DFFN 2048
#define MROWS (LSEQ * BATCH)   // 8192
#define NVOCAB 32000

// ---------------- scratch (device globals; no allocation allowed) ----------------
__device__ float g_x[MROWS * DMODEL];
__device__ float g_t[MROWS * DMODEL];
__device__ __nv_bfloat16 g_xs[2 * MROWS * DMODEL];
__device__ __nv_bfloat16 g_qkvs[2 * MROWS * 3 * DMODEL];   // fused qkv, stride 1536
__device__ __nv_bfloat16 g_cs[2 * MROWS * DMODEL];
__device__ __nv_bfloat16 g_ahi[MROWS * DFFN];
__device__ __nv_bfloat16 g_alo[MROWS * DFFN];

// weight split storage (bf16 hi/lo except decoder region used as fp16), element offsets:
#define WQKV0 0                 // fused [NLAYER][1536][512]
#define WO0 3145728
#define W10 4194304
#define W20 8388608
#define WD0 12582912
#define WTOT 28966912
__device__ __nv_bfloat16 g_whi[WTOT];
__device__ __nv_bfloat16 g_wlo[WTOT];

// ---------------- helpers ----------------
__device__ __forceinline__ uint32_t s2u(const void* p) {
    uint32_t a;
    asm("{ .reg .u64 t; cvta.to.shared.u64 t, %1; cvt.u32.u64 %0, t; }" : "=r"(a) : "l"(p));
    return a;
}
__device__ __forceinline__ void cpa16(uint32_t d, const void* s) {
    asm volatile("cp.async.cg.shared.global [%0], [%1], 16;" :: "r"(d), "l"(s));
}
__device__ __forceinline__ uint32_t bf2pack(float x, float y) {
    __nv_bfloat162 t; t.x = __float2bfloat16(x); t.y = __float2bfloat16(y);
    return *(uint32_t*)&t;
}

#define LDSM4(r, a) \
    asm volatile("ldmatrix.sync.aligned.m8n8.x4.shared.b16 {%0,%1,%2,%3}, [%4];" \
        : "=r"((r)[0]), "=r"((r)[1]), "=r"((r)[2]), "=r"((r)[3]) : "r"(a))
#define LDSM4T(r, a) \
    asm volatile("ldmatrix.sync.aligned.m8n8.x4.trans.shared.b16 {%0,%1,%2,%3}, [%4];" \
        : "=r"((r)[0]), "=r"((r)[1]), "=r"((r)[2]), "=r"((r)[3]) : "r"(a))

#define MMA16816(c, a, b0, b1) \
    asm volatile("mma.sync.aligned.m16n8k16.row.col.f32.bf16.bf16.f32 " \
        "{%0,%1,%2,%3}, {%4,%5,%6,%7}, {%8,%9}, {%0,%1,%2,%3};" \
        : "+f"((c)[0]), "+f"((c)[1]), "+f"((c)[2]), "+f"((c)[3]) \
        : "r"((a)[0]), "r"((a)[1]), "r"((a)[2]), "r"((a)[3]), "r"(b0), "r"(b1))

#define MMAF16(c, a, b0, b1) \
    asm volatile("mma.sync.aligned.m16n8k16.row.col.f32.f16.f16.f32 " \
        "{%0,%1,%2,%3}, {%4,%5,%6,%7}, {%8,%9}, {%0,%1,%2,%3};" \
        : "+f"((c)[0]), "+f"((c)[1]), "+f"((c)[2]), "+f"((c)[3]) \
        : "r"((a)[0]), "r"((a)[1]), "r"((a)[2]), "r"((a)[3]), "r"(b0), "r"(b1))

// ---------------- fp32 -> bf16 hi/lo split (plain, contiguous) ----------------
__global__ void __launch_bounds__(256) split_kernel(__nv_bfloat16* __restrict__ hi,
                                                    __nv_bfloat16* __restrict__ lo,
                                                    const float* __restrict__ src,
                                                    float scale, int n4)
{
    int i = blockIdx.x * 256 + threadIdx.x;
    if (i >= n4) return;
    float4 v = ((const float4*)src)[i];
    v.x *= scale; v.y *= scale; v.z *= scale; v.w *= scale;
    float h0f = __bfloat162float(__float2bfloat16(v.x));
    float h1f = __bfloat162float(__float2bfloat16(v.y));
    float h2f = __bfloat162float(__float2bfloat16(v.z));
    float h3f = __bfloat162float(__float2bfloat16(v.w));
    ((uint32_t*)hi)[2 * i + 0] = bf2pack(v.x, v.y);
    ((uint32_t*)hi)[2 * i + 1] = bf2pack(v.z, v.w);
    ((uint32_t*)lo)[2 * i + 0] = bf2pack(v.x - h0f, v.y - h1f);
    ((uint32_t*)lo)[2 * i + 1] = bf2pack(v.z - h2f, v.w - h3f);
}

// strided QKV split: src [NLAYER][512][512] contiguous -> dst layer stride 1536*512
__global__ void __launch_bounds__(256) split_qkv_kernel(__nv_bfloat16* __restrict__ hi,
                                                        __nv_bfloat16* __restrict__ lo,
                                                        const float* __restrict__ src,
                                                        float scale, int region2)
{
    int i = blockIdx.x * 256 + threadIdx.x;     // 262144 float4s total
    float4 v = ((const float4*)src)[i];
    v.x *= scale; v.y *= scale; v.z *= scale; v.w *= scale;
    int l = i >> 16, w = i & 65535;
    int di = l * 393216 + region2 + 2 * w;      // uint32 units
    float h0f = __bfloat162float(__float2bfloat16(v.x));
    float h1f = __bfloat162float(__float2bfloat16(v.y));
    float h2f = __bfloat162float(__float2bfloat16(v.z));
    float h3f = __bfloat162float(__float2bfloat16(v.w));
    ((uint32_t*)hi)[di + 0] = bf2pack(v.x, v.y);
    ((uint32_t*)hi)[di + 1] = bf2pack(v.z, v.w);
    ((uint32_t*)lo)[di + 0] = bf2pack(v.x - h0f, v.y - h1f);
    ((uint32_t*)lo)[di + 1] = bf2pack(v.z - h2f, v.w - h3f);
}

// fp32 -> single fp16 (decoder weights)
__global__ void __launch_bounds__(256) split16_kernel(__half* __restrict__ hi,
                                                      const float* __restrict__ src,
                                                      int n4)
{
    int i = blockIdx.x * 256 + threadIdx.x;
    if (i >= n4) return;
    float4 v = ((const float4*)src)[i];
    __half2 p0 = __floats2half2_rn(v.x, v.y);
    __half2 p1 = __floats2half2_rn(v.z, v.w);
    ((__half2*)hi)[2 * i + 0] = p0;
    ((__half2*)hi)[2 * i + 1] = p1;
}

// ---------------- bf16 mma.sync GEMM: C[M,N] = A[M,K]*W[N,K]^T, 3x split ----------------
// BM=128, BN=256, BK=64; 256 threads; warp grid 2(m)x4(n); warp tile 64x64; 2 stages.
#define TSTRIDE 144
#define A_TILE_B (128 * TSTRIDE)             // 18432
#define B_TILE_B (256 * TSTRIDE)             // 36864
#define STAGE_B (2 * A_TILE_B + 2 * B_TILE_B)   // 110592
#define GEMM_SMEM (2 * STAGE_B)              // 221184
#define OFF_AH 0
#define OFF_AL A_TILE_B
#define OFF_BH (2 * A_TILE_B)
#define OFF_BL (2 * A_TILE_B + B_TILE_B)

template <bool BIAS, bool RELU, bool SPLIT>
__global__ void __launch_bounds__(256) gemm_mma(float* __restrict__ C,
                                                __nv_bfloat16* __restrict__ Oh,
                                                __nv_bfloat16* __restrict__ Ol,
                                                const __nv_bfloat16* __restrict__ Ahi,
                                                const __nv_bfloat16* __restrict__ Alo,
                                                const __nv_bfloat16* __restrict__ Bhi,
                                                const __nv_bfloat16* __restrict__ Blo,
                                                const float* __restrict__ bias,
                                                int M, int N, int K)
{
    extern __shared__ char smem[];
    const uint32_t sb = s2u(smem);
    const int tid = threadIdx.x;
    const int warp = tid >> 5, lane = tid & 31;
    const int bm = blockIdx.y * 128;
    const int bn = blockIdx.x * 256;
    const int warp_m = warp >> 2;
    const int warp_n = warp & 3;
    const int nch = K >> 6;

    const __nv_bfloat16* pAh = Ahi + (size_t)bm * K;
    const __nv_bfloat16* pAl = Alo + (size_t)bm * K;
    const __nv_bfloat16* pBh = Bhi + (size_t)bn * K;
    const __nv_bfloat16* pBl = Blo + (size_t)bn * K;

    auto load_stage = [&](uint32_t st, int k0) {
#pragma unroll
        for (int j = 0; j < 8; j++) {
            int idx = tid + j * 256;
            int arr = idx >> 10;
            int r = (idx >> 3) & 127;
            int seg = idx & 7;
            const __nv_bfloat16* src = arr ? pAl : pAh;
            cpa16(st + arr * A_TILE_B + r * TSTRIDE + seg * 16,
                  src + (size_t)r * K + k0 + seg * 8);
        }
#pragma unroll
        for (int j = 0; j < 16; j++) {
            int idx = tid + j * 256;
            int arr = idx >> 11;
            int r = (idx >> 3) & 255;
            int seg = idx & 7;
            const __nv_bfloat16* src = arr ? pBl : pBh;
            cpa16(st + OFF_BH + arr * B_TILE_B + r * TSTRIDE + seg * 16,
                  src + (size_t)r * K + k0 + seg * 8);
        }
    };

    float acc[4][8][4];
#pragma unroll
    for (int i = 0; i < 4; i++)
#pragma unroll
        for (int j = 0; j < 8; j++)
#pragma unroll
            for (int q = 0; q < 4; q++) acc[i][j][q] = 0.f;

    const int g = lane >> 3, lr = lane & 7;
    const int a_row = lr + (g & 1) * 8;
    const int a_k8 = g >> 1;
    const int b_row = lr + (g >> 1) * 8;
    const int b_k8 = g & 1;

    load_stage(sb, 0);
    asm volatile("cp.async.commit_group;" ::: "memory");

    for (int i = 0; i < nch; i++) {
        const uint32_t st = sb + (i & 1) * STAGE_B;
        __syncthreads();
        if (i + 1 < nch) load_stage(sb + ((i + 1) & 1) * STAGE_B, (i + 1) * 64);
        asm volatile("cp.async.commit_group;" ::: "memory");
        asm volatile("cp.async.wait_group 1;" ::: "memory");
        __syncthreads();

#pragma unroll
        for (int ks = 0; ks < 4; ks++) {
            uint32_t ah[4][4], al[4][4];
#pragma unroll
            for (int mi = 0; mi < 4; mi++) {
                uint32_t aaddr = st + (warp_m * 64 + mi * 16 + a_row) * TSTRIDE +
                                 ks * 32 + a_k8 * 16;
                LDSM4(ah[mi], aaddr + OFF_AH);
                LDSM4(al[mi], aaddr + OFF_AL);
            }
#pragma unroll
            for (int ng = 0; ng < 4; ng++) {
                uint32_t bh[4], bl[4];
                uint32_t baddr = st + (warp_n * 64 + ng * 16 + b_row) * TSTRIDE +
                                 ks * 32 + b_k8 * 16;
                LDSM4(bh, baddr + OFF_BH);
                LDSM4(bl, baddr + OFF_BL);
#pragma unroll
                for (int mi = 0; mi < 4; mi++) {
                    MMA16816(acc[mi][2 * ng], ah[mi], bh[0], bh[1]);
                    MMA16816(acc[mi][2 * ng + 1], ah[mi], bh[2], bh[3]);
                    MMA16816(acc[mi][2 * ng], ah[mi], bl[0], bl[1]);
                    MMA16816(acc[mi][2 * ng + 1], ah[mi], bl[2], bl[3]);
                    MMA16816(acc[mi][2 * ng], al[mi], bh[0], bh[1]);
                    MMA16816(acc[mi][2 * ng + 1], al[mi], bh[2], bh[3]);
                }
            }
        }
    }

    const int tm = lane >> 2, tn = (lane & 3) * 2;
#pragma unroll
    for (int mi = 0; mi < 4; mi++) {
#pragma unroll
        for (int nj = 0; nj < 8; nj++) {
            const float* a4 = acc[mi][nj];
            int row0 = bm + warp_m * 64 + mi * 16 + tm;
            int col = bn + warp_n * 64 + nj * 8 + tn;
            float b0 = 0.f, b1 = 0.f;
            if (BIAS) { b0 = bias[col]; b1 = bias[col + 1]; }
            float v0 = a4[0] + b0, v1 = a4[1] + b1;
            float v2 = a4[2] + b0, v3 = a4[3] + b1;
            if (RELU) {
                v0 = fmaxf(v0, 0.f); v1 = fmaxf(v1, 0.f);
                v2 = fmaxf(v2, 0.f); v3 = fmaxf(v3, 0.f);
            }
            if (SPLIT) {
                uint32_t h0 = bf2pack(v0, v1), h1 = bf2pack(v2, v3);
                __nv_bfloat162 hh0 = *(__nv_bfloat162*)&h0;
                __nv_bfloat162 hh1 = *(__nv_bfloat162*)&h1;
                uint32_t l0p = bf2pack(v0 - __bfloat162float(hh0.x),
                                       v1 - __bfloat162float(hh0.y));
                uint32_t l1p = bf2pack(v2 - __bfloat162float(hh1.x),
                                       v3 - __bfloat162float(hh1.y));
                *(uint32_t*)(Oh + (size_t)row0 * N + col) = h0;
                *(uint32_t*)(Oh + (size_t)(row0 + 8) * N + col) = h1;
                *(uint32_t*)(Ol + (size_t)row0 * N + col) = l0p;
                *(uint32_t*)(Ol + (size_t)(row0 + 8) * N + col) = l1p;
            } else {
                *(float2*)(C + (size_t)row0 * N + col) = make_float2(v0, v1);
                *(float2*)(C + (size_t)(row0 + 8) * N + col) = make_float2(v2, v3);
            }
        }
    }
}

// ---------------- fp16 2-term GEMM (decoder): C = (Ah+Al)*Bh^T + bias ----------------
#define F_STAGE_B (2 * A_TILE_B + B_TILE_B)     // 73728
#define GEMM_SMEM16 (2 * F_STAGE_B)             // 147456
#define OFF16_BH (2 * A_TILE_B)

__global__ void __launch_bounds__(256) gemm_f16(float* __restrict__ C,
                                                const __half* __restrict__ Ahi,
                                                const __half* __restrict__ Alo,
                                                const __half* __restrict__ Bhi,
                                                const float* __restrict__ bias,
                                                int M, int N, int K)
{
    extern __shared__ char smem[];
    const uint32_t sb = s2u(smem);
    const int tid = threadIdx.x;
    const int warp = tid >> 5, lane = tid & 31;
    const int bm = blockIdx.y * 128;
    const int bn = blockIdx.x * 256;
    const int warp_m = warp >> 2;
    const int warp_n = warp & 3;
    const int nch = K >> 6;

    const __half* pAh = Ahi + (size_t)bm * K;
    const __half* pAl = Alo + (size_t)bm * K;
    const __half* pBh = Bhi + (size_t)bn * K;

    auto load_stage = [&](uint32_t st, int k0) {
#pragma unroll
        for (int j = 0; j < 8; j++) {
            int idx = tid + j * 256;
            int arr = idx >> 10;
            int r = (idx >> 3) & 127;
            int seg = idx & 7;
            const __half* src = arr ? pAl : pAh;
            cpa16(st + arr * A_TILE_B + r * TSTRIDE + seg * 16,
                  src + (size_t)r * K + k0 + seg * 8);
        }
#pragma unroll
        for (int j = 0; j < 8; j++) {
            int idx = tid + j * 256;
            int r = (idx >> 3) & 255;
            int seg = idx & 7;
            cpa16(st + OFF16_BH + r * TSTRIDE + seg * 16,
                  pBh + (size_t)r * K + k0 + seg * 8);
        }
    };

    float acc[4][8][4];
#pragma unroll
    for (int i = 0; i < 4; i++)
#pragma unroll
        for (int j = 0; j < 8; j++)
#pragma unroll
            for (int q = 0; q < 4; q++) acc[i][j][q] = 0.f;

    const int g = lane >> 3, lr = lane & 7;
    const int a_row = lr + (g & 1) * 8;
    const int a_k8 = g >> 1;
    const int b_row = lr + (g >> 1) * 8;
    const int b_k8 = g & 1;

    load_stage(sb, 0);
    asm volatile("cp.async.commit_group;" ::: "memory");

    for (int i = 0; i < nch; i++) {
        const uint32_t st = sb + (i & 1) * F_STAGE_B;
        __syncthreads();
        if (i + 1 < nch) load_stage(sb + ((i + 1) & 1) * F_STAGE_B, (i + 1) * 64);
        asm volatile("cp.async.commit_group;" ::: "memory");
        asm volatile("cp.async.wait_group 1;" ::: "memory");
        __syncthreads();

#pragma unroll
        for (int ks = 0; ks < 4; ks++) {
            uint32_t ah[4][4], al[4][4];
#pragma unroll
            for (int mi = 0; mi < 4; mi++) {
                uint32_t aaddr = st + (warp_m * 64 + mi * 16 + a_row) * TSTRIDE +
                                 ks * 32 + a_k8 * 16;
                LDSM4(ah[mi], aaddr + OFF_AH);
                LDSM4(al[mi], aaddr + OFF_AL);
            }
#pragma unroll
            for (int ng = 0; ng < 4; ng++) {
                uint32_t bh[4];
                uint32_t baddr = st + (warp_n * 64 + ng * 16 + b_row) * TSTRIDE +
                                 ks * 32 + b_k8 * 16;
                LDSM4(bh, baddr + OFF16_BH);
#pragma unroll
                for (int mi = 0; mi < 4; mi++) {
                    MMAF16(acc[mi][2 * ng], ah[mi], bh[0], bh[1]);
                    MMAF16(acc[mi][2 * ng + 1], ah[mi], bh[2], bh[3]);
                    MMAF16(acc[mi][2 * ng], al[mi], bh[0], bh[1]);
                    MMAF16(acc[mi][2 * ng + 1], al[mi], bh[2], bh[3]);
                }
            }
        }
    }

    const int tm = lane >> 2, tn = (lane & 3) * 2;
#pragma unroll
    for (int mi = 0; mi < 4; mi++) {
#pragma unroll
        for (int nj = 0; nj < 8; nj++) {
            const float* a4 = acc[mi][nj];
            int row0 = bm + warp_m * 64 + mi * 16 + tm;
            int col = bn + warp_n * 64 + nj * 8 + tn;
            float b0 = bias[col], b1 = bias[col + 1];
            *(float2*)(C + (size_t)row0 * N + col) = make_float2(a4[0] + b0, a4[1] + b1);
            *(float2*)(C + (size_t)(row0 + 8) * N + col) = make_float2(a4[2] + b0, a4[3] + b1);
        }
    }
}

// ---------------- embedding + positional encoding (fp32 + split out) ----------------
__global__ void __launch_bounds__(128) embed_kernel(float* __restrict__ x,
                                                    __nv_bfloat16* __restrict__ xh,
                                                    __nv_bfloat16* __restrict__ xl,
                                                    const int* __restrict__ tok,
                                                    const float* __restrict__ emb)
{
    int m = blockIdx.x;
    int l = m >> 2;
    int t = tok[m];
    const float sq = 22.627416997969522f;
    const double nlog = 9.210340371976184;
#pragma unroll
    for (int j = 0; j < 4; j++) {
        int d = threadIdx.x + j * 128;
        int i = d >> 1;
        float freqf = (float)exp(-(double)(2 * i) * (nlog / 512.0));
        float angf = (float)l * freqf;
        double ang = (double)angf;
        float pe = (d & 1) ? (float)cos(ang) : (float)sin(ang);
        float v = emb[(size_t)t * DMODEL + d] * sq + pe;
        x[(size_t)m * DMODEL + d] = v;
        __nv_bfloat16 h = __float2bfloat16(v);
        xh[(size_t)m * DMODEL + d] = h;
        xl[(size_t)m * DMODEL + d] = __float2bfloat16(v - __bfloat162float(h));
    }
}

// ---------------- mma flash attention (causal, 3x bf16 split), fused-QKV input --------
#define QKVSTR 1536
#define AT_S 144
#define AQ_B (128 * AT_S)
#define AKV_TILE (64 * AT_S)
#define AKV_STAGE (4 * AKV_TILE)
#define ATTN_SMEM (2 * AQ_B + 2 * AKV_STAGE)  // 110592

__global__ void __launch_bounds__(256) attn_mma(
    __nv_bfloat16* __restrict__ ctxh, __nv_bfloat16* __restrict__ ctxl,
    const __nv_bfloat16* __restrict__ qkvh, const __nv_bfloat16* __restrict__ qkvl)
{
    extern __shared__ char smem[];
    const uint32_t sb = s2u(smem);
    const int tid = threadIdx.x, warp = tid >> 5, lane = tid & 31;
    const int bx = blockIdx.x, b = blockIdx.y, h = blockIdx.z;
    const int l0 = bx * 128;
    const int ntiles = 2 * bx + 2;

    const uint32_t sQh = sb, sQl = sb + AQ_B;
    const uint32_t sKV = sb + 2 * AQ_B;

#pragma unroll
    for (int t = 0; t < 8; t++) {
        int idx = tid + t * 256;
        int row = idx >> 4;
        int sub = idx & 15;
        int seg = sub & 7;
        const __nv_bfloat16* src = (sub < 8) ? qkvh : qkvl;
        uint32_t dst = ((sub < 8) ? sQh : sQl) + row * AT_S + seg * 16;
        cpa16(dst, src + ((size_t)(l0 + row) * 4 + b) * QKVSTR + h * 64 + seg * 8);
    }
    asm volatile("cp.async.commit_group;" ::: "memory");

    auto load_kv = [&](int s, int jt) {
        uint32_t st = sKV + s * AKV_STAGE;
#pragma unroll
        for (int t = 0; t < 8; t++) {
            int idx = tid + t * 256;
            int arr = idx >> 9;
            int row = (idx >> 3) & 63;
            int seg = idx & 7;
            const __nv_bfloat16* src = (arr & 1) ? qkvl : qkvh;
            int coff = (arr < 2) ? 512 : 1024;
            cpa16(st + arr * AKV_TILE + row * AT_S + seg * 16,
                  src + ((size_t)(jt * 64 + row) * 4 + b) * QKVSTR + coff + h * 64 + seg * 8);
        }
    };
    load_kv(0, 0);
    asm volatile("cp.async.commit_group;" ::: "memory");

    const int a_row = (lane & 7) + ((lane >> 3) & 1) * 8;
    const int a_k8 = lane >> 4;
    const int b_row = (lane & 7) + (lane >> 4) * 8;
    const int b_k8 = (lane >> 3) & 1;

    uint32_t qfh[4][4], qfl[4][4];
    float ctx[8][4];
#pragma unroll
    for (int i = 0; i < 8; i++)
#pragma unroll
        for (int j = 0; j < 4; j++) ctx[i][j] = 0.f;
    float m0 = -INFINITY, m1 = -INFINITY, l0s = 0.f, l1s = 0.f;

    for (int jt = 0; jt < ntiles; jt++) {
        const uint32_t st = sKV + (jt & 1) * AKV_STAGE;
        __syncthreads();
        if (jt + 1 < ntiles) {
            load_kv((jt + 1) & 1, jt + 1);
            asm volatile("cp.async.commit_group;" ::: "memory");
            asm volatile("cp.async.wait_group 1;" ::: "memory");
        } else {
            asm volatile("cp.async.wait_group 0;" ::: "memory");
        }
        __syncthreads();

        if (jt == 0) {
#pragma unroll
            for (int kb = 0; kb < 4; kb++) {
                uint32_t qa = sQh + (warp * 16 + a_row) * AT_S + (kb * 2 + a_k8) * 16;
                LDSM4(qfh[kb], qa);
                LDSM4(qfl[kb], qa + AQ_B);
            }
        }

        float S[8][4];
#pragma unroll
        for (int i = 0; i < 8; i++)
#pragma unroll
            for (int j = 0; j < 4; j++) S[i][j] = 0.f;
#pragma unroll
        for (int kb = 0; kb < 4; kb++) {
#pragma unroll
            for (int ng = 0; ng < 4; ng++) {
                uint32_t kbh[4], kbl[4];
                uint32_t ka = st + (ng * 16 + b_row) * AT_S + (kb * 2 + b_k8) * 16;
                LDSM4(kbh, ka);
                LDSM4(kbl, ka + AKV_TILE);
                int nb = ng * 2;
                MMA16816(S[nb], qfh[kb], kbh[0], kbh[1]);
                MMA16816(S[nb + 1], qfh[kb], kbh[2], kbh[3]);
                MMA16816(S[nb], qfh[kb], kbl[0], kbl[1]);
                MMA16816(S[nb + 1], qfh[kb], kbl[2], kbl[3]);
                MMA16816(S[nb], qfl[kb], kbh[0], kbh[1]);
                MMA16816(S[nb + 1], qfl[kb], kbh[2], kbh[3]);
            }
        }

        const int qr0 = l0 + warp * 16 + (lane >> 2);
        const int qr1 = qr0 + 8;
        if (jt >= ntiles - 2) {
#pragma unroll
            for (int nb = 0; nb < 8; nb++) {
                int c = jt * 64 + nb * 8 + 2 * (lane & 3);
                if (c > qr0) S[nb][0] = -INFINITY;
                if (c + 1 > qr0) S[nb][1] = -INFINITY;
                if (c > qr1) S[nb][2] = -INFINITY;
                if (c + 1 > qr1) S[nb][3] = -INFINITY;
            }
        }

        float mx0 = -INFINITY, mx1 = -INFINITY;
#pragma unroll
        for (int nb = 0; nb < 8; nb++) {
            mx0 = fmaxf(mx0, fmaxf(S[nb][0], S[nb][1]));
            mx1 = fmaxf(mx1, fmaxf(S[nb][2], S[nb][3]));
        }
        mx0 = fmaxf(mx0, __shfl_xor_sync(0xffffffffu, mx0, 1));
        mx0 = fmaxf(mx0, __shfl_xor_sync(0xffffffffu, mx0, 2));
        mx1 = fmaxf(mx1, __shfl_xor_sync(0xffffffffu, mx1, 1));
        mx1 = fmaxf(mx1, __shfl_xor_sync(0xffffffffu, mx1, 2));
        float nm0 = fmaxf(m0, mx0), nm1 = fmaxf(m1, mx1);
        float c0 = __expf(m0 - nm0), c1 = __expf(m1 - nm1);
        m0 = nm0; m1 = nm1;
        float s0 = 0.f, s1 = 0.f;
#pragma unroll
        for (int nb = 0; nb < 8; nb++) {
            S[nb][0] = __expf(S[nb][0] - nm0);
            S[nb][1] = __expf(S[nb][1] - nm0);
            S[nb][2] = __expf(S[nb][2] - nm1);
            S[nb][3] = __expf(S[nb][3] - nm1);
            s0 += S[nb][0] + S[nb][1];
            s1 += S[nb][2] + S[nb][3];
        }
        s0 += __shfl_xor_sync(0xffffffffu, s0, 1);
        s0 += __shfl_xor_sync(0xffffffffu, s0, 2);
        s1 += __shfl_xor_sync(0xffffffffu, s1, 1);
        s1 += __shfl_xor_sync(0xffffffffu, s1, 2);
        l0s = l0s * c0 + s0;
        l1s = l1s * c1 + s1;
#pragma unroll
        for (int nb = 0; nb < 8; nb++) {
            ctx[nb][0] *= c0; ctx[nb][1] *= c0;
            ctx[nb][2] *= c1; ctx[nb][3] *= c1;
        }

        uint32_t ph[4][4], pl[4][4];
#pragma unroll
        for (int kb = 0; kb < 4; kb++) {
            const float* sA = S[2 * kb];
            const float* sB = S[2 * kb + 1];
            ph[kb][0] = bf2pack(sA[0], sA[1]);
            ph[kb][1] = bf2pack(sA[2], sA[3]);
            ph[kb][2] = bf2pack(sB[0], sB[1]);
            ph[kb][3] = bf2pack(sB[2], sB[3]);
            __nv_bfloat162 t0 = *(__nv_bfloat162*)&ph[kb][0];
            __nv_bfloat162 t1 = *(__nv_bfloat162*)&ph[kb][1];
            __nv_bfloat162 t2 = *(__nv_bfloat162*)&ph[kb][2];
            __nv_bfloat162 t3 = *(__nv_bfloat162*)&ph[kb][3];
            pl[kb][0] = bf2pack(sA[0] - __bfloat162float(t0.x), sA[1] - __bfloat162float(t0.y));
            pl[kb][1] = bf2pack(sA[2] - __bfloat162float(t1.x), sA[3] - __bfloat162float(t1.y));
            pl[kb][2] = bf2pack(sB[0] - __bfloat162float(t2.x), sB[1] - __bfloat162float(t2.y));
            pl[kb][3] = bf2pack(sB[2] - __bfloat162float(t3.x), sB[3] - __bfloat162float(t3.y));
        }

        const uint32_t vrow = (lane & 7) + ((lane >> 3) & 1) * 8;
        const uint32_t vcol16 = (lane >> 4) * 16;
#pragma unroll
        for (int kb = 0; kb < 4; kb++) {
#pragma unroll
            for (int ngd = 0; ngd < 4; ngd++) {
                uint32_t vbh[4], vbl[4];
                uint32_t va = st + 2 * AKV_TILE + (kb * 16 + vrow) * AT_S + ngd * 32 + vcol16;
                LDSM4T(vbh, va);
                LDSM4T(vbl, va + AKV_TILE);
                int nd = ngd * 2;
                MMA16816(ctx[nd], ph[kb], vbh[0], vbh[1]);
                MMA16816(ctx[nd + 1], ph[kb], vbh[2], vbh[3]);
                MMA16816(ctx[nd], ph[kb], vbl[0], vbl[1]);
                MMA16816(ctx[nd + 1], ph[kb], vbl[2], vbl[3]);
                MMA16816(ctx[nd], pl[kb], vbh[0], vbh[1]);
                MMA16816(ctx[nd + 1], pl[kb], vbh[2], vbh[3]);
            }
        }
    }

    float inv0 = 1.f / l0s, inv1 = 1.f / l1s;
    const size_t mg0 = (size_t)(l0 + warp * 16 + (lane >> 2)) * 4 + b;
    const size_t mg1 = mg0 + 32;
#pragma unroll
    for (int nd = 0; nd < 8; nd++) {
        int col = h * 64 + nd * 8 + 2 * (lane & 3);
        float v0 = ctx[nd][0] * inv0, v1 = ctx[nd][1] * inv0;
        float v2 = ctx[nd][2] * inv1, v3 = ctx[nd][3] * inv1;
        uint32_t h0 = bf2pack(v0, v1), h1 = bf2pack(v2, v3);
        __nv_bfloat162 hh0 = *(__nv_bfloat162*)&h0;
        __nv_bfloat162 hh1 = *(__nv_bfloat162*)&h1;
        uint32_t l0p = bf2pack(v0 - __bfloat162float(hh0.x), v1 - __bfloat162float(hh0.y));
        uint32_t l1p = bf2pack(v2 - __bfloat162float(hh1.x), v3 - __bfloat162float(hh1.y));
        *(uint32_t*)(ctxh + mg0 * 512 + col) = h0;
        *(uint32_t*)(ctxh + mg1 * 512 + col) = h1;
        *(uint32_t*)(ctxl + mg0 * 512 + col) = l0p;
        *(uint32_t*)(ctxl + mg1 * 512 + col) = l1p;
    }
}

// ---------------- fused residual-add + LayerNorm (+ optional final LN, split out) ----
// fp16out != 0: write fp16 hi/lo split (for decoder) instead of bf16.
__global__ void __launch_bounds__(128) add_ln_kernel(float* __restrict__ x,
                                                     __nv_bfloat16* __restrict__ xh,
                                                     __nv_bfloat16* __restrict__ xl,
                                                     const float* __restrict__ y,
                                                     const float* __restrict__ a,
                                                     const float* __restrict__ b,
                                                     const float* __restrict__ fa,
                                                     const float* __restrict__ fb,
                                                     int fp16out)
{
    const int m = blockIdx.x;
    const int tid = threadIdx.x;
    const size_t base = (size_t)m * DMODEL;
    __shared__ float red[8];

    float v[4];
#pragma unroll
    for (int j = 0; j < 4; j++) {
        int d = tid + j * 128;
        float xv = x[base + d];
        if (y) xv += y[base + d];
        v[j] = xv;
    }
    float s = v[0] + v[1] + v[2] + v[3];
#pragma unroll
    for (int o = 16; o > 0; o >>= 1) s += __shfl_xor_sync(0xffffffffu, s, o);
    if ((tid & 31) == 0) red[tid >> 5] = s;
    __syncthreads();
    float mean = (red[0] + red[1] + red[2] + red[3]) * (1.f / 512.f);

    float ss = 0.f;
#pragma unroll
    for (int j = 0; j < 4; j++) {
        float dm = v[j] - mean;
        ss += dm * dm;
    }
#pragma unroll
    for (int o = 16; o > 0; o >>= 1) ss += __shfl_xor_sync(0xffffffffu, ss, o);
    if ((tid & 31) == 0) red[4 + (tid >> 5)] = ss;
    __syncthreads();
    float var = (red[4] + red[5] + red[6] + red[7]) * (1.f / 511.f);
    float inv = 1.f / (sqrtf(var) + 1e-6f);

    float o4[4];
#pragma unroll
    for (int j = 0; j < 4; j++) {
        int d = tid + j * 128;
        o4[j] = a[d] * (v[j] - mean) * inv + b[d];
    }

    if (fa) {
        __syncthreads();
        float s2 = o4[0] + o4[1] + o4[2] + o4[3];
#pragma unroll
        for (int o = 16; o > 0; o >>= 1) s2 += __shfl_xor_sync(0xffffffffu, s2, o);
        if ((tid & 31) == 0) red[tid >> 5] = s2;
        __syncthreads();
        float mean2 = (red[0] + red[1] + red[2] + red[3]) * (1.f / 512.f);
        float ss2 = 0.f;
#pragma unroll
        for (int j = 0; j < 4; j++) {
            float dm = o4[j] - mean2;
            ss2 += dm * dm;
        }
#pragma unroll
        for (int o = 16; o > 0; o >>= 1) ss2 += __shfl_xor_sync(0xffffffffu, ss2, o);
        if ((tid & 31) == 0) red[4 + (tid >> 5)] = ss2;
        __syncthreads();
        float var2 = (red[4] + red[5] + red[6] + red[7]) * (1.f / 511.f);
        float inv2 = 1.f / (sqrtf(var2) + 1e-6f);
#pragma unroll
        for (int j = 0; j < 4; j++) {
            int d = tid + j * 128;
            o4[j] = fa[d] * (o4[j] - mean2) * inv2 + fb[d];
        }
    }

#pragma unroll
    for (int j = 0; j < 4; j++) {
        int d = tid + j * 128;
        float o = o4[j];
        x[base + d] = o;
        if (fp16out) {
            __half h = __float2half(o);
            ((__half*)xh)[base + d] = h;
            ((__half*)xl)[base + d] = __float2half(o - __half2float(h));
        } else {
            __nv_bfloat16 h = __float2bfloat16(o);
            xh[base + d] = h;
            xl[base + d] = __float2bfloat16(o - __bfloat162float(h));
        }
    }
}

// ---------------- orchestration ----------------
extern "C" void kernel_launch(void* const* d_in, const int* in_sizes, int n_in,
                              void* d_out, int out_size)
{
    (void)in_sizes; (void)n_in; (void)out_size;
    const int*   input = (const int*)  d_in[0];
    const float* emb   = (const float*)d_in[1];
    const float* Wq    = (const float*)d_in[2];
    const float* Wk    = (const float*)d_in[3];
    const float* Wv    = (const float*)d_in[4];
    const float* Wo    = (const float*)d_in[5];
    const float* w1    = (const float*)d_in[6];
    const float* b1    = (const float*)d_in[7];
    const float* w2    = (const float*)d_in[8];
    const float* b2    = (const float*)d_in[9];
    const float* ln1a  = (const float*)d_in[10];
    const float* ln1b  = (const float*)d_in[11];
    const float* ln2a  = (const float*)d_in[12];
    const float* ln2b  = (const float*)d_in[13];
    const float* fna   = (const float*)d_in[14];
    const float* fnb   = (const float*)d_in[15];
    const float* decW  = (const float*)d_in[16];
    const float* decb  = (const float*)d_in[17];
    float* out = (float*)d_out;

    float *x, *t;
    __nv_bfloat16 *xs, *qkvs, *cs, *ahi, *alo, *whi, *wlo;
    cudaGetSymbolAddress((void**)&x,    g_x);
    cudaGetSymbolAddress((void**)&t,    g_t);
    cudaGetSymbolAddress((void**)&xs,   g_xs);
    cudaGetSymbolAddress((void**)&qkvs, g_qkvs);
    cudaGetSymbolAddress((void**)&cs,   g_cs);
    cudaGetSymbolAddress((void**)&ahi,  g_ahi);
    cudaGetSymbolAddress((void**)&alo,  g_alo);
    cudaGetSymbolAddress((void**)&whi,  g_whi);
    cudaGetSymbolAddress((void**)&wlo,  g_wlo);

    const int AS = MROWS * DMODEL;
    const int QAS = MROWS * 3 * DMODEL;
    __nv_bfloat16 *xh = xs, *xl = xs + AS;
    __nv_bfloat16 *qkvh = qkvs, *qkvl = qkvs + QAS;
    __nv_bfloat16 *ch = cs, *cl = cs + AS;
    __half* wd16 = (__half*)(whi + WD0);

    cudaFuncSetAttribute(attn_mma, cudaFuncAttributeMaxDynamicSharedMemorySize, ATTN_SMEM);
    cudaFuncSetAttribute(gemm_mma<false, false, true>,  cudaFuncAttributeMaxDynamicSharedMemorySize, GEMM_SMEM);
    cudaFuncSetAttribute(gemm_mma<false, false, false>, cudaFuncAttributeMaxDynamicSharedMemorySize, GEMM_SMEM);
    cudaFuncSetAttribute(gemm_mma<true, true, true>,    cudaFuncAttributeMaxDynamicSharedMemorySize, GEMM_SMEM);
    cudaFuncSetAttribute(gemm_mma<true, false, false>,  cudaFuncAttributeMaxDynamicSharedMemorySize, GEMM_SMEM);
    cudaFuncSetAttribute(gemm_f16, cudaFuncAttributeMaxDynamicSharedMemorySize, GEMM_SMEM16);

    // weight splits: fused QKV (strided over all layers; q scaled 1/8), Wo/w1/w2 bf16,
    // decoder fp16 single.
    split_qkv_kernel<<<1024, 256>>>(whi + WQKV0, wlo + WQKV0, Wq, 0.125f, 0);
    split_qkv_kernel<<<1024, 256>>>(whi + WQKV0, wlo + WQKV0, Wk, 1.0f, 131072);
    split_qkv_kernel<<<1024, 256>>>(whi + WQKV0, wlo + WQKV0, Wv, 1.0f, 262144);
    split_kernel<<<1024, 256>>>(whi + WO0, wlo + WO0, Wo, 1.0f, 1048576 / 4);
    split_kernel<<<4096, 256>>>(whi + W10, wlo + W10, w1, 1.0f, 4194304 / 4);
    split_kernel<<<4096, 256>>>(whi + W20, wlo + W20, w2, 1.0f, 4194304 / 4);
    split16_kernel<<<16000, 256>>>(wd16, decW, 16384000 / 4);

    embed_kernel<<<MROWS, 128>>>(x, xh, xl, input, emb);

    const dim3 gQKV(3 * DMODEL / 256, MROWS / 128);  // (6, 64)
    const dim3 gD(DMODEL / 256, MROWS / 128);        // (2, 64)
    const dim3 gF(DFFN / 256, MROWS / 128);          // (8, 64)
    const dim3 gV(NVOCAB / 256, MROWS / 128);        // (125, 64)
    const dim3 gAttn(LSEQ / 128, BATCH, NHEAD);

    for (int l = 0; l < NLAYER; l++) {
        const size_t qofs = (size_t)l * 1536 * 512;
        const size_t wofs = (size_t)l * DMODEL * DMODEL;
        const size_t f1 = (size_t)l * DFFN * DMODEL;
        const bool last = (l == NLAYER - 1);

        gemm_mma<false, false, true><<<gQKV, 256, GEMM_SMEM>>>(
            nullptr, qkvh, qkvl, xh, xl, whi + WQKV0 + qofs, wlo + WQKV0 + qofs,
            nullptr, MROWS, 3 * DMODEL, DMODEL);

        attn_mma<<<gAttn, 256, ATTN_SMEM>>>(ch, cl, qkvh, qkvl);

        gemm_mma<false, false, false><<<gD, 256, GEMM_SMEM>>>(
            t, nullptr, nullptr, ch, cl, whi + WO0 + wofs, wlo + WO0 + wofs,
            nullptr, MROWS, DMODEL, DMODEL);
        add_ln_kernel<<<MROWS, 128>>>(x, xh, xl, t, ln1a + l * DMODEL, ln1b + l * DMODEL,
                                      nullptr, nullptr, 0);

        gemm_mma<true, true, true><<<gF, 256, GEMM_SMEM>>>(
            nullptr, ahi, alo, xh, xl, whi + W10 + f1, wlo + W10 + f1,
            b1 + l * DFFN, MROWS, DFFN, DMODEL);
        gemm_mma<true, false, false><<<gD, 256, GEMM_SMEM>>>(
            t, nullptr, nullptr, ahi, alo, whi + W20 + f1, wlo + W20 + f1,
            b2 + l * DMODEL, MROWS, DMODEL, DFFN);
        add_ln_kernel<<<MROWS, 128>>>(x, xh, xl, t, ln2a + l * DMODEL, ln2b + l * DMODEL,
                                      last ? fna : nullptr, last ? fnb : nullptr,
                                      last ? 1 : 0);
    }

    gemm_f16<<<gV, 256, GEMM_SMEM16>>>(
        out, (const __half*)xh, (const __half*)xl, wd16,
        decb, MROWS, NVOCAB, DMODEL);
}

// round 8
// speedup vs baseline: 4.0773x; 1.1177x over previous
#include <cuda_runtime.h>
#include <cuda_bf16.h>
#include <cuda_fp16.h>
#include <math.h>
#include <stdint.h>

#define LSEQ 2048
#define BATCH 4
#define DMODEL 512
#define NHEAD 8
#define DKH 64
#define NLAYER 4
#define DFFN 2048
#define MROWS (LSEQ * BATCH)   // 8192
#define NVOCAB 32000

// ---------------- scratch (device globals; no allocation allowed) ----------------
__device__ float g_x[MROWS * DMODEL];
__device__ float g_t[MROWS * DMODEL];
__device__ __nv_bfloat16 g_xs[2 * MROWS * DMODEL];          // x16 fp16 (half used)
__device__ __nv_bfloat16 g_qkvs[2 * MROWS * 3 * DMODEL];    // fused qkv bf16 hi/lo
__device__ __nv_bfloat16 g_cs[2 * MROWS * DMODEL];          // ctx16 fp16 (half used)
__device__ __nv_bfloat16 g_ahi[MROWS * DFFN];               // ff fp16
__device__ __nv_bfloat16 g_alo[MROWS * DFFN];               // unused spare

// weight storage (fp16 hi/lo), element offsets:
#define WQKV0 0                 // fused [NLAYER][1536][512]
#define WO0 3145728
#define W10 4194304
#define W20 8388608
#define WD0 12582912
#define WTOT 28966912
__device__ __nv_bfloat16 g_whi[WTOT];
__device__ __nv_bfloat16 g_wlo[WTOT];

// ---------------- helpers ----------------
__device__ __forceinline__ uint32_t s2u(const void* p) {
    uint32_t a;
    asm("{ .reg .u64 t; cvta.to.shared.u64 t, %1; cvt.u32.u64 %0, t; }" : "=r"(a) : "l"(p));
    return a;
}
__device__ __forceinline__ void cpa16(uint32_t d, const void* s) {
    asm volatile("cp.async.cg.shared.global [%0], [%1], 16;" :: "r"(d), "l"(s));
}
__device__ __forceinline__ uint32_t bf2pack(float x, float y) {
    __nv_bfloat162 t; t.x = __float2bfloat16(x); t.y = __float2bfloat16(y);
    return *(uint32_t*)&t;
}
__device__ __forceinline__ uint32_t h2pack(float x, float y) {
    __half2 t = __floats2half2_rn(x, y);
    return *(uint32_t*)&t;
}

#define LDSM4(r, a) \
    asm volatile("ldmatrix.sync.aligned.m8n8.x4.shared.b16 {%0,%1,%2,%3}, [%4];" \
        : "=r"((r)[0]), "=r"((r)[1]), "=r"((r)[2]), "=r"((r)[3]) : "r"(a))
#define LDSM4T(r, a) \
    asm volatile("ldmatrix.sync.aligned.m8n8.x4.trans.shared.b16 {%0,%1,%2,%3}, [%4];" \
        : "=r"((r)[0]), "=r"((r)[1]), "=r"((r)[2]), "=r"((r)[3]) : "r"(a))

#define MMA16816(c, a, b0, b1) \
    asm volatile("mma.sync.aligned.m16n8k16.row.col.f32.bf16.bf16.f32 " \
        "{%0,%1,%2,%3}, {%4,%5,%6,%7}, {%8,%9}, {%0,%1,%2,%3};" \
        : "+f"((c)[0]), "+f"((c)[1]), "+f"((c)[2]), "+f"((c)[3]) \
        : "r"((a)[0]), "r"((a)[1]), "r"((a)[2]), "r"((a)[3]), "r"(b0), "r"(b1))

#define MMAF16(c, a, b0, b1) \
    asm volatile("mma.sync.aligned.m16n8k16.row.col.f32.f16.f16.f32 " \
        "{%0,%1,%2,%3}, {%4,%5,%6,%7}, {%8,%9}, {%0,%1,%2,%3};" \
        : "+f"((c)[0]), "+f"((c)[1]), "+f"((c)[2]), "+f"((c)[3]) \
        : "r"((a)[0]), "r"((a)[1]), "r"((a)[2]), "r"((a)[3]), "r"(b0), "r"(b1))

// ---------------- fp32 -> fp16 hi/lo weight splits ----------------
__global__ void __launch_bounds__(256) split16_2(__half* __restrict__ hi,
                                                 __half* __restrict__ lo,
                                                 const float* __restrict__ src,
                                                 int n4)
{
    int i = blockIdx.x * 256 + threadIdx.x;
    if (i >= n4) return;
    float4 v = ((const float4*)src)[i];
    __half h0 = __float2half(v.x), h1 = __float2half(v.y);
    __half h2 = __float2half(v.z), h3 = __float2half(v.w);
    ((uint32_t*)hi)[2 * i + 0] = h2pack(v.x, v.y);
    ((uint32_t*)hi)[2 * i + 1] = h2pack(v.z, v.w);
    ((uint32_t*)lo)[2 * i + 0] = h2pack(v.x - __half2float(h0), v.y - __half2float(h1));
    ((uint32_t*)lo)[2 * i + 1] = h2pack(v.z - __half2float(h2), v.w - __half2float(h3));
}

// strided QKV split: src [NLAYER][512][512] -> dst layer stride 1536*512
__global__ void __launch_bounds__(256) split_qkv16(__half* __restrict__ hi,
                                                   __half* __restrict__ lo,
                                                   const float* __restrict__ src,
                                                   float scale, int region2)
{
    int i = blockIdx.x * 256 + threadIdx.x;     // 262144 float4s total
    float4 v = ((const float4*)src)[i];
    v.x *= scale; v.y *= scale; v.z *= scale; v.w *= scale;
    int l = i >> 16, w = i & 65535;
    int di = l * 393216 + region2 + 2 * w;      // uint32 units
    __half h0 = __float2half(v.x), h1 = __float2half(v.y);
    __half h2 = __float2half(v.z), h3 = __float2half(v.w);
    ((uint32_t*)hi)[di + 0] = h2pack(v.x, v.y);
    ((uint32_t*)hi)[di + 1] = h2pack(v.z, v.w);
    ((uint32_t*)lo)[di + 0] = h2pack(v.x - __half2float(h0), v.y - __half2float(h1));
    ((uint32_t*)lo)[di + 1] = h2pack(v.z - __half2float(h2), v.w - __half2float(h3));
}

// ---------------- fp16 2-term GEMM: C = A * (Bh+Bl)^T (+bias,+relu) ----------------
// BM=128, BN=256, BK=64; 256 threads; warp 64x64; double buffered.
// OUTM: 0 = fp32 C, 1 = fp16 O16, 2 = bf16 hi/lo split (Oh/Ol)
#define TSTRIDE 144
#define T2_A_TILE (128 * TSTRIDE)               // 18432
#define T2_B_TILE (256 * TSTRIDE)               // 36864
#define T2_STAGE (T2_A_TILE + 2 * T2_B_TILE)    // 92160
#define GEMM2_SMEM (2 * T2_STAGE)               // 184320
#define OFF2_BH T2_A_TILE
#define OFF2_BL (T2_A_TILE + T2_B_TILE)

template <bool BIAS, bool RELU, int OUTM>
__global__ void __launch_bounds__(256) gemm_2t(float* __restrict__ C,
                                               __half* __restrict__ O16,
                                               __nv_bfloat16* __restrict__ Oh,
                                               __nv_bfloat16* __restrict__ Ol,
                                               const __half* __restrict__ A,
                                               const __half* __restrict__ Bh,
                                               const __half* __restrict__ Bl,
                                               const float* __restrict__ bias,
                                               int M, int N, int K)
{
    extern __shared__ char smem[];
    const uint32_t sb = s2u(smem);
    const int tid = threadIdx.x;
    const int warp = tid >> 5, lane = tid & 31;
    const int bm = blockIdx.y * 128;
    const int bn = blockIdx.x * 256;
    const int warp_m = warp >> 2;
    const int warp_n = warp & 3;
    const int nch = K >> 6;

    const __half* pA = A + (size_t)bm * K;
    const __half* pBh = Bh + (size_t)bn * K;
    const __half* pBl = Bl + (size_t)bn * K;

    auto load_stage = [&](uint32_t st, int k0) {
#pragma unroll
        for (int j = 0; j < 4; j++) {
            int idx = tid + j * 256;
            int r = idx >> 3, seg = idx & 7;
            cpa16(st + r * TSTRIDE + seg * 16, pA + (size_t)r * K + k0 + seg * 8);
        }
#pragma unroll
        for (int j = 0; j < 16; j++) {
            int idx = tid + j * 256;
            int arr = idx >> 11;
            int r = (idx >> 3) & 255, seg = idx & 7;
            const __half* src = arr ? pBl : pBh;
            cpa16(st + OFF2_BH + arr * T2_B_TILE + r * TSTRIDE + seg * 16,
                  src + (size_t)r * K + k0 + seg * 8);
        }
    };

    float acc[4][8][4];
#pragma unroll
    for (int i = 0; i < 4; i++)
#pragma unroll
        for (int j = 0; j < 8; j++)
#pragma unroll
            for (int q = 0; q < 4; q++) acc[i][j][q] = 0.f;

    const int g = lane >> 3, lr = lane & 7;
    const int a_row = lr + (g & 1) * 8;
    const int a_k8 = g >> 1;
    const int b_row = lr + (g >> 1) * 8;
    const int b_k8 = g & 1;

    load_stage(sb, 0);
    asm volatile("cp.async.commit_group;" ::: "memory");

    for (int i = 0; i < nch; i++) {
        const uint32_t st = sb + (i & 1) * T2_STAGE;
        __syncthreads();
        if (i + 1 < nch) load_stage(sb + ((i + 1) & 1) * T2_STAGE, (i + 1) * 64);
        asm volatile("cp.async.commit_group;" ::: "memory");
        asm volatile("cp.async.wait_group 1;" ::: "memory");
        __syncthreads();

#pragma unroll
        for (int ks = 0; ks < 4; ks++) {
            uint32_t ah[4][4];
#pragma unroll
            for (int mi = 0; mi < 4; mi++) {
                uint32_t aaddr = st + (warp_m * 64 + mi * 16 + a_row) * TSTRIDE +
                                 ks * 32 + a_k8 * 16;
                LDSM4(ah[mi], aaddr);
            }
#pragma unroll
            for (int ng = 0; ng < 4; ng++) {
                uint32_t bh[4], bl[4];
                uint32_t baddr = st + (warp_n * 64 + ng * 16 + b_row) * TSTRIDE +
                                 ks * 32 + b_k8 * 16;
                LDSM4(bh, baddr + OFF2_BH);
                LDSM4(bl, baddr + OFF2_BL);
#pragma unroll
                for (int mi = 0; mi < 4; mi++) {
                    MMAF16(acc[mi][2 * ng], ah[mi], bh[0], bh[1]);
                    MMAF16(acc[mi][2 * ng + 1], ah[mi], bh[2], bh[3]);
                    MMAF16(acc[mi][2 * ng], ah[mi], bl[0], bl[1]);
                    MMAF16(acc[mi][2 * ng + 1], ah[mi], bl[2], bl[3]);
                }
            }
        }
    }

    const int tm = lane >> 2, tn = (lane & 3) * 2;
#pragma unroll
    for (int mi = 0; mi < 4; mi++) {
#pragma unroll
        for (int nj = 0; nj < 8; nj++) {
            const float* a4 = acc[mi][nj];
            int row0 = bm + warp_m * 64 + mi * 16 + tm;
            int col = bn + warp_n * 64 + nj * 8 + tn;
            float b0 = 0.f, b1 = 0.f;
            if (BIAS) { b0 = bias[col]; b1 = bias[col + 1]; }
            float v0 = a4[0] + b0, v1 = a4[1] + b1;
            float v2 = a4[2] + b0, v3 = a4[3] + b1;
            if (RELU) {
                v0 = fmaxf(v0, 0.f); v1 = fmaxf(v1, 0.f);
                v2 = fmaxf(v2, 0.f); v3 = fmaxf(v3, 0.f);
            }
            if (OUTM == 0) {
                *(float2*)(C + (size_t)row0 * N + col) = make_float2(v0, v1);
                *(float2*)(C + (size_t)(row0 + 8) * N + col) = make_float2(v2, v3);
            } else if (OUTM == 1) {
                *(uint32_t*)(O16 + (size_t)row0 * N + col) = h2pack(v0, v1);
                *(uint32_t*)(O16 + (size_t)(row0 + 8) * N + col) = h2pack(v2, v3);
            } else {
                uint32_t h0 = bf2pack(v0, v1), h1 = bf2pack(v2, v3);
                __nv_bfloat162 hh0 = *(__nv_bfloat162*)&h0;
                __nv_bfloat162 hh1 = *(__nv_bfloat162*)&h1;
                uint32_t l0p = bf2pack(v0 - __bfloat162float(hh0.x),
                                       v1 - __bfloat162float(hh0.y));
                uint32_t l1p = bf2pack(v2 - __bfloat162float(hh1.x),
                                       v3 - __bfloat162float(hh1.y));
                *(uint32_t*)(Oh + (size_t)row0 * N + col) = h0;
                *(uint32_t*)(Oh + (size_t)(row0 + 8) * N + col) = h1;
                *(uint32_t*)(Ol + (size_t)row0 * N + col) = l0p;
                *(uint32_t*)(Ol + (size_t)(row0 + 8) * N + col) = l1p;
            }
        }
    }
}

// ---------------- embedding + positional encoding (fp32 + fp16 out) ----------------
__global__ void __launch_bounds__(128) embed_kernel(float* __restrict__ x,
                                                    __half* __restrict__ x16,
                                                    const int* __restrict__ tok,
                                                    const float* __restrict__ emb)
{
    int m = blockIdx.x;
    int l = m >> 2;
    int t = tok[m];
    const float sq = 22.627416997969522f;
    const double nlog = 9.210340371976184;
#pragma unroll
    for (int j = 0; j < 4; j++) {
        int d = threadIdx.x + j * 128;
        int i = d >> 1;
        float freqf = (float)exp(-(double)(2 * i) * (nlog / 512.0));
        float angf = (float)l * freqf;
        double ang = (double)angf;
        float pe = (d & 1) ? (float)cos(ang) : (float)sin(ang);
        float v = emb[(size_t)t * DMODEL + d] * sq + pe;
        x[(size_t)m * DMODEL + d] = v;
        x16[(size_t)m * DMODEL + d] = __float2half(v);
    }
}

// ---------------- mma flash attention (causal, 3x bf16 split), fused-QKV input --------
#define QKVSTR 1536
#define AT_S 144
#define AQ_B (128 * AT_S)
#define AKV_TILE (64 * AT_S)
#define AKV_STAGE (4 * AKV_TILE)
#define ATTN_SMEM (2 * AQ_B + 2 * AKV_STAGE)  // 110592

__global__ void __launch_bounds__(256) attn_mma(
    __half* __restrict__ ctx16,
    const __nv_bfloat16* __restrict__ qkvh, const __nv_bfloat16* __restrict__ qkvl)
{
    extern __shared__ char smem[];
    const uint32_t sb = s2u(smem);
    const int tid = threadIdx.x, warp = tid >> 5, lane = tid & 31;
    const int bx = blockIdx.x, b = blockIdx.y, h = blockIdx.z;
    const int l0 = bx * 128;
    const int ntiles = 2 * bx + 2;

    const uint32_t sQh = sb, sQl = sb + AQ_B;
    const uint32_t sKV = sb + 2 * AQ_B;

#pragma unroll
    for (int t = 0; t < 8; t++) {
        int idx = tid + t * 256;
        int row = idx >> 4;
        int sub = idx & 15;
        int seg = sub & 7;
        const __nv_bfloat16* src = (sub < 8) ? qkvh : qkvl;
        uint32_t dst = ((sub < 8) ? sQh : sQl) + row * AT_S + seg * 16;
        cpa16(dst, src + ((size_t)(l0 + row) * 4 + b) * QKVSTR + h * 64 + seg * 8);
    }
    asm volatile("cp.async.commit_group;" ::: "memory");

    auto load_kv = [&](int s, int jt) {
        uint32_t st = sKV + s * AKV_STAGE;
#pragma unroll
        for (int t = 0; t < 8; t++) {
            int idx = tid + t * 256;
            int arr = idx >> 9;
            int row = (idx >> 3) & 63;
            int seg = idx & 7;
            const __nv_bfloat16* src = (arr & 1) ? qkvl : qkvh;
            int coff = (arr < 2) ? 512 : 1024;
            cpa16(st + arr * AKV_TILE + row * AT_S + seg * 16,
                  src + ((size_t)(jt * 64 + row) * 4 + b) * QKVSTR + coff + h * 64 + seg * 8);
        }
    };
    load_kv(0, 0);
    asm volatile("cp.async.commit_group;" ::: "memory");

    const int a_row = (lane & 7) + ((lane >> 3) & 1) * 8;
    const int a_k8 = lane >> 4;
    const int b_row = (lane & 7) + (lane >> 4) * 8;
    const int b_k8 = (lane >> 3) & 1;

    uint32_t qfh[4][4], qfl[4][4];
    float ctx[8][4];
#pragma unroll
    for (int i = 0; i < 8; i++)
#pragma unroll
        for (int j = 0; j < 4; j++) ctx[i][j] = 0.f;
    float m0 = -INFINITY, m1 = -INFINITY, l0s = 0.f, l1s = 0.f;

    for (int jt = 0; jt < ntiles; jt++) {
        const uint32_t st = sKV + (jt & 1) * AKV_STAGE;
        __syncthreads();
        if (jt + 1 < ntiles) {
            load_kv((jt + 1) & 1, jt + 1);
            asm volatile("cp.async.commit_group;" ::: "memory");
            asm volatile("cp.async.wait_group 1;" ::: "memory");
        } else {
            asm volatile("cp.async.wait_group 0;" ::: "memory");
        }
        __syncthreads();

        if (jt == 0) {
#pragma unroll
            for (int kb = 0; kb < 4; kb++) {
                uint32_t qa = sQh + (warp * 16 + a_row) * AT_S + (kb * 2 + a_k8) * 16;
                LDSM4(qfh[kb], qa);
                LDSM4(qfl[kb], qa + AQ_B);
            }
        }

        float S[8][4];
#pragma unroll
        for (int i = 0; i < 8; i++)
#pragma unroll
            for (int j = 0; j < 4; j++) S[i][j] = 0.f;
#pragma unroll
        for (int kb = 0; kb < 4; kb++) {
#pragma unroll
            for (int ng = 0; ng < 4; ng++) {
                uint32_t kbh[4], kbl[4];
                uint32_t ka = st + (ng * 16 + b_row) * AT_S + (kb * 2 + b_k8) * 16;
                LDSM4(kbh, ka);
                LDSM4(kbl, ka + AKV_TILE);
                int nb = ng * 2;
                MMA16816(S[nb], qfh[kb], kbh[0], kbh[1]);
                MMA16816(S[nb + 1], qfh[kb], kbh[2], kbh[3]);
                MMA16816(S[nb], qfh[kb], kbl[0], kbl[1]);
                MMA16816(S[nb + 1], qfh[kb], kbl[2], kbl[3]);
                MMA16816(S[nb], qfl[kb], kbh[0], kbh[1]);
                MMA16816(S[nb + 1], qfl[kb], kbh[2], kbh[3]);
            }
        }

        const int qr0 = l0 + warp * 16 + (lane >> 2);
        const int qr1 = qr0 + 8;
        if (jt >= ntiles - 2) {
#pragma unroll
            for (int nb = 0; nb < 8; nb++) {
                int c = jt * 64 + nb * 8 + 2 * (lane & 3);
                if (c > qr0) S[nb][0] = -INFINITY;
                if (c + 1 > qr0) S[nb][1] = -INFINITY;
                if (c > qr1) S[nb][2] = -INFINITY;
                if (c + 1 > qr1) S[nb][3] = -INFINITY;
            }
        }

        float mx0 = -INFINITY, mx1 = -INFINITY;
#pragma unroll
        for (int nb = 0; nb < 8; nb++) {
            mx0 = fmaxf(mx0, fmaxf(S[nb][0], S[nb][1]));
            mx1 = fmaxf(mx1, fmaxf(S[nb][2], S[nb][3]));
        }
        mx0 = fmaxf(mx0, __shfl_xor_sync(0xffffffffu, mx0, 1));
        mx0 = fmaxf(mx0, __shfl_xor_sync(0xffffffffu, mx0, 2));
        mx1 = fmaxf(mx1, __shfl_xor_sync(0xffffffffu, mx1, 1));
        mx1 = fmaxf(mx1, __shfl_xor_sync(0xffffffffu, mx1, 2));
        float nm0 = fmaxf(m0, mx0), nm1 = fmaxf(m1, mx1);
        float c0 = __expf(m0 - nm0), c1 = __expf(m1 - nm1);
        m0 = nm0; m1 = nm1;
        float s0 = 0.f, s1 = 0.f;
#pragma unroll
        for (int nb = 0; nb < 8; nb++) {
            S[nb][0] = __expf(S[nb][0] - nm0);
            S[nb][1] = __expf(S[nb][1] - nm0);
            S[nb][2] = __expf(S[nb][2] - nm1);
            S[nb][3] = __expf(S[nb][3] - nm1);
            s0 += S[nb][0] + S[nb][1];
            s1 += S[nb][2] + S[nb][3];
        }
        s0 += __shfl_xor_sync(0xffffffffu, s0, 1);
        s0 += __shfl_xor_sync(0xffffffffu, s0, 2);
        s1 += __shfl_xor_sync(0xffffffffu, s1, 1);
        s1 += __shfl_xor_sync(0xffffffffu, s1, 2);
        l0s = l0s * c0 + s0;
        l1s = l1s * c1 + s1;
#pragma unroll
        for (int nb = 0; nb < 8; nb++) {
            ctx[nb][0] *= c0; ctx[nb][1] *= c0;
            ctx[nb][2] *= c1; ctx[nb][3] *= c1;
        }

        uint32_t ph[4][4], pl[4][4];
#pragma unroll
        for (int kb = 0; kb < 4; kb++) {
            const float* sA = S[2 * kb];
            const float* sB = S[2 * kb + 1];
            ph[kb][0] = bf2pack(sA[0], sA[1]);
            ph[kb][1] = bf2pack(sA[2], sA[3]);
            ph[kb][2] = bf2pack(sB[0], sB[1]);
            ph[kb][3] = bf2pack(sB[2], sB[3]);
            __nv_bfloat162 t0 = *(__nv_bfloat162*)&ph[kb][0];
            __nv_bfloat162 t1 = *(__nv_bfloat162*)&ph[kb][1];
            __nv_bfloat162 t2 = *(__nv_bfloat162*)&ph[kb][2];
            __nv_bfloat162 t3 = *(__nv_bfloat162*)&ph[kb][3];
            pl[kb][0] = bf2pack(sA[0] - __bfloat162float(t0.x), sA[1] - __bfloat162float(t0.y));
            pl[kb][1] = bf2pack(sA[2] - __bfloat162float(t1.x), sA[3] - __bfloat162float(t1.y));
            pl[kb][2] = bf2pack(sB[0] - __bfloat162float(t2.x), sB[1] - __bfloat162float(t2.y));
            pl[kb][3] = bf2pack(sB[2] - __bfloat162float(t3.x), sB[3] - __bfloat162float(t3.y));
        }

        const uint32_t vrow = (lane & 7) + ((lane >> 3) & 1) * 8;
        const uint32_t vcol16 = (lane >> 4) * 16;
#pragma unroll
        for (int kb = 0; kb < 4; kb++) {
#pragma unroll
            for (int ngd = 0; ngd < 4; ngd++) {
                uint32_t vbh[4], vbl[4];
                uint32_t va = st + 2 * AKV_TILE + (kb * 16 + vrow) * AT_S + ngd * 32 + vcol16;
                LDSM4T(vbh, va);
                LDSM4T(vbl, va + AKV_TILE);
                int nd = ngd * 2;
                MMA16816(ctx[nd], ph[kb], vbh[0], vbh[1]);
                MMA16816(ctx[nd + 1], ph[kb], vbh[2], vbh[3]);
                MMA16816(ctx[nd], ph[kb], vbl[0], vbl[1]);
                MMA16816(ctx[nd + 1], ph[kb], vbl[2], vbl[3]);
                MMA16816(ctx[nd], pl[kb], vbh[0], vbh[1]);
                MMA16816(ctx[nd + 1], pl[kb], vbh[2], vbh[3]);
            }
        }
    }

    float inv0 = 1.f / l0s, inv1 = 1.f / l1s;
    const size_t mg0 = (size_t)(l0 + warp * 16 + (lane >> 2)) * 4 + b;
    const size_t mg1 = mg0 + 32;
#pragma unroll
    for (int nd = 0; nd < 8; nd++) {
        int col = h * 64 + nd * 8 + 2 * (lane & 3);
        *(uint32_t*)(ctx16 + mg0 * 512 + col) = h2pack(ctx[nd][0] * inv0, ctx[nd][1] * inv0);
        *(uint32_t*)(ctx16 + mg1 * 512 + col) = h2pack(ctx[nd][2] * inv1, ctx[nd][3] * inv1);
    }
}

// ---------------- fused residual-add + LayerNorm (+ optional final LN, fp16 out) ----
__global__ void __launch_bounds__(128) add_ln_kernel(float* __restrict__ x,
                                                     __half* __restrict__ x16,
                                                     const float* __restrict__ y,
                                                     const float* __restrict__ a,
                                                     const float* __restrict__ b,
                                                     const float* __restrict__ fa,
                                                     const float* __restrict__ fb)
{
    const int m = blockIdx.x;
    const int tid = threadIdx.x;
    const size_t base = (size_t)m * DMODEL;
    __shared__ float red[8];

    float v[4];
#pragma unroll
    for (int j = 0; j < 4; j++) {
        int d = tid + j * 128;
        float xv = x[base + d];
        if (y) xv += y[base + d];
        v[j] = xv;
    }
    float s = v[0] + v[1] + v[2] + v[3];
#pragma unroll
    for (int o = 16; o > 0; o >>= 1) s += __shfl_xor_sync(0xffffffffu, s, o);
    if ((tid & 31) == 0) red[tid >> 5] = s;
    __syncthreads();
    float mean = (red[0] + red[1] + red[2] + red[3]) * (1.f / 512.f);

    float ss = 0.f;
#pragma unroll
    for (int j = 0; j < 4; j++) {
        float dm = v[j] - mean;
        ss += dm * dm;
    }
#pragma unroll
    for (int o = 16; o > 0; o >>= 1) ss += __shfl_xor_sync(0xffffffffu, ss, o);
    if ((tid & 31) == 0) red[4 + (tid >> 5)] = ss;
    __syncthreads();
    float var = (red[4] + red[5] + red[6] + red[7]) * (1.f / 511.f);
    float inv = 1.f / (sqrtf(var) + 1e-6f);

    float o4[4];
#pragma unroll
    for (int j = 0; j < 4; j++) {
        int d = tid + j * 128;
        o4[j] = a[d] * (v[j] - mean) * inv + b[d];
    }

    if (fa) {
        __syncthreads();
        float s2 = o4[0] + o4[1] + o4[2] + o4[3];
#pragma unroll
        for (int o = 16; o > 0; o >>= 1) s2 += __shfl_xor_sync(0xffffffffu, s2, o);
        if ((tid & 31) == 0) red[tid >> 5] = s2;
        __syncthreads();
        float mean2 = (red[0] + red[1] + red[2] + red[3]) * (1.f / 512.f);
        float ss2 = 0.f;
#pragma unroll
        for (int j = 0; j < 4; j++) {
            float dm = o4[j] - mean2;
            ss2 += dm * dm;
        }
#pragma unroll
        for (int o = 16; o > 0; o >>= 1) ss2 += __shfl_xor_sync(0xffffffffu, ss2, o);
        if ((tid & 31) == 0) red[4 + (tid >> 5)] = ss2;
        __syncthreads();
        float var2 = (red[4] + red[5] + red[6] + red[7]) * (1.f / 511.f);
        float inv2 = 1.f / (sqrtf(var2) + 1e-6f);
#pragma unroll
        for (int j = 0; j < 4; j++) {
            int d = tid + j * 128;
            o4[j] = fa[d] * (o4[j] - mean2) * inv2 + fb[d];
        }
    }

#pragma unroll
    for (int j = 0; j < 4; j++) {
        int d = tid + j * 128;
        x[base + d] = o4[j];
        x16[base + d] = __float2half(o4[j]);
    }
}

// ---------------- orchestration ----------------
extern "C" void kernel_launch(void* const* d_in, const int* in_sizes, int n_in,
                              void* d_out, int out_size)
{
    (void)in_sizes; (void)n_in; (void)out_size;
    const int*   input = (const int*)  d_in[0];
    const float* emb   = (const float*)d_in[1];
    const float* Wq    = (const float*)d_in[2];
    const float* Wk    = (const float*)d_in[3];
    const float* Wv    = (const float*)d_in[4];
    const float* Wo    = (const float*)d_in[5];
    const float* w1    = (const float*)d_in[6];
    const float* b1    = (const float*)d_in[7];
    const float* w2    = (const float*)d_in[8];
    const float* b2    = (const float*)d_in[9];
    const float* ln1a  = (const float*)d_in[10];
    const float* ln1b  = (const float*)d_in[11];
    const float* ln2a  = (const float*)d_in[12];
    const float* ln2b  = (const float*)d_in[13];
    const float* fna   = (const float*)d_in[14];
    const float* fnb   = (const float*)d_in[15];
    const float* decW  = (const float*)d_in[16];
    const float* decb  = (const float*)d_in[17];
    float* out = (float*)d_out;

    float *x, *t;
    __nv_bfloat16 *xs, *qkvs, *cs, *ahi, *whi, *wlo;
    cudaGetSymbolAddress((void**)&x,    g_x);
    cudaGetSymbolAddress((void**)&t,    g_t);
    cudaGetSymbolAddress((void**)&xs,   g_xs);
    cudaGetSymbolAddress((void**)&qkvs, g_qkvs);
    cudaGetSymbolAddress((void**)&cs,   g_cs);
    cudaGetSymbolAddress((void**)&ahi,  g_ahi);
    cudaGetSymbolAddress((void**)&whi,  g_whi);
    cudaGetSymbolAddress((void**)&wlo,  g_wlo);

    const int AS = MROWS * DMODEL;
    const int QAS = MROWS * 3 * DMODEL;
    __half* x16 = (__half*)xs;
    __nv_bfloat16 *qkvh = qkvs, *qkvl = qkvs + QAS;
    __half* c16 = (__half*)cs;
    __half* a16 = (__half*)ahi;
    __half* wh = (__half*)whi;
    __half* wl = (__half*)wlo;

    cudaFuncSetAttribute(attn_mma, cudaFuncAttributeMaxDynamicSharedMemorySize, ATTN_SMEM);
    cudaFuncSetAttribute(gemm_2t<false, false, 2>, cudaFuncAttributeMaxDynamicSharedMemorySize, GEMM2_SMEM);
    cudaFuncSetAttribute(gemm_2t<false, false, 0>, cudaFuncAttributeMaxDynamicSharedMemorySize, GEMM2_SMEM);
    cudaFuncSetAttribute(gemm_2t<true, true, 1>,   cudaFuncAttributeMaxDynamicSharedMemorySize, GEMM2_SMEM);
    cudaFuncSetAttribute(gemm_2t<true, false, 0>,  cudaFuncAttributeMaxDynamicSharedMemorySize, GEMM2_SMEM);

    // weight splits (fp16 2-term): fused QKV strided (q scaled 1/8), Wo/w1/w2/decW
    split_qkv16<<<1024, 256>>>(wh + WQKV0, wl + WQKV0, Wq, 0.125f, 0);
    split_qkv16<<<1024, 256>>>(wh + WQKV0, wl + WQKV0, Wk, 1.0f, 131072);
    split_qkv16<<<1024, 256>>>(wh + WQKV0, wl + WQKV0, Wv, 1.0f, 262144);
    split16_2<<<1024, 256>>>(wh + WO0, wl + WO0, Wo, 1048576 / 4);
    split16_2<<<4096, 256>>>(wh + W10, wl + W10, w1, 4194304 / 4);
    split16_2<<<4096, 256>>>(wh + W20, wl + W20, w2, 4194304 / 4);
    split16_2<<<16000, 256>>>(wh + WD0, wl + WD0, decW, 16384000 / 4);

    embed_kernel<<<MROWS, 128>>>(x, x16, input, emb);

    const dim3 gQKV(3 * DMODEL / 256, MROWS / 128);  // (6, 64)
    const dim3 gD(DMODEL / 256, MROWS / 128);        // (2, 64)
    const dim3 gF(DFFN / 256, MROWS / 128);          // (8, 64)
    const dim3 gV(NVOCAB / 256, MROWS / 128);        // (125, 64)
    const dim3 gAttn(LSEQ / 128, BATCH, NHEAD);

    for (int l = 0; l < NLAYER; l++) {
        const size_t qofs = (size_t)l * 1536 * 512;
        const size_t wofs = (size_t)l * DMODEL * DMODEL;
        const size_t f1 = (size_t)l * DFFN * DMODEL;
        const bool last = (l == NLAYER - 1);

        gemm_2t<false, false, 2><<<gQKV, 256, GEMM2_SMEM>>>(
            nullptr, nullptr, qkvh, qkvl, x16, wh + WQKV0 + qofs, wl + WQKV0 + qofs,
            nullptr, MROWS, 3 * DMODEL, DMODEL);

        attn_mma<<<gAttn, 256, ATTN_SMEM>>>(c16, qkvh, qkvl);

        gemm_2t<false, false, 0><<<gD, 256, GEMM2_SMEM>>>(
            t, nullptr, nullptr, nullptr, c16, wh + WO0 + wofs, wl + WO0 + wofs,
            nullptr, MROWS, DMODEL, DMODEL);
        add_ln_kernel<<<MROWS, 128>>>(x, x16, t, ln1a + l * DMODEL, ln1b + l * DMODEL,
                                      nullptr, nullptr);

        gemm_2t<true, true, 1><<<gF, 256, GEMM2_SMEM>>>(
            nullptr, a16, nullptr, nullptr, x16, wh + W10 + f1, wl + W10 + f1,
            b1 + l * DFFN, MROWS, DFFN, DMODEL);
        gemm_2t<true, false, 0><<<gD, 256, GEMM2_SMEM>>>(
            t, nullptr, nullptr, nullptr, a16, wh + W20 + f1, wl + W20 + f1,
            b2 + l * DMODEL, MROWS, DMODEL, DFFN);
        add_ln_kernel<<<MROWS, 128>>>(x, x16, t, ln2a + l * DMODEL, ln2b + l * DMODEL,
                                      last ? fna : nullptr, last ? fnb : nullptr);
    }

    gemm_2t<true, false, 0><<<gV, 256, GEMM2_SMEM>>>(
        out, nullptr, nullptr, nullptr, x16, wh + WD0, wl + WD0,
        decb, MROWS, NVOCAB, DMODEL);
}

// round 9
// speedup vs baseline: 5.5670x; 1.3654x over previous
#include <cuda_runtime.h>
#include <cuda_bf16.h>
#include <cuda_fp16.h>
#include <math.h>
#include <stdint.h>

#define LSEQ 2048
#define BATCH 4
#define DMODEL 512
#define NHEAD 8
#define DKH 64
#define NLAYER 4
#define DFFN 2048
#define MROWS (LSEQ * BATCH)   // 8192
#define NVOCAB 32000

// ---------------- scratch (device globals; no allocation allowed) ----------------
__device__ float g_x[MROWS * DMODEL];
__device__ float g_t[MROWS * DMODEL];
__device__ __nv_bfloat16 g_xs[2 * MROWS * DMODEL];          // x16 fp16 (half used)
__device__ __nv_bfloat16 g_qkvs[2 * MROWS * 3 * DMODEL];    // fused qkv bf16 hi/lo
__device__ __nv_bfloat16 g_cs[2 * MROWS * DMODEL];          // ctx16 fp16 (half used)
__device__ __nv_bfloat16 g_ahi[MROWS * DFFN];               // ff fp16

// weight storage (fp16 single), element offsets:
#define WQKV0 0                 // fused [NLAYER][1536][512]
#define WO0 3145728
#define W10 4194304
#define W20 8388608
#define WD0 12582912
#define WTOT 28966912
__device__ __nv_bfloat16 g_whi[WTOT];

// ---------------- helpers ----------------
__device__ __forceinline__ uint32_t s2u(const void* p) {
    uint32_t a;
    asm("{ .reg .u64 t; cvta.to.shared.u64 t, %1; cvt.u32.u64 %0, t; }" : "=r"(a) : "l"(p));
    return a;
}
__device__ __forceinline__ void cpa16(uint32_t d, const void* s) {
    asm volatile("cp.async.cg.shared.global [%0], [%1], 16;" :: "r"(d), "l"(s));
}
__device__ __forceinline__ uint32_t bf2pack(float x, float y) {
    __nv_bfloat162 t; t.x = __float2bfloat16(x); t.y = __float2bfloat16(y);
    return *(uint32_t*)&t;
}
__device__ __forceinline__ uint32_t h2pack(float x, float y) {
    __half2 t = __floats2half2_rn(x, y);
    return *(uint32_t*)&t;
}

#define LDSM4(r, a) \
    asm volatile("ldmatrix.sync.aligned.m8n8.x4.shared.b16 {%0,%1,%2,%3}, [%4];" \
        : "=r"((r)[0]), "=r"((r)[1]), "=r"((r)[2]), "=r"((r)[3]) : "r"(a))
#define LDSM4T(r, a) \
    asm volatile("ldmatrix.sync.aligned.m8n8.x4.trans.shared.b16 {%0,%1,%2,%3}, [%4];" \
        : "=r"((r)[0]), "=r"((r)[1]), "=r"((r)[2]), "=r"((r)[3]) : "r"(a))

#define MMA16816(c, a, b0, b1) \
    asm volatile("mma.sync.aligned.m16n8k16.row.col.f32.bf16.bf16.f32 " \
        "{%0,%1,%2,%3}, {%4,%5,%6,%7}, {%8,%9}, {%0,%1,%2,%3};" \
        : "+f"((c)[0]), "+f"((c)[1]), "+f"((c)[2]), "+f"((c)[3]) \
        : "r"((a)[0]), "r"((a)[1]), "r"((a)[2]), "r"((a)[3]), "r"(b0), "r"(b1))

#define MMAF16(c, a, b0, b1) \
    asm volatile("mma.sync.aligned.m16n8k16.row.col.f32.f16.f16.f32 " \
        "{%0,%1,%2,%3}, {%4,%5,%6,%7}, {%8,%9}, {%0,%1,%2,%3};" \
        : "+f"((c)[0]), "+f"((c)[1]), "+f"((c)[2]), "+f"((c)[3]) \
        : "r"((a)[0]), "r"((a)[1]), "r"((a)[2]), "r"((a)[3]), "r"(b0), "r"(b1))

// ---------------- fp32 -> fp16 single weight converts ----------------
__global__ void __launch_bounds__(256) cvt16(__half* __restrict__ dst,
                                             const float* __restrict__ src,
                                             int n4)
{
    int i = blockIdx.x * 256 + threadIdx.x;
    if (i >= n4) return;
    float4 v = ((const float4*)src)[i];
    ((uint32_t*)dst)[2 * i + 0] = h2pack(v.x, v.y);
    ((uint32_t*)dst)[2 * i + 1] = h2pack(v.z, v.w);
}

// strided QKV convert: src [NLAYER][512][512] -> dst layer stride 1536*512
__global__ void __launch_bounds__(256) cvt16_qkv(__half* __restrict__ dst,
                                                 const float* __restrict__ src,
                                                 float scale, int region2)
{
    int i = blockIdx.x * 256 + threadIdx.x;     // 262144 float4s total
    float4 v = ((const float4*)src)[i];
    v.x *= scale; v.y *= scale; v.z *= scale; v.w *= scale;
    int l = i >> 16, w = i & 65535;
    int di = l * 393216 + region2 + 2 * w;      // uint32 units
    ((uint32_t*)dst)[di + 0] = h2pack(v.x, v.y);
    ((uint32_t*)dst)[di + 1] = h2pack(v.z, v.w);
}

// ---------------- fp16 1-term GEMM: C = A * B^T (+bias,+relu) ----------------
// BM=128, BN=256, BK=128; 256 threads; warp 64x64; double buffered.
// OUTM: 0 = fp32 C, 1 = fp16 O16, 2 = bf16 hi/lo split (Oh/Ol)
#define T1S 272                                  // 256B data + 16B pad
#define T1_A_TILE (128 * T1S)                    // 34816
#define T1_B_TILE (256 * T1S)                    // 69632
#define T1_STAGE (T1_A_TILE + T1_B_TILE)         // 104448
#define GEMM1_SMEM (2 * T1_STAGE)                // 208896
#define OFF1_B T1_A_TILE

template <bool BIAS, bool RELU, int OUTM>
__global__ void __launch_bounds__(256) gemm_1t(float* __restrict__ C,
                                               __half* __restrict__ O16,
                                               __nv_bfloat16* __restrict__ Oh,
                                               __nv_bfloat16* __restrict__ Ol,
                                               const __half* __restrict__ A,
                                               const __half* __restrict__ B,
                                               const float* __restrict__ bias,
                                               int M, int N, int K)
{
    extern __shared__ char smem[];
    const uint32_t sb = s2u(smem);
    const int tid = threadIdx.x;
    const int warp = tid >> 5, lane = tid & 31;
    const int bm = blockIdx.y * 128;
    const int bn = blockIdx.x * 256;
    const int warp_m = warp >> 2;
    const int warp_n = warp & 3;
    const int nch = K >> 7;                      // K/128

    const __half* pA = A + (size_t)bm * K;
    const __half* pB = B + (size_t)bn * K;

    auto load_stage = [&](uint32_t st, int k0) {
        // A: 128 rows x 16 segs of 16B
#pragma unroll
        for (int j = 0; j < 8; j++) {
            int idx = tid + j * 256;
            int r = idx >> 4, seg = idx & 15;
            cpa16(st + r * T1S + seg * 16, pA + (size_t)r * K + k0 + seg * 8);
        }
        // B: 256 rows x 16 segs
#pragma unroll
        for (int j = 0; j < 16; j++) {
            int idx = tid + j * 256;
            int r = idx >> 4, seg = idx & 15;
            cpa16(st + OFF1_B + r * T1S + seg * 16, pB + (size_t)r * K + k0 + seg * 8);
        }
    };

    float acc[4][8][4];
#pragma unroll
    for (int i = 0; i < 4; i++)
#pragma unroll
        for (int j = 0; j < 8; j++)
#pragma unroll
            for (int q = 0; q < 4; q++) acc[i][j][q] = 0.f;

    const int g = lane >> 3, lr = lane & 7;
    const int a_row = lr + (g & 1) * 8;
    const int a_k8 = g >> 1;
    const int b_row = lr + (g >> 1) * 8;
    const int b_k8 = g & 1;

    load_stage(sb, 0);
    asm volatile("cp.async.commit_group;" ::: "memory");

    for (int i = 0; i < nch; i++) {
        const uint32_t st = sb + (i & 1) * T1_STAGE;
        __syncthreads();
        if (i + 1 < nch) load_stage(sb + ((i + 1) & 1) * T1_STAGE, (i + 1) * 128);
        asm volatile("cp.async.commit_group;" ::: "memory");
        asm volatile("cp.async.wait_group 1;" ::: "memory");
        __syncthreads();

#pragma unroll
        for (int ks = 0; ks < 8; ks++) {
            uint32_t ah[4][4];
#pragma unroll
            for (int mi = 0; mi < 4; mi++) {
                uint32_t aaddr = st + (warp_m * 64 + mi * 16 + a_row) * T1S +
                                 ks * 32 + a_k8 * 16;
                LDSM4(ah[mi], aaddr);
            }
#pragma unroll
            for (int ng = 0; ng < 4; ng++) {
                uint32_t bfr[4];
                uint32_t baddr = st + OFF1_B + (warp_n * 64 + ng * 16 + b_row) * T1S +
                                 ks * 32 + b_k8 * 16;
                LDSM4(bfr, baddr);
#pragma unroll
                for (int mi = 0; mi < 4; mi++) {
                    MMAF16(acc[mi][2 * ng], ah[mi], bfr[0], bfr[1]);
                    MMAF16(acc[mi][2 * ng + 1], ah[mi], bfr[2], bfr[3]);
                }
            }
        }
    }

    const int tm = lane >> 2, tn = (lane & 3) * 2;
#pragma unroll
    for (int mi = 0; mi < 4; mi++) {
#pragma unroll
        for (int nj = 0; nj < 8; nj++) {
            const float* a4 = acc[mi][nj];
            int row0 = bm + warp_m * 64 + mi * 16 + tm;
            int col = bn + warp_n * 64 + nj * 8 + tn;
            float b0 = 0.f, b1 = 0.f;
            if (BIAS) { b0 = bias[col]; b1 = bias[col + 1]; }
            float v0 = a4[0] + b0, v1 = a4[1] + b1;
            float v2 = a4[2] + b0, v3 = a4[3] + b1;
            if (RELU) {
                v0 = fmaxf(v0, 0.f); v1 = fmaxf(v1, 0.f);
                v2 = fmaxf(v2, 0.f); v3 = fmaxf(v3, 0.f);
            }
            if (OUTM == 0) {
                *(float2*)(C + (size_t)row0 * N + col) = make_float2(v0, v1);
                *(float2*)(C + (size_t)(row0 + 8) * N + col) = make_float2(v2, v3);
            } else if (OUTM == 1) {
                *(uint32_t*)(O16 + (size_t)row0 * N + col) = h2pack(v0, v1);
                *(uint32_t*)(O16 + (size_t)(row0 + 8) * N + col) = h2pack(v2, v3);
            } else {
                uint32_t h0 = bf2pack(v0, v1), h1 = bf2pack(v2, v3);
                __nv_bfloat162 hh0 = *(__nv_bfloat162*)&h0;
                __nv_bfloat162 hh1 = *(__nv_bfloat162*)&h1;
                uint32_t l0p = bf2pack(v0 - __bfloat162float(hh0.x),
                                       v1 - __bfloat162float(hh0.y));
                uint32_t l1p = bf2pack(v2 - __bfloat162float(hh1.x),
                                       v3 - __bfloat162float(hh1.y));
                *(uint32_t*)(Oh + (size_t)row0 * N + col) = h0;
                *(uint32_t*)(Oh + (size_t)(row0 + 8) * N + col) = h1;
                *(uint32_t*)(Ol + (size_t)row0 * N + col) = l0p;
                *(uint32_t*)(Ol + (size_t)(row0 + 8) * N + col) = l1p;
            }
        }
    }
}

// ---------------- embedding + positional encoding (fp32 + fp16 out) ----------------
__global__ void __launch_bounds__(128) embed_kernel(float* __restrict__ x,
                                                    __half* __restrict__ x16,
                                                    const int* __restrict__ tok,
                                                    const float* __restrict__ emb)
{
    int m = blockIdx.x;
    int l = m >> 2;
    int t = tok[m];
    const float sq = 22.627416997969522f;
    const double nlog = 9.210340371976184;
#pragma unroll
    for (int j = 0; j < 4; j++) {
        int d = threadIdx.x + j * 128;
        int i = d >> 1;
        float freqf = (float)exp(-(double)(2 * i) * (nlog / 512.0));
        float angf = (float)l * freqf;
        double ang = (double)angf;
        float pe = (d & 1) ? (float)cos(ang) : (float)sin(ang);
        float v = emb[(size_t)t * DMODEL + d] * sq + pe;
        x[(size_t)m * DMODEL + d] = v;
        x16[(size_t)m * DMODEL + d] = __float2half(v);
    }
}

// ---------------- mma flash attention (causal, 3x bf16 split), fused-QKV input --------
#define QKVSTR 1536
#define AT_S 144
#define AQ_B (128 * AT_S)
#define AKV_TILE (64 * AT_S)
#define AKV_STAGE (4 * AKV_TILE)
#define ATTN_SMEM (2 * AQ_B + 2 * AKV_STAGE)  // 110592

__global__ void __launch_bounds__(256) attn_mma(
    __half* __restrict__ ctx16,
    const __nv_bfloat16* __restrict__ qkvh, const __nv_bfloat16* __restrict__ qkvl)
{
    extern __shared__ char smem[];
    const uint32_t sb = s2u(smem);
    const int tid = threadIdx.x, warp = tid >> 5, lane = tid & 31;
    const int bx = blockIdx.x, b = blockIdx.y, h = blockIdx.z;
    const int l0 = bx * 128;
    const int ntiles = 2 * bx + 2;

    const uint32_t sQh = sb, sQl = sb + AQ_B;
    const uint32_t sKV = sb + 2 * AQ_B;

#pragma unroll
    for (int t = 0; t < 8; t++) {
        int idx = tid + t * 256;
        int row = idx >> 4;
        int sub = idx & 15;
        int seg = sub & 7;
        const __nv_bfloat16* src = (sub < 8) ? qkvh : qkvl;
        uint32_t dst = ((sub < 8) ? sQh : sQl) + row * AT_S + seg * 16;
        cpa16(dst, src + ((size_t)(l0 + row) * 4 + b) * QKVSTR + h * 64 + seg * 8);
    }
    asm volatile("cp.async.commit_group;" ::: "memory");

    auto load_kv = [&](int s, int jt) {
        uint32_t st = sKV + s * AKV_STAGE;
#pragma unroll
        for (int t = 0; t < 8; t++) {
            int idx = tid + t * 256;
            int arr = idx >> 9;
            int row = (idx >> 3) & 63;
            int seg = idx & 7;
            const __nv_bfloat16* src = (arr & 1) ? qkvl : qkvh;
            int coff = (arr < 2) ? 512 : 1024;
            cpa16(st + arr * AKV_TILE + row * AT_S + seg * 16,
                  src + ((size_t)(jt * 64 + row) * 4 + b) * QKVSTR + coff + h * 64 + seg * 8);
        }
    };
    load_kv(0, 0);
    asm volatile("cp.async.commit_group;" ::: "memory");

    const int a_row = (lane & 7) + ((lane >> 3) & 1) * 8;
    const int a_k8 = lane >> 4;
    const int b_row = (lane & 7) + (lane >> 4) * 8;
    const int b_k8 = (lane >> 3) & 1;

    uint32_t qfh[4][4], qfl[4][4];
    float ctx[8][4];
#pragma unroll
    for (int i = 0; i < 8; i++)
#pragma unroll
        for (int j = 0; j < 4; j++) ctx[i][j] = 0.f;
    float m0 = -INFINITY, m1 = -INFINITY, l0s = 0.f, l1s = 0.f;

    for (int jt = 0; jt < ntiles; jt++) {
        const uint32_t st = sKV + (jt & 1) * AKV_STAGE;
        __syncthreads();
        if (jt + 1 < ntiles) {
            load_kv((jt + 1) & 1, jt + 1);
            asm volatile("cp.async.commit_group;" ::: "memory");
            asm volatile("cp.async.wait_group 1;" ::: "memory");
        } else {
            asm volatile("cp.async.wait_group 0;" ::: "memory");
        }
        __syncthreads();

        if (jt == 0) {
#pragma unroll
            for (int kb = 0; kb < 4; kb++) {
                uint32_t qa = sQh + (warp * 16 + a_row) * AT_S + (kb * 2 + a_k8) * 16;
                LDSM4(qfh[kb], qa);
                LDSM4(qfl[kb], qa + AQ_B);
            }
        }

        float S[8][4];
#pragma unroll
        for (int i = 0; i < 8; i++)
#pragma unroll
            for (int j = 0; j < 4; j++) S[i][j] = 0.f;
#pragma unroll
        for (int kb = 0; kb < 4; kb++) {
#pragma unroll
            for (int ng = 0; ng < 4; ng++) {
                uint32_t kbh[4], kbl[4];
                uint32_t ka = st + (ng * 16 + b_row) * AT_S + (kb * 2 + b_k8) * 16;
                LDSM4(kbh, ka);
                LDSM4(kbl, ka + AKV_TILE);
                int nb = ng * 2;
                MMA16816(S[nb], qfh[kb], kbh[0], kbh[1]);
                MMA16816(S[nb + 1], qfh[kb], kbh[2], kbh[3]);
                MMA16816(S[nb], qfh[kb], kbl[0], kbl[1]);
                MMA16816(S[nb + 1], qfh[kb], kbl[2], kbl[3]);
                MMA16816(S[nb], qfl[kb], kbh[0], kbh[1]);
                MMA16816(S[nb + 1], qfl[kb], kbh[2], kbh[3]);
            }
        }

        const int qr0 = l0 + warp * 16 + (lane >> 2);
        const int qr1 = qr0 + 8;
        if (jt >= ntiles - 2) {
#pragma unroll
            for (int nb = 0; nb < 8; nb++) {
                int c = jt * 64 + nb * 8 + 2 * (lane & 3);
                if (c > qr0) S[nb][0] = -INFINITY;
                if (c + 1 > qr0) S[nb][1] = -INFINITY;
                if (c > qr1) S[nb][2] = -INFINITY;
                if (c + 1 > qr1) S[nb][3] = -INFINITY;
            }
        }

        float mx0 = -INFINITY, mx1 = -INFINITY;
#pragma unroll
        for (int nb = 0; nb < 8; nb++) {
            mx0 = fmaxf(mx0, fmaxf(S[nb][0], S[nb][1]));
            mx1 = fmaxf(mx1, fmaxf(S[nb][2], S[nb][3]));
        }
        mx0 = fmaxf(mx0, __shfl_xor_sync(0xffffffffu, mx0, 1));
        mx0 = fmaxf(mx0, __shfl_xor_sync(0xffffffffu, mx0, 2));
        mx1 = fmaxf(mx1, __shfl_xor_sync(0xffffffffu, mx1, 1));
        mx1 = fmaxf(mx1, __shfl_xor_sync(0xffffffffu, mx1, 2));
        float nm0 = fmaxf(m0, mx0), nm1 = fmaxf(m1, mx1);
        float c0 = __expf(m0 - nm0), c1 = __expf(m1 - nm1);
        m0 = nm0; m1 = nm1;
        float s0 = 0.f, s1 = 0.f;
#pragma unroll
        for (int nb = 0; nb < 8; nb++) {
            S[nb][0] = __expf(S[nb][0] - nm0);
            S[nb][1] = __expf(S[nb][1] - nm0);
            S[nb][2] = __expf(S[nb][2] - nm1);
            S[nb][3] = __expf(S[nb][3] - nm1);
            s0 += S[nb][0] + S[nb][1];
            s1 += S[nb][2] + S[nb][3];
        }
        s0 += __shfl_xor_sync(0xffffffffu, s0, 1);
        s0 += __shfl_xor_sync(0xffffffffu, s0, 2);
        s1 += __shfl_xor_sync(0xffffffffu, s1, 1);
        s1 += __shfl_xor_sync(0xffffffffu, s1, 2);
        l0s = l0s * c0 + s0;
        l1s = l1s * c1 + s1;
#pragma unroll
        for (int nb = 0; nb < 8; nb++) {
            ctx[nb][0] *= c0; ctx[nb][1] *= c0;
            ctx[nb][2] *= c1; ctx[nb][3] *= c1;
        }

        uint32_t ph[4][4], pl[4][4];
#pragma unroll
        for (int kb = 0; kb < 4; kb++) {
            const float* sA = S[2 * kb];
            const float* sB = S[2 * kb + 1];
            ph[kb][0] = bf2pack(sA[0], sA[1]);
            ph[kb][1] = bf2pack(sA[2], sA[3]);
            ph[kb][2] = bf2pack(sB[0], sB[1]);
            ph[kb][3] = bf2pack(sB[2], sB[3]);
            __nv_bfloat162 t0 = *(__nv_bfloat162*)&ph[kb][0];
            __nv_bfloat162 t1 = *(__nv_bfloat162*)&ph[kb][1];
            __nv_bfloat162 t2 = *(__nv_bfloat162*)&ph[kb][2];
            __nv_bfloat162 t3 = *(__nv_bfloat162*)&ph[kb][3];
            pl[kb][0] = bf2pack(sA[0] - __bfloat162float(t0.x), sA[1] - __bfloat162float(t0.y));
            pl[kb][1] = bf2pack(sA[2] - __bfloat162float(t1.x), sA[3] - __bfloat162float(t1.y));
            pl[kb][2] = bf2pack(sB[0] - __bfloat162float(t2.x), sB[1] - __bfloat162float(t2.y));
            pl[kb][3] = bf2pack(sB[2] - __bfloat162float(t3.x), sB[3] - __bfloat162float(t3.y));
        }

        const uint32_t vrow = (lane & 7) + ((lane >> 3) & 1) * 8;
        const uint32_t vcol16 = (lane >> 4) * 16;
#pragma unroll
        for (int kb = 0; kb < 4; kb++) {
#pragma unroll
            for (int ngd = 0; ngd < 4; ngd++) {
                uint32_t vbh[4], vbl[4];
                uint32_t va = st + 2 * AKV_TILE + (kb * 16 + vrow) * AT_S + ngd * 32 + vcol16;
                LDSM4T(vbh, va);
                LDSM4T(vbl, va + AKV_TILE);
                int nd = ngd * 2;
                MMA16816(ctx[nd], ph[kb], vbh[0], vbh[1]);
                MMA16816(ctx[nd + 1], ph[kb], vbh[2], vbh[3]);
                MMA16816(ctx[nd], ph[kb], vbl[0], vbl[1]);
                MMA16816(ctx[nd + 1], ph[kb], vbl[2], vbl[3]);
                MMA16816(ctx[nd], pl[kb], vbh[0], vbh[1]);
                MMA16816(ctx[nd + 1], pl[kb], vbh[2], vbh[3]);
            }
        }
    }

    float inv0 = 1.f / l0s, inv1 = 1.f / l1s;
    const size_t mg0 = (size_t)(l0 + warp * 16 + (lane >> 2)) * 4 + b;
    const size_t mg1 = mg0 + 32;
#pragma unroll
    for (int nd = 0; nd < 8; nd++) {
        int col = h * 64 + nd * 8 + 2 * (lane & 3);
        *(uint32_t*)(ctx16 + mg0 * 512 + col) = h2pack(ctx[nd][0] * inv0, ctx[nd][1] * inv0);
        *(uint32_t*)(ctx16 + mg1 * 512 + col) = h2pack(ctx[nd][2] * inv1, ctx[nd][3] * inv1);
    }
}

// ---------------- fused residual-add + LayerNorm (+ optional final LN, fp16 out) ----
__global__ void __launch_bounds__(128) add_ln_kernel(float* __restrict__ x,
                                                     __half* __restrict__ x16,
                                                     const float* __restrict__ y,
                                                     const float* __restrict__ a,
                                                     const float* __restrict__ b,
                                                     const float* __restrict__ fa,
                                                     const float* __restrict__ fb)
{
    const int m = blockIdx.x;
    const int tid = threadIdx.x;
    const size_t base = (size_t)m * DMODEL;
    __shared__ float red[8];

    float v[4];
#pragma unroll
    for (int j = 0; j < 4; j++) {
        int d = tid + j * 128;
        float xv = x[base + d];
        if (y) xv += y[base + d];
        v[j] = xv;
    }
    float s = v[0] + v[1] + v[2] + v[3];
#pragma unroll
    for (int o = 16; o > 0; o >>= 1) s += __shfl_xor_sync(0xffffffffu, s, o);
    if ((tid & 31) == 0) red[tid >> 5] = s;
    __syncthreads();
    float mean = (red[0] + red[1] + red[2] + red[3]) * (1.f / 512.f);

    float ss = 0.f;
#pragma unroll
    for (int j = 0; j < 4; j++) {
        float dm = v[j] - mean;
        ss += dm * dm;
    }
#pragma unroll
    for (int o = 16; o > 0; o >>= 1) ss += __shfl_xor_sync(0xffffffffu, ss, o);
    if ((tid & 31) == 0) red[4 + (tid >> 5)] = ss;
    __syncthreads();
    float var = (red[4] + red[5] + red[6] + red[7]) * (1.f / 511.f);
    float inv = 1.f / (sqrtf(var) + 1e-6f);

    float o4[4];
#pragma unroll
    for (int j = 0; j < 4; j++) {
        int d = tid + j * 128;
        o4[j] = a[d] * (v[j] - mean) * inv + b[d];
    }

    if (fa) {
        __syncthreads();
        float s2 = o4[0] + o4[1] + o4[2] + o4[3];
#pragma unroll
        for (int o = 16; o > 0; o >>= 1) s2 += __shfl_xor_sync(0xffffffffu, s2, o);
        if ((tid & 31) == 0) red[tid >> 5] = s2;
        __syncthreads();
        float mean2 = (red[0] + red[1] + red[2] + red[3]) * (1.f / 512.f);
        float ss2 = 0.f;
#pragma unroll
        for (int j = 0; j < 4; j++) {
            float dm = o4[j] - mean2;
            ss2 += dm * dm;
        }
#pragma unroll
        for (int o = 16; o > 0; o >>= 1) ss2 += __shfl_xor_sync(0xffffffffu, ss2, o);
        if ((tid & 31) == 0) red[4 + (tid >> 5)] = ss2;
        __syncthreads();
        float var2 = (red[4] + red[5] + red[6] + red[7]) * (1.f / 511.f);
        float inv2 = 1.f / (sqrtf(var2) + 1e-6f);
#pragma unroll
        for (int j = 0; j < 4; j++) {
            int d = tid + j * 128;
            o4[j] = fa[d] * (o4[j] - mean2) * inv2 + fb[d];
        }
    }

#pragma unroll
    for (int j = 0; j < 4; j++) {
        int d = tid + j * 128;
        x[base + d] = o4[j];
        x16[base + d] = __float2half(o4[j]);
    }
}

// ---------------- orchestration ----------------
extern "C" void kernel_launch(void* const* d_in, const int* in_sizes, int n_in,
                              void* d_out, int out_size)
{
    (void)in_sizes; (void)n_in; (void)out_size;
    const int*   input = (const int*)  d_in[0];
    const float* emb   = (const float*)d_in[1];
    const float* Wq    = (const float*)d_in[2];
    const float* Wk    = (const float*)d_in[3];
    const float* Wv    = (const float*)d_in[4];
    const float* Wo    = (const float*)d_in[5];
    const float* w1    = (const float*)d_in[6];
    const float* b1    = (const float*)d_in[7];
    const float* w2    = (const float*)d_in[8];
    const float* b2    = (const float*)d_in[9];
    const float* ln1a  = (const float*)d_in[10];
    const float* ln1b  = (const float*)d_in[11];
    const float* ln2a  = (const float*)d_in[12];
    const float* ln2b  = (const float*)d_in[13];
    const float* fna   = (const float*)d_in[14];
    const float* fnb   = (const float*)d_in[15];
    const float* decW  = (const float*)d_in[16];
    const float* decb  = (const float*)d_in[17];
    float* out = (float*)d_out;

    float *x, *t;
    __nv_bfloat16 *xs, *qkvs, *cs, *ahi, *whi;
    cudaGetSymbolAddress((void**)&x,    g_x);
    cudaGetSymbolAddress((void**)&t,    g_t);
    cudaGetSymbolAddress((void**)&xs,   g_xs);
    cudaGetSymbolAddress((void**)&qkvs, g_qkvs);
    cudaGetSymbolAddress((void**)&cs,   g_cs);
    cudaGetSymbolAddress((void**)&ahi,  g_ahi);
    cudaGetSymbolAddress((void**)&whi,  g_whi);

    const int QAS = MROWS * 3 * DMODEL;
    __half* x16 = (__half*)xs;
    __nv_bfloat16 *qkvh = qkvs, *qkvl = qkvs + QAS;
    __half* c16 = (__half*)cs;
    __half* a16 = (__half*)ahi;
    __half* wh = (__half*)whi;

    cudaFuncSetAttribute(attn_mma, cudaFuncAttributeMaxDynamicSharedMemorySize, ATTN_SMEM);
    cudaFuncSetAttribute(gemm_1t<false, false, 2>, cudaFuncAttributeMaxDynamicSharedMemorySize, GEMM1_SMEM);
    cudaFuncSetAttribute(gemm_1t<false, false, 0>, cudaFuncAttributeMaxDynamicSharedMemorySize, GEMM1_SMEM);
    cudaFuncSetAttribute(gemm_1t<true, true, 1>,   cudaFuncAttributeMaxDynamicSharedMemorySize, GEMM1_SMEM);
    cudaFuncSetAttribute(gemm_1t<true, false, 0>,  cudaFuncAttributeMaxDynamicSharedMemorySize, GEMM1_SMEM);

    // weight converts (fp16 single): fused QKV strided (q scaled 1/8), Wo/w1/w2/decW
    cvt16_qkv<<<1024, 256>>>(wh + WQKV0, Wq, 0.125f, 0);
    cvt16_qkv<<<1024, 256>>>(wh + WQKV0, Wk, 1.0f, 131072);
    cvt16_qkv<<<1024, 256>>>(wh + WQKV0, Wv, 1.0f, 262144);
    cvt16<<<1024, 256>>>(wh + WO0, Wo, 1048576 / 4);
    cvt16<<<4096, 256>>>(wh + W10, w1, 4194304 / 4);
    cvt16<<<4096, 256>>>(wh + W20, w2, 4194304 / 4);
    cvt16<<<16000, 256>>>(wh + WD0, decW, 16384000 / 4);

    embed_kernel<<<MROWS, 128>>>(x, x16, input, emb);

    const dim3 gQKV(3 * DMODEL / 256, MROWS / 128);  // (6, 64)
    const dim3 gD(DMODEL / 256, MROWS / 128);        // (2, 64)
    const dim3 gF(DFFN / 256, MROWS / 128);          // (8, 64)
    const dim3 gV(NVOCAB / 256, MROWS / 128);        // (125, 64)
    const dim3 gAttn(LSEQ / 128, BATCH, NHEAD);

    for (int l = 0; l < NLAYER; l++) {
        const size_t qofs = (size_t)l * 1536 * 512;
        const size_t wofs = (size_t)l * DMODEL * DMODEL;
        const size_t f1 = (size_t)l * DFFN * DMODEL;
        const bool last = (l == NLAYER - 1);

        gemm_1t<false, false, 2><<<gQKV, 256, GEMM1_SMEM>>>(
            nullptr, nullptr, qkvh, qkvl, x16, wh + WQKV0 + qofs,
            nullptr, MROWS, 3 * DMODEL, DMODEL);

        attn_mma<<<gAttn, 256, ATTN_SMEM>>>(c16, qkvh, qkvl);

        gemm_1t<false, false, 0><<<gD, 256, GEMM1_SMEM>>>(
            t, nullptr, nullptr, nullptr, c16, wh + WO0 + wofs,
            nullptr, MROWS, DMODEL, DMODEL);
        add_ln_kernel<<<MROWS, 128>>>(x, x16, t, ln1a + l * DMODEL, ln1b + l * DMODEL,
                                      nullptr, nullptr);

        gemm_1t<true, true, 1><<<gF, 256, GEMM1_SMEM>>>(
            nullptr, a16, nullptr, nullptr, x16, wh + W10 + f1,
            b1 + l * DFFN, MROWS, DFFN, DMODEL);
        gemm_1t<true, false, 0><<<gD, 256, GEMM1_SMEM>>>(
            t, nullptr, nullptr, nullptr, a16, wh + W20 + f1,
            b2 + l * DMODEL, MROWS, DMODEL, DFFN);
        add_ln_kernel<<<MROWS, 128>>>(x, x16, t, ln2a + l * DMODEL, ln2b + l * DMODEL,
                                      last ? fna : nullptr, last ? fnb : nullptr);
    }

    gemm_1t<true, false, 0><<<gV, 256, GEMM1_SMEM>>>(
        out, nullptr, nullptr, nullptr, x16, wh + WD0,
        decb, MROWS, NVOCAB, DMODEL);
}

// round 10
// speedup vs baseline: 6.8572x; 1.2318x over previous
#include <cuda_runtime.h>
#include <cuda_bf16.h>
#include <cuda_fp16.h>
#include <math.h>
#include <stdint.h>

#define LSEQ 2048
#define BATCH 4
#define DMODEL 512
#define NHEAD 8
#define DKH 64
#define NLAYER 4
#define DFFN 2048
#define MROWS (LSEQ * BATCH)   // 8192
#define NVOCAB 32000

// ---------------- scratch (device globals; no allocation allowed) ----------------
__device__ float g_x[MROWS * DMODEL];
__device__ float g_t[MROWS * DMODEL];
__device__ __nv_bfloat16 g_xs[2 * MROWS * DMODEL];          // x16 fp16 (half used)
__device__ __nv_bfloat16 g_qkvs[2 * MROWS * 3 * DMODEL];    // qkv fp16 (half used)
__device__ __nv_bfloat16 g_cs[2 * MROWS * DMODEL];          // ctx16 fp16 (half used)
__device__ __nv_bfloat16 g_ahi[MROWS * DFFN];               // ff fp16

// weight storage (fp16 single), element offsets:
#define WQKV0 0                 // fused [NLAYER][1536][512]
#define WO0 3145728
#define W10 4194304
#define W20 8388608
#define WD0 12582912
#define WTOT 28966912
__device__ __nv_bfloat16 g_whi[WTOT];

// ---------------- helpers ----------------
__device__ __forceinline__ uint32_t s2u(const void* p) {
    uint32_t a;
    asm("{ .reg .u64 t; cvta.to.shared.u64 t, %1; cvt.u32.u64 %0, t; }" : "=r"(a) : "l"(p));
    return a;
}
__device__ __forceinline__ void cpa16(uint32_t d, const void* s) {
    asm volatile("cp.async.cg.shared.global [%0], [%1], 16;" :: "r"(d), "l"(s));
}
__device__ __forceinline__ uint32_t h2pack(float x, float y) {
    __half2 t = __floats2half2_rn(x, y);
    return *(uint32_t*)&t;
}

#define LDSM4(r, a) \
    asm volatile("ldmatrix.sync.aligned.m8n8.x4.shared.b16 {%0,%1,%2,%3}, [%4];" \
        : "=r"((r)[0]), "=r"((r)[1]), "=r"((r)[2]), "=r"((r)[3]) : "r"(a))
#define LDSM4T(r, a) \
    asm volatile("ldmatrix.sync.aligned.m8n8.x4.trans.shared.b16 {%0,%1,%2,%3}, [%4];" \
        : "=r"((r)[0]), "=r"((r)[1]), "=r"((r)[2]), "=r"((r)[3]) : "r"(a))

#define MMAF16(c, a, b0, b1) \
    asm volatile("mma.sync.aligned.m16n8k16.row.col.f32.f16.f16.f32 " \
        "{%0,%1,%2,%3}, {%4,%5,%6,%7}, {%8,%9}, {%0,%1,%2,%3};" \
        : "+f"((c)[0]), "+f"((c)[1]), "+f"((c)[2]), "+f"((c)[3]) \
        : "r"((a)[0]), "r"((a)[1]), "r"((a)[2]), "r"((a)[3]), "r"(b0), "r"(b1))

// ---------------- fp32 -> fp16 single weight converts ----------------
__global__ void __launch_bounds__(256) cvt16(__half* __restrict__ dst,
                                             const float* __restrict__ src,
                                             int n4)
{
    int i = blockIdx.x * 256 + threadIdx.x;
    if (i >= n4) return;
    float4 v = ((const float4*)src)[i];
    ((uint32_t*)dst)[2 * i + 0] = h2pack(v.x, v.y);
    ((uint32_t*)dst)[2 * i + 1] = h2pack(v.z, v.w);
}

// strided QKV convert: src [NLAYER][512][512] -> dst layer stride 1536*512
__global__ void __launch_bounds__(256) cvt16_qkv(__half* __restrict__ dst,
                                                 const float* __restrict__ src,
                                                 float scale, int region2)
{
    int i = blockIdx.x * 256 + threadIdx.x;     // 262144 float4s total
    float4 v = ((const float4*)src)[i];
    v.x *= scale; v.y *= scale; v.z *= scale; v.w *= scale;
    int l = i >> 16, w = i & 65535;
    int di = l * 393216 + region2 + 2 * w;      // uint32 units
    ((uint32_t*)dst)[di + 0] = h2pack(v.x, v.y);
    ((uint32_t*)dst)[di + 1] = h2pack(v.z, v.w);
}

// ---------------- fp16 1-term GEMM: C = A * B^T (+bias,+relu) ----------------
// BM=128, BN=256, BK=128; 256 threads; warp 64x64; double buffered.
// OUTM: 0 = fp32 C, 1 = fp16 O16
#define T1S 272                                  // 256B data + 16B pad
#define T1_A_TILE (128 * T1S)                    // 34816
#define T1_B_TILE (256 * T1S)                    // 69632
#define T1_STAGE (T1_A_TILE + T1_B_TILE)         // 104448
#define GEMM1_SMEM (2 * T1_STAGE)                // 208896
#define OFF1_B T1_A_TILE

template <bool BIAS, bool RELU, int OUTM>
__global__ void __launch_bounds__(256) gemm_1t(float* __restrict__ C,
                                               __half* __restrict__ O16,
                                               const __half* __restrict__ A,
                                               const __half* __restrict__ B,
                                               const float* __restrict__ bias,
                                               int M, int N, int K)
{
    extern __shared__ char smem[];
    const uint32_t sb = s2u(smem);
    const int tid = threadIdx.x;
    const int warp = tid >> 5, lane = tid & 31;
    const int bm = blockIdx.y * 128;
    const int bn = blockIdx.x * 256;
    const int warp_m = warp >> 2;
    const int warp_n = warp & 3;
    const int nch = K >> 7;                      // K/128

    const __half* pA = A + (size_t)bm * K;
    const __half* pB = B + (size_t)bn * K;

    auto load_stage = [&](uint32_t st, int k0) {
#pragma unroll
        for (int j = 0; j < 8; j++) {
            int idx = tid + j * 256;
            int r = idx >> 4, seg = idx & 15;
            cpa16(st + r * T1S + seg * 16, pA + (size_t)r * K + k0 + seg * 8);
        }
#pragma unroll
        for (int j = 0; j < 16; j++) {
            int idx = tid + j * 256;
            int r = idx >> 4, seg = idx & 15;
            cpa16(st + OFF1_B + r * T1S + seg * 16, pB + (size_t)r * K + k0 + seg * 8);
        }
    };

    float acc[4][8][4];
#pragma unroll
    for (int i = 0; i < 4; i++)
#pragma unroll
        for (int j = 0; j < 8; j++)
#pragma unroll
            for (int q = 0; q < 4; q++) acc[i][j][q] = 0.f;

    const int g = lane >> 3, lr = lane & 7;
    const int a_row = lr + (g & 1) * 8;
    const int a_k8 = g >> 1;
    const int b_row = lr + (g >> 1) * 8;
    const int b_k8 = g & 1;

    load_stage(sb, 0);
    asm volatile("cp.async.commit_group;" ::: "memory");

    for (int i = 0; i < nch; i++) {
        const uint32_t st = sb + (i & 1) * T1_STAGE;
        __syncthreads();
        if (i + 1 < nch) load_stage(sb + ((i + 1) & 1) * T1_STAGE, (i + 1) * 128);
        asm volatile("cp.async.commit_group;" ::: "memory");
        asm volatile("cp.async.wait_group 1;" ::: "memory");
        __syncthreads();

#pragma unroll
        for (int ks = 0; ks < 8; ks++) {
            uint32_t ah[4][4];
#pragma unroll
            for (int mi = 0; mi < 4; mi++) {
                uint32_t aaddr = st + (warp_m * 64 + mi * 16 + a_row) * T1S +
                                 ks * 32 + a_k8 * 16;
                LDSM4(ah[mi], aaddr);
            }
#pragma unroll
            for (int ng = 0; ng < 4; ng++) {
                uint32_t bfr[4];
                uint32_t baddr = st + OFF1_B + (warp_n * 64 + ng * 16 + b_row) * T1S +
                                 ks * 32 + b_k8 * 16;
                LDSM4(bfr, baddr);
#pragma unroll
                for (int mi = 0; mi < 4; mi++) {
                    MMAF16(acc[mi][2 * ng], ah[mi], bfr[0], bfr[1]);
                    MMAF16(acc[mi][2 * ng + 1], ah[mi], bfr[2], bfr[3]);
                }
            }
        }
    }

    const int tm = lane >> 2, tn = (lane & 3) * 2;
#pragma unroll
    for (int mi = 0; mi < 4; mi++) {
#pragma unroll
        for (int nj = 0; nj < 8; nj++) {
            const float* a4 = acc[mi][nj];
            int row0 = bm + warp_m * 64 + mi * 16 + tm;
            int col = bn + warp_n * 64 + nj * 8 + tn;
            float b0 = 0.f, b1 = 0.f;
            if (BIAS) { b0 = bias[col]; b1 = bias[col + 1]; }
            float v0 = a4[0] + b0, v1 = a4[1] + b1;
            float v2 = a4[2] + b0, v3 = a4[3] + b1;
            if (RELU) {
                v0 = fmaxf(v0, 0.f); v1 = fmaxf(v1, 0.f);
                v2 = fmaxf(v2, 0.f); v3 = fmaxf(v3, 0.f);
            }
            if (OUTM == 0) {
                *(float2*)(C + (size_t)row0 * N + col) = make_float2(v0, v1);
                *(float2*)(C + (size_t)(row0 + 8) * N + col) = make_float2(v2, v3);
            } else {
                *(uint32_t*)(O16 + (size_t)row0 * N + col) = h2pack(v0, v1);
                *(uint32_t*)(O16 + (size_t)(row0 + 8) * N + col) = h2pack(v2, v3);
            }
        }
    }
}

// ---------------- embedding + positional encoding (fp32 + fp16 out) ----------------
__global__ void __launch_bounds__(128) embed_kernel(float* __restrict__ x,
                                                    __half* __restrict__ x16,
                                                    const int* __restrict__ tok,
                                                    const float* __restrict__ emb)
{
    int m = blockIdx.x;
    int l = m >> 2;
    int t = tok[m];
    const float sq = 22.627416997969522f;
    const double nlog = 9.210340371976184;
#pragma unroll
    for (int j = 0; j < 4; j++) {
        int d = threadIdx.x + j * 128;
        int i = d >> 1;
        float freqf = (float)exp(-(double)(2 * i) * (nlog / 512.0));
        float angf = (float)l * freqf;
        double ang = (double)angf;
        float pe = (d & 1) ? (float)cos(ang) : (float)sin(ang);
        float v = emb[(size_t)t * DMODEL + d] * sq + pe;
        x[(size_t)m * DMODEL + d] = v;
        x16[(size_t)m * DMODEL + d] = __float2half(v);
    }
}

// ---------------- fp16 flash attention (causal, 1-term), fused-QKV input --------
#define QKVSTR 1536
#define AT_S 144
#define AQ_B (128 * AT_S)          // 18432
#define AKV_TILE (64 * AT_S)       // 9216
#define AKV_STAGE (2 * AKV_TILE)   // 18432 (K + V)
#define ATTN_SMEM (AQ_B + 2 * AKV_STAGE)   // 55296

__global__ void __launch_bounds__(256) attn_mma(
    __half* __restrict__ ctx16,
    const __half* __restrict__ qkv16)
{
    extern __shared__ char smem[];
    const uint32_t sb = s2u(smem);
    const int tid = threadIdx.x, warp = tid >> 5, lane = tid & 31;
    const int bx = blockIdx.x, b = blockIdx.y, h = blockIdx.z;
    const int l0 = bx * 128;
    const int ntiles = 2 * bx + 2;

    const uint32_t sQ = sb;
    const uint32_t sKV = sb + AQ_B;

    // load Q tile: 128 rows x 8 segs of 16B
#pragma unroll
    for (int t = 0; t < 4; t++) {
        int idx = tid + t * 256;
        int row = idx >> 3, seg = idx & 7;
        cpa16(sQ + row * AT_S + seg * 16,
              qkv16 + ((size_t)(l0 + row) * 4 + b) * QKVSTR + h * 64 + seg * 8);
    }
    asm volatile("cp.async.commit_group;" ::: "memory");

    auto load_kv = [&](int s, int jt) {
        uint32_t st = sKV + s * AKV_STAGE;
#pragma unroll
        for (int t = 0; t < 4; t++) {
            int idx = tid + t * 256;
            int arr = idx >> 9;            // 0=K, 1=V
            int row = (idx >> 3) & 63;
            int seg = idx & 7;
            int coff = 512 + arr * 512;
            cpa16(st + arr * AKV_TILE + row * AT_S + seg * 16,
                  qkv16 + ((size_t)(jt * 64 + row) * 4 + b) * QKVSTR + coff + h * 64 + seg * 8);
        }
    };
    load_kv(0, 0);
    asm volatile("cp.async.commit_group;" ::: "memory");

    const int a_row = (lane & 7) + ((lane >> 3) & 1) * 8;
    const int a_k8 = lane >> 4;
    const int b_row = (lane & 7) + (lane >> 4) * 8;
    const int b_k8 = (lane >> 3) & 1;

    uint32_t qf[4][4];
    float ctx[8][4];
#pragma unroll
    for (int i = 0; i < 8; i++)
#pragma unroll
        for (int j = 0; j < 4; j++) ctx[i][j] = 0.f;
    float m0 = -INFINITY, m1 = -INFINITY, l0s = 0.f, l1s = 0.f;

    for (int jt = 0; jt < ntiles; jt++) {
        const uint32_t st = sKV + (jt & 1) * AKV_STAGE;
        __syncthreads();
        if (jt + 1 < ntiles) {
            load_kv((jt + 1) & 1, jt + 1);
            asm volatile("cp.async.commit_group;" ::: "memory");
            asm volatile("cp.async.wait_group 1;" ::: "memory");
        } else {
            asm volatile("cp.async.wait_group 0;" ::: "memory");
        }
        __syncthreads();

        if (jt == 0) {
#pragma unroll
            for (int kb = 0; kb < 4; kb++) {
                uint32_t qa = sQ + (warp * 16 + a_row) * AT_S + (kb * 2 + a_k8) * 16;
                LDSM4(qf[kb], qa);
            }
        }

        // S = Q K^T (1 term)
        float S[8][4];
#pragma unroll
        for (int i = 0; i < 8; i++)
#pragma unroll
            for (int j = 0; j < 4; j++) S[i][j] = 0.f;
#pragma unroll
        for (int kb = 0; kb < 4; kb++) {
#pragma unroll
            for (int ng = 0; ng < 4; ng++) {
                uint32_t kf[4];
                uint32_t ka = st + (ng * 16 + b_row) * AT_S + (kb * 2 + b_k8) * 16;
                LDSM4(kf, ka);
                int nb = ng * 2;
                MMAF16(S[nb], qf[kb], kf[0], kf[1]);
                MMAF16(S[nb + 1], qf[kb], kf[2], kf[3]);
            }
        }

        const int qr0 = l0 + warp * 16 + (lane >> 2);
        const int qr1 = qr0 + 8;
        if (jt >= ntiles - 2) {
#pragma unroll
            for (int nb = 0; nb < 8; nb++) {
                int c = jt * 64 + nb * 8 + 2 * (lane & 3);
                if (c > qr0) S[nb][0] = -INFINITY;
                if (c + 1 > qr0) S[nb][1] = -INFINITY;
                if (c > qr1) S[nb][2] = -INFINITY;
                if (c + 1 > qr1) S[nb][3] = -INFINITY;
            }
        }

        // online softmax
        float mx0 = -INFINITY, mx1 = -INFINITY;
#pragma unroll
        for (int nb = 0; nb < 8; nb++) {
            mx0 = fmaxf(mx0, fmaxf(S[nb][0], S[nb][1]));
            mx1 = fmaxf(mx1, fmaxf(S[nb][2], S[nb][3]));
        }
        mx0 = fmaxf(mx0, __shfl_xor_sync(0xffffffffu, mx0, 1));
        mx0 = fmaxf(mx0, __shfl_xor_sync(0xffffffffu, mx0, 2));
        mx1 = fmaxf(mx1, __shfl_xor_sync(0xffffffffu, mx1, 1));
        mx1 = fmaxf(mx1, __shfl_xor_sync(0xffffffffu, mx1, 2));
        float nm0 = fmaxf(m0, mx0), nm1 = fmaxf(m1, mx1);
        float c0 = __expf(m0 - nm0), c1 = __expf(m1 - nm1);
        m0 = nm0; m1 = nm1;
        float s0 = 0.f, s1 = 0.f;
#pragma unroll
        for (int nb = 0; nb < 8; nb++) {
            S[nb][0] = __expf(S[nb][0] - nm0);
            S[nb][1] = __expf(S[nb][1] - nm0);
            S[nb][2] = __expf(S[nb][2] - nm1);
            S[nb][3] = __expf(S[nb][3] - nm1);
            s0 += S[nb][0] + S[nb][1];
            s1 += S[nb][2] + S[nb][3];
        }
        s0 += __shfl_xor_sync(0xffffffffu, s0, 1);
        s0 += __shfl_xor_sync(0xffffffffu, s0, 2);
        s1 += __shfl_xor_sync(0xffffffffu, s1, 1);
        s1 += __shfl_xor_sync(0xffffffffu, s1, 2);
        l0s = l0s * c0 + s0;
        l1s = l1s * c1 + s1;
#pragma unroll
        for (int nb = 0; nb < 8; nb++) {
            ctx[nb][0] *= c0; ctx[nb][1] *= c0;
            ctx[nb][2] *= c1; ctx[nb][3] *= c1;
        }

        // P fragments (fp16, values in [0,1])
        uint32_t ph[4][4];
#pragma unroll
        for (int kb = 0; kb < 4; kb++) {
            const float* sA = S[2 * kb];
            const float* sB = S[2 * kb + 1];
            ph[kb][0] = h2pack(sA[0], sA[1]);
            ph[kb][1] = h2pack(sA[2], sA[3]);
            ph[kb][2] = h2pack(sB[0], sB[1]);
            ph[kb][3] = h2pack(sB[2], sB[3]);
        }

        // ctx += P V (1 term); V via ldmatrix.trans
        const uint32_t vrow = (lane & 7) + ((lane >> 3) & 1) * 8;
        const uint32_t vcol16 = (lane >> 4) * 16;
#pragma unroll
        for (int kb = 0; kb < 4; kb++) {
#pragma unroll
            for (int ngd = 0; ngd < 4; ngd++) {
                uint32_t vb[4];
                uint32_t va = st + AKV_TILE + (kb * 16 + vrow) * AT_S + ngd * 32 + vcol16;
                LDSM4T(vb, va);
                int nd = ngd * 2;
                MMAF16(ctx[nd], ph[kb], vb[0], vb[1]);
                MMAF16(ctx[nd + 1], ph[kb], vb[2], vb[3]);
            }
        }
    }

    float inv0 = 1.f / l0s, inv1 = 1.f / l1s;
    const size_t mg0 = (size_t)(l0 + warp * 16 + (lane >> 2)) * 4 + b;
    const size_t mg1 = mg0 + 32;
#pragma unroll
    for (int nd = 0; nd < 8; nd++) {
        int col = h * 64 + nd * 8 + 2 * (lane & 3);
        *(uint32_t*)(ctx16 + mg0 * 512 + col) = h2pack(ctx[nd][0] * inv0, ctx[nd][1] * inv0);
        *(uint32_t*)(ctx16 + mg1 * 512 + col) = h2pack(ctx[nd][2] * inv1, ctx[nd][3] * inv1);
    }
}

// ---------------- fused residual-add + LayerNorm (+ optional final LN, fp16 out) ----
__global__ void __launch_bounds__(128) add_ln_kernel(float* __restrict__ x,
                                                     __half* __restrict__ x16,
                                                     const float* __restrict__ y,
                                                     const float* __restrict__ a,
                                                     const float* __restrict__ b,
                                                     const float* __restrict__ fa,
                                                     const float* __restrict__ fb)
{
    const int m = blockIdx.x;
    const int tid = threadIdx.x;
    const size_t base = (size_t)m * DMODEL;
    __shared__ float red[8];

    float v[4];
#pragma unroll
    for (int j = 0; j < 4; j++) {
        int d = tid + j * 128;
        float xv = x[base + d];
        if (y) xv += y[base + d];
        v[j] = xv;
    }
    float s = v[0] + v[1] + v[2] + v[3];
#pragma unroll
    for (int o = 16; o > 0; o >>= 1) s += __shfl_xor_sync(0xffffffffu, s, o);
    if ((tid & 31) == 0) red[tid >> 5] = s;
    __syncthreads();
    float mean = (red[0] + red[1] + red[2] + red[3]) * (1.f / 512.f);

    float ss = 0.f;
#pragma unroll
    for (int j = 0; j < 4; j++) {
        float dm = v[j] - mean;
        ss += dm * dm;
    }
#pragma unroll
    for (int o = 16; o > 0; o >>= 1) ss += __shfl_xor_sync(0xffffffffu, ss, o);
    if ((tid & 31) == 0) red[4 + (tid >> 5)] = ss;
    __syncthreads();
    float var = (red[4] + red[5] + red[6] + red[7]) * (1.f / 511.f);
    float inv = 1.f / (sqrtf(var) + 1e-6f);

    float o4[4];
#pragma unroll
    for (int j = 0; j < 4; j++) {
        int d = tid + j * 128;
        o4[j] = a[d] * (v[j] - mean) * inv + b[d];
    }

    if (fa) {
        __syncthreads();
        float s2 = o4[0] + o4[1] + o4[2] + o4[3];
#pragma unroll
        for (int o = 16; o > 0; o >>= 1) s2 += __shfl_xor_sync(0xffffffffu, s2, o);
        if ((tid & 31) == 0) red[tid >> 5] = s2;
        __syncthreads();
        float mean2 = (red[0] + red[1] + red[2] + red[3]) * (1.f / 512.f);
        float ss2 = 0.f;
#pragma unroll
        for (int j = 0; j < 4; j++) {
            float dm = o4[j] - mean2;
            ss2 += dm * dm;
        }
#pragma unroll
        for (int o = 16; o > 0; o >>= 1) ss2 += __shfl_xor_sync(0xffffffffu, ss2, o);
        if ((tid & 31) == 0) red[4 + (tid >> 5)] = ss2;
        __syncthreads();
        float var2 = (red[4] + red[5] + red[6] + red[7]) * (1.f / 511.f);
        float inv2 = 1.f / (sqrtf(var2) + 1e-6f);
#pragma unroll
        for (int j = 0; j < 4; j++) {
            int d = tid + j * 128;
            o4[j] = fa[d] * (o4[j] - mean2) * inv2 + fb[d];
        }
    }

#pragma unroll
    for (int j = 0; j < 4; j++) {
        int d = tid + j * 128;
        x[base + d] = o4[j];
        x16[base + d] = __float2half(o4[j]);
    }
}

// ---------------- orchestration ----------------
extern "C" void kernel_launch(void* const* d_in, const int* in_sizes, int n_in,
                              void* d_out, int out_size)
{
    (void)in_sizes; (void)n_in; (void)out_size;
    const int*   input = (const int*)  d_in[0];
    const float* emb   = (const float*)d_in[1];
    const float* Wq    = (const float*)d_in[2];
    const float* Wk    = (const float*)d_in[3];
    const float* Wv    = (const float*)d_in[4];
    const float* Wo    = (const float*)d_in[5];
    const float* w1    = (const float*)d_in[6];
    const float* b1    = (const float*)d_in[7];
    const float* w2    = (const float*)d_in[8];
    const float* b2    = (const float*)d_in[9];
    const float* ln1a  = (const float*)d_in[10];
    const float* ln1b  = (const float*)d_in[11];
    const float* ln2a  = (const float*)d_in[12];
    const float* ln2b  = (const float*)d_in[13];
    const float* fna   = (const float*)d_in[14];
    const float* fnb   = (const float*)d_in[15];
    const float* decW  = (const float*)d_in[16];
    const float* decb  = (const float*)d_in[17];
    float* out = (float*)d_out;

    float *x, *t;
    __nv_bfloat16 *xs, *qkvs, *cs, *ahi, *whi;
    cudaGetSymbolAddress((void**)&x,    g_x);
    cudaGetSymbolAddress((void**)&t,    g_t);
    cudaGetSymbolAddress((void**)&xs,   g_xs);
    cudaGetSymbolAddress((void**)&qkvs, g_qkvs);
    cudaGetSymbolAddress((void**)&cs,   g_cs);
    cudaGetSymbolAddress((void**)&ahi,  g_ahi);
    cudaGetSymbolAddress((void**)&whi,  g_whi);

    __half* x16 = (__half*)xs;
    __half* qkv16 = (__half*)qkvs;
    __half* c16 = (__half*)cs;
    __half* a16 = (__half*)ahi;
    __half* wh = (__half*)whi;

    cudaFuncSetAttribute(attn_mma, cudaFuncAttributeMaxDynamicSharedMemorySize, ATTN_SMEM);
    cudaFuncSetAttribute(gemm_1t<false, false, 1>, cudaFuncAttributeMaxDynamicSharedMemorySize, GEMM1_SMEM);
    cudaFuncSetAttribute(gemm_1t<false, false, 0>, cudaFuncAttributeMaxDynamicSharedMemorySize, GEMM1_SMEM);
    cudaFuncSetAttribute(gemm_1t<true, true, 1>,   cudaFuncAttributeMaxDynamicSharedMemorySize, GEMM1_SMEM);
    cudaFuncSetAttribute(gemm_1t<true, false, 0>,  cudaFuncAttributeMaxDynamicSharedMemorySize, GEMM1_SMEM);

    // weight converts (fp16 single): fused QKV strided (q scaled 1/8), Wo/w1/w2/decW
    cvt16_qkv<<<1024, 256>>>(wh + WQKV0, Wq, 0.125f, 0);
    cvt16_qkv<<<1024, 256>>>(wh + WQKV0, Wk, 1.0f, 131072);
    cvt16_qkv<<<1024, 256>>>(wh + WQKV0, Wv, 1.0f, 262144);
    cvt16<<<1024, 256>>>(wh + WO0, Wo, 1048576 / 4);
    cvt16<<<4096, 256>>>(wh + W10, w1, 4194304 / 4);
    cvt16<<<4096, 256>>>(wh + W20, w2, 4194304 / 4);
    cvt16<<<16000, 256>>>(wh + WD0, decW, 16384000 / 4);

    embed_kernel<<<MROWS, 128>>>(x, x16, input, emb);

    const dim3 gQKV(3 * DMODEL / 256, MROWS / 128);  // (6, 64)
    const dim3 gD(DMODEL / 256, MROWS / 128);        // (2, 64)
    const dim3 gF(DFFN / 256, MROWS / 128);          // (8, 64)
    const dim3 gV(NVOCAB / 256, MROWS / 128);        // (125, 64)
    const dim3 gAttn(LSEQ / 128, BATCH, NHEAD);

    for (int l = 0; l < NLAYER; l++) {
        const size_t qofs = (size_t)l * 1536 * 512;
        const size_t wofs = (size_t)l * DMODEL * DMODEL;
        const size_t f1 = (size_t)l * DFFN * DMODEL;
        const bool last = (l == NLAYER - 1);

        gemm_1t<false, false, 1><<<gQKV, 256, GEMM1_SMEM>>>(
            nullptr, qkv16, x16, wh + WQKV0 + qofs,
            nullptr, MROWS, 3 * DMODEL, DMODEL);

        attn_mma<<<gAttn, 256, ATTN_SMEM>>>(c16, qkv16);

        gemm_1t<false, false, 0><<<gD, 256, GEMM1_SMEM>>>(
            t, nullptr, c16, wh + WO0 + wofs,
            nullptr, MROWS, DMODEL, DMODEL);
        add_ln_kernel<<<MROWS, 128>>>(x, x16, t, ln1a + l * DMODEL, ln1b + l * DMODEL,
                                      nullptr, nullptr);

        gemm_1t<true, true, 1><<<gF, 256, GEMM1_SMEM>>>(
            nullptr, a16, x16, wh + W10 + f1,
            b1 + l * DFFN, MROWS, DFFN, DMODEL);
        gemm_1t<true, false, 0><<<gD, 256, GEMM1_SMEM>>>(
            t, nullptr, a16, wh + W20 + f1,
            b2 + l * DMODEL, MROWS, DMODEL, DFFN);
        add_ln_kernel<<<MROWS, 128>>>(x, x16, t, ln2a + l * DMODEL, ln2b + l * DMODEL,
                                      last ? fna : nullptr, last ? fnb : nullptr);
    }

    gemm_1t<true, false, 0><<<gV, 256, GEMM1_SMEM>>>(
        out, nullptr, x16, wh + WD0,
        decb, MROWS, NVOCAB, DMODEL);
}